// round 9
// baseline (speedup 1.0000x reference)
#include <cuda_runtime.h>
#include <cuda_bf16.h>
#include <math.h>
#include <stdint.h>

// Problem constants
#define TT   2048
#define DD   768
#define HH   12
#define DKK  64
#define FFF  2048
#define VV   50304
#define LL   12
#define KC   4
#define EPSF 1e-6f
#define NCH  32     // chunks (T / 64)
#define PSTR 65     // padded smem stride

// packed word counts per matrix (word = uint32 = 2 bf16 packed along K)
#define WSM 294912     // 384*768   (Wq/Wk/Wv/Wo per layer)
#define WGU 786432     // 384*2048  (Wgate/Wup per layer)
#define WDN 786432     // 1024*768  (Wdown per layer)
#define WLM 19316736   // 384*50304 (lm_head)

// ---------------- scratch (__device__ globals; no allocation allowed) ----------------
__device__ float g_h[TT * DD];
__device__ float g_x[TT * DD];
__device__ float g_t0[TT * DD];
__device__ float g_t1[TT * DD];
__device__ float g_t2[TT * DD];
__device__ float g_q[TT * DD];
__device__ float g_k[TT * DD];
__device__ float g_v[TT * DD];
__device__ float g_o[TT * DD];
__device__ float g_beta[TT * HH];
__device__ float g_gate[TT * FFF];
__device__ float g_up[TT * FFF];
__device__ float g_nll[TT];
__device__ float g_msk[TT];
__device__ float g_logits_fb[(size_t)TT * VV];

// chunked-delta intermediates: [H][NCH][64][64]
__device__ float g_Qe[HH * NCH * 4096];
__device__ float g_Of[HH * NCH * 4096];
__device__ float g_Pm[HH * NCH * 4096];
__device__ float g_Rm[HH * NCH * 4096];

// packed activation A operand, max Kd=2048 -> 1024 words/row
__device__ uint32_t g_pA_h[TT * 1024];
__device__ uint32_t g_pA_l[TT * 1024];

// packed weights
__device__ uint32_t g_Wq_h[LL * WSM]; __device__ uint32_t g_Wq_l[LL * WSM];
__device__ uint32_t g_Wk_h[LL * WSM]; __device__ uint32_t g_Wk_l[LL * WSM];
__device__ uint32_t g_Wv_h[LL * WSM]; __device__ uint32_t g_Wv_l[LL * WSM];
__device__ uint32_t g_Wo_h[LL * WSM]; __device__ uint32_t g_Wo_l[LL * WSM];
__device__ uint32_t g_Wg_h[LL * WGU]; __device__ uint32_t g_Wg_l[LL * WGU];
__device__ uint32_t g_Wu_h[LL * WGU]; __device__ uint32_t g_Wu_l[LL * WGU];
__device__ uint32_t g_Wd_h[LL * WDN]; __device__ uint32_t g_Wd_l[LL * WDN];
__device__ uint32_t g_Lm_h[WLM];      __device__ uint32_t g_Lm_l[WLM];

// ---------------- helpers ----------------
__device__ __forceinline__ void mma_bf16(float* c, const uint32_t* a, const uint32_t* b) {
    asm volatile(
        "mma.sync.aligned.m16n8k16.row.col.f32.bf16.bf16.f32 "
        "{%0,%1,%2,%3}, {%4,%5,%6,%7}, {%8,%9}, {%0,%1,%2,%3};\n"
        : "+f"(c[0]), "+f"(c[1]), "+f"(c[2]), "+f"(c[3])
        : "r"(a[0]), "r"(a[1]), "r"(a[2]), "r"(a[3]), "r"(b[0]), "r"(b[1]));
}

__device__ __forceinline__ void split_pack(float x0, float x1, uint32_t& hp, uint32_t& lp) {
    __nv_bfloat16 h0 = __float2bfloat16(x0), h1 = __float2bfloat16(x1);
    float f0 = __bfloat162float(h0), f1 = __bfloat162float(h1);
    __nv_bfloat16 l0 = __float2bfloat16(x0 - f0), l1 = __float2bfloat16(x1 - f1);
    hp = (uint32_t)__bfloat16_as_ushort(h0) | ((uint32_t)__bfloat16_as_ushort(h1) << 16);
    lp = (uint32_t)__bfloat16_as_ushort(l0) | ((uint32_t)__bfloat16_as_ushort(l1) << 16);
}

// ---------------- kernels ----------------

__global__ void embed_k(const int* __restrict__ idx, const float* __restrict__ emb,
                        float* __restrict__ out) {
    int t = blockIdx.x;
    int row = idx[t];
    const float* src = emb + (size_t)row * DD;
    float* dst = out + (size_t)t * DD;
    for (int d = threadIdx.x; d < DD; d += blockDim.x) dst[d] = src[d];
}

// pack weights: src [count][2*Kw][N] fp32 -> dstH/dstL [count][Kw][N] words.
// grid: (ceil(N/256), Kw, count)
__global__ void pack_w_k(const float* __restrict__ src, uint32_t* __restrict__ dH,
                         uint32_t* __restrict__ dL, int Kw, int N) {
    int n = blockIdx.x * 256 + threadIdx.x;
    if (n >= N) return;
    int kw = blockIdx.y;
    size_t nw = (size_t)Kw * N;
    size_t bs = (size_t)blockIdx.z * 2u * nw;
    size_t bd = (size_t)blockIdx.z * nw;
    float a0 = src[bs + (size_t)(2 * kw) * N + n];
    float a1 = src[bs + (size_t)(2 * kw + 1) * N + n];
    uint32_t h, l;
    split_pack(a0, a1, h, l);
    dH[bd + (size_t)kw * N + n] = h;
    dL[bd + (size_t)kw * N + n] = l;
}

// rmsnorm; optional fp32 out; packed hi/lo words (row stride n/2)
__global__ void rmsnorm_pack_k(const float* __restrict__ in, const float* __restrict__ w,
                               float* __restrict__ outf,
                               uint32_t* __restrict__ pH, uint32_t* __restrict__ pL, int n) {
    int t = blockIdx.x;
    const float* r = in + (size_t)t * n;
    int tid = threadIdx.x;
    __shared__ float red[256];
    float s = 0.f;
    for (int i = tid; i < n; i += 256) { float vv = r[i]; s += vv * vv; }
    red[tid] = s; __syncthreads();
    for (int o = 128; o > 0; o >>= 1) { if (tid < o) red[tid] += red[tid + o]; __syncthreads(); }
    float rs = rsqrtf(red[0] / (float)n + EPSF);
    int nw = n >> 1;
    for (int i = tid; i < nw; i += 256) {
        float x0 = r[2 * i] * rs * w[2 * i];
        float x1 = r[2 * i + 1] * rs * w[2 * i + 1];
        if (outf) { outf[(size_t)t * n + 2 * i] = x0; outf[(size_t)t * n + 2 * i + 1] = x1; }
        uint32_t h, l;
        split_pack(x0, x1, h, l);
        pH[(size_t)t * nw + i] = h;
        pL[(size_t)t * nw + i] = l;
    }
}

// =======================================================================
// bf16x3 split-precision tensor-core GEMM, pre-packed operands.
// MT tiles: BM=MT*32, BN=128, BK=32; __launch_bounds__(256,2).
// MT=4: 64KB stage x2 CTA = 131KB smem/SM (fits 228KB).
// SW swaps grid axes (m-fastest) for B-panel L2 reuse on huge-N GEMMs.
// =======================================================================
template <bool ADD, int MT, bool SW>
__global__ __launch_bounds__(256, 2) void tbgemm_k(
    const uint32_t* __restrict__ AHg, const uint32_t* __restrict__ ALg,
    const uint32_t* __restrict__ B0H, const uint32_t* __restrict__ B0L,
    const uint32_t* __restrict__ B1H, const uint32_t* __restrict__ B1L,
    const uint32_t* __restrict__ B2H, const uint32_t* __restrict__ B2L,
    float* __restrict__ C0, float* __restrict__ C1, float* __restrict__ C2,
    int M, int N, int Kd) {
    extern __shared__ uint32_t smw[];
    const int AW = MT * 512;
    const int BUF = AW * 2 + 4096;
    const int Kw = Kd >> 1;

    const uint32_t* BHg = (blockIdx.z == 0) ? B0H : (blockIdx.z == 1 ? B1H : B2H);
    const uint32_t* BLg = (blockIdx.z == 0) ? B0L : (blockIdx.z == 1 ? B1L : B2L);
    float*          C   = (blockIdx.z == 0) ? C0  : (blockIdx.z == 1 ? C1  : C2);

    const int bm = (SW ? blockIdx.x : blockIdx.y) * (MT * 32);
    const int bn = (SW ? blockIdx.y : blockIdx.x) * 128;
    const int tid = threadIdx.x;
    const int warp = tid >> 5, lane = tid & 31;
    const int warpM = warp >> 2;
    const int warpN = warp & 3;
    const int g = lane >> 2, t4 = lane & 3;

    float acc[MT][4][4];
#pragma unroll
    for (int i = 0; i < MT; i++)
#pragma unroll
        for (int j = 0; j < 4; j++)
#pragma unroll
            for (int r = 0; r < 4; r++) acc[i][j][r] = 0.f;

    uint2 sa_h[MT], sa_l[MT];
    uint4 sb_h[2], sb_l[2];

    auto LOAD = [&](int kt) {
#pragma unroll
        for (int i = 0; i < MT; i++) {
            int id = i * 256 + tid;
            int r = id >> 3, c4 = id & 7;
            size_t off = (size_t)(bm + r) * Kw + kt * 16 + c4 * 2;
            sa_h[i] = *reinterpret_cast<const uint2*>(AHg + off);
            sa_l[i] = *reinterpret_cast<const uint2*>(ALg + off);
        }
#pragma unroll
        for (int i = 0; i < 2; i++) {
            int id = i * 256 + tid;
            int kw = id >> 5, n4 = id & 31;
            size_t off = (size_t)(kt * 16 + kw) * N + bn + n4 * 4;
            sb_h[i] = *reinterpret_cast<const uint4*>(BHg + off);
            sb_l[i] = *reinterpret_cast<const uint4*>(BLg + off);
        }
    };

    auto STORE = [&](int buf) {
        uint32_t* AH = smw + buf * BUF;
        uint32_t* AL = AH + AW;
        uint32_t* BH = AH + 2 * AW;
        uint32_t* BL = BH + 2048;
#pragma unroll
        for (int i = 0; i < MT; i++) {
            int id = i * 256 + tid;
            int r = id >> 3, c4 = id & 7;
            int off = r * 16 + ((c4 * 2) ^ ((r & 7) * 2));
            *reinterpret_cast<uint2*>(AH + off) = sa_h[i];
            *reinterpret_cast<uint2*>(AL + off) = sa_l[i];
        }
#pragma unroll
        for (int i = 0; i < 2; i++) {
            int id = i * 256 + tid;
            int kw = id >> 5, n4 = id & 31;
            int off = kw * 128 + ((n4 * 4) ^ ((kw * 8) & 127));
            *reinterpret_cast<uint4*>(BH + off) = sb_h[i];
            *reinterpret_cast<uint4*>(BL + off) = sb_l[i];
        }
    };

    auto COMPUTE = [&](int buf) {
        uint32_t* AH = smw + buf * BUF;
        uint32_t* AL = AH + AW;
        uint32_t* BH = AH + 2 * AW;
        uint32_t* BL = BH + 2048;
#pragma unroll
        for (int ks = 0; ks < 2; ks++) {
            uint32_t bh[4][2], bl[4][2];
#pragma unroll
            for (int nt = 0; nt < 4; nt++) {
                int n = warpN * 32 + nt * 8 + g;
                int k0w = ks * 8 + t4, k1w = k0w + 4;
                int o0 = k0w * 128 + (n ^ ((k0w * 8) & 127));
                int o1 = k1w * 128 + (n ^ ((k1w * 8) & 127));
                bh[nt][0] = BH[o0]; bh[nt][1] = BH[o1];
                bl[nt][0] = BL[o0]; bl[nt][1] = BL[o1];
            }
#pragma unroll
            for (int mt = 0; mt < MT; mt++) {
                uint32_t ah[4], al[4];
                int r0 = warpM * (MT * 16) + mt * 16 + g;
                int r1 = r0 + 8;
                int ka = ks * 8 + t4, kb = ka + 4;
                int o0 = r0 * 16 + (ka ^ ((r0 & 7) * 2));
                int o1 = r1 * 16 + (ka ^ ((r1 & 7) * 2));
                int o2 = r0 * 16 + (kb ^ ((r0 & 7) * 2));
                int o3 = r1 * 16 + (kb ^ ((r1 & 7) * 2));
                ah[0] = AH[o0]; ah[1] = AH[o1]; ah[2] = AH[o2]; ah[3] = AH[o3];
                al[0] = AL[o0]; al[1] = AL[o1]; al[2] = AL[o2]; al[3] = AL[o3];
#pragma unroll
                for (int nt = 0; nt < 4; nt++) {
                    mma_bf16(acc[mt][nt], al, bh[nt]);
                    mma_bf16(acc[mt][nt], ah, bl[nt]);
                    mma_bf16(acc[mt][nt], ah, bh[nt]);
                }
            }
        }
    };

    const int ntiles = Kd / 32;
    LOAD(0);
    STORE(0);
    __syncthreads();
    for (int kt = 0; kt < ntiles; kt++) {
        if (kt + 1 < ntiles) LOAD(kt + 1);
        COMPUTE(kt & 1);
        if (kt + 1 < ntiles) STORE((kt + 1) & 1);
        __syncthreads();
    }

#pragma unroll
    for (int mt = 0; mt < MT; mt++) {
        int r0 = bm + warpM * (MT * 16) + mt * 16 + g;
#pragma unroll
        for (int nt = 0; nt < 4; nt++) {
            int c0 = bn + warpN * 32 + nt * 8 + 2 * t4;
            float* p0 = C + (size_t)r0 * N + c0;
            float* p1 = C + (size_t)(r0 + 8) * N + c0;
            if (ADD) {
                p0[0] += acc[mt][nt][0]; p0[1] += acc[mt][nt][1];
                p1[0] += acc[mt][nt][2]; p1[1] += acc[mt][nt][3];
            } else {
                p0[0] = acc[mt][nt][0]; p0[1] = acc[mt][nt][1];
                p1[0] = acc[mt][nt][2]; p1[1] = acc[mt][nt][3];
            }
        }
    }
}

// =======================================================================
// Fused post-QKV, one 768-thread block per timestep.
// =======================================================================
__global__ __launch_bounds__(768) void postqkv_k(
    const float* __restrict__ t0, const float* __restrict__ t1, const float* __restrict__ t2,
    const float* __restrict__ cq, const float* __restrict__ ck, const float* __restrict__ cv,
    const float* __restrict__ x, const float* __restrict__ Wb,
    float* __restrict__ q, float* __restrict__ k, float* __restrict__ v,
    float* __restrict__ beta) {
    int t = blockIdx.x;
    int d = threadIdx.x;            // 0..767
    int h = d >> 6;
    int warp = d >> 5, lane = d & 31;
    __shared__ float sx[DD];
    __shared__ float redq[24], redk[24], redb[24];

    sx[d] = x[(size_t)t * DD + d];

    auto conv = [&](const float* src, const float* w) -> float {
        float acc = 0.f;
#pragma unroll
        for (int j = 0; j < KC; j++) {
            int tt = t - (KC - 1) + j;
            if (tt >= 0) acc += src[(size_t)tt * DD + d] * w[d * KC + j];
        }
        return acc / (1.f + __expf(-acc));
    };
    float qv = conv(t0, cq);
    float kv = conv(t1, ck);
    float vv = conv(t2, cv);

    float sq = qv * qv, sk = kv * kv;
#pragma unroll
    for (int o = 16; o > 0; o >>= 1) {
        sq += __shfl_xor_sync(0xffffffffu, sq, o);
        sk += __shfl_xor_sync(0xffffffffu, sk, o);
    }
    if (lane == 0) { redq[warp] = sq; redk[warp] = sk; }
    __syncthreads();

    {
        int h2 = warp >> 1, half = warp & 1;
        float sb = 0.f;
        for (int i = half * 384 + lane; i < half * 384 + 384; i += 32)
            sb += sx[i] * Wb[i * HH + h2];
#pragma unroll
        for (int o = 16; o > 0; o >>= 1) sb += __shfl_xor_sync(0xffffffffu, sb, o);
        if (lane == 0) redb[warp] = sb;
    }

    float rq = rsqrtf(redq[2 * h] + redq[2 * h + 1] + EPSF);
    float rk = rsqrtf(redk[2 * h] + redk[2 * h + 1] + EPSF);
    size_t gi = (size_t)t * DD + d;
    q[gi] = qv * rq;
    k[gi] = kv * rk;
    v[gi] = vv;
    __syncthreads();
    if (d < HH) beta[t * HH + d] = 1.f / (1.f + __expf(-(redb[2 * d] + redb[2 * d + 1])));
}

// =======================================================================
// Chunked delta rule, phase 1 (parallel; WY form).
// =======================================================================
__global__ __launch_bounds__(256) void deltaprep_k(
    const float* __restrict__ q, const float* __restrict__ k,
    const float* __restrict__ v, const float* __restrict__ beta,
    float* __restrict__ Qe, float* __restrict__ Of,
    float* __restrict__ Pm, float* __restrict__ Rm) {
    extern __shared__ float sm[];
    float* sK = sm;
    float* sV = sK + 64 * PSTR;
    float* sQ = sV + 64 * PSTR;
    float* bA = sQ + 64 * PSTR;
    float* bT = bA + 64 * PSTR;
    float* bU = bT + 64 * PSTR;
    float* sb = bU + 64 * PSTR;
    const int c = blockIdx.x, h = blockIdx.y;
    const int tid = threadIdx.x;
    const int tr = (tid >> 4) * 4, tc = (tid & 15) * 4;

    for (int i = tid; i < 4096; i += 256) {
        int t = i >> 6, d = i & 63;
        size_t g = (size_t)(c * 64 + t) * DD + h * 64 + d;
        sK[t * PSTR + d] = k[g];
        sV[t * PSTR + d] = v[g];
        sQ[t * PSTR + d] = q[g];
    }
    if (tid < 64) sb[tid] = beta[(c * 64 + tid) * HH + h];
    __syncthreads();

    {
        float acc[4][4] = {};
        for (int m = 0; m < 64; m++) {
            float a[4], b[4];
#pragma unroll
            for (int i = 0; i < 4; i++) a[i] = sK[(tr + i) * PSTR + m];
#pragma unroll
            for (int j = 0; j < 4; j++) b[j] = sK[(tc + j) * PSTR + m];
#pragma unroll
            for (int i = 0; i < 4; i++)
#pragma unroll
                for (int j = 0; j < 4; j++) acc[i][j] += a[i] * b[j];
        }
#pragma unroll
        for (int i = 0; i < 4; i++)
#pragma unroll
            for (int j = 0; j < 4; j++) {
                int t = tr + i, s = tc + j;
                bA[t * PSTR + s] = (s < t) ? acc[i][j] * sb[t] : 0.f;
            }
    }
    __syncthreads();

    for (int t = 0; t < 64; t++) {
        if (tid < 64) {
            float acc = (t == tid) ? 1.f : 0.f;
            for (int s = 0; s < t; s++) acc -= bA[t * PSTR + s] * bT[s * PSTR + tid];
            bT[t * PSTR + tid] = acc;
        }
        __syncthreads();
    }

    {
        float accW[4][4] = {}, accU[4][4] = {};
        for (int m = 0; m < 64; m++) {
            float a[4];
#pragma unroll
            for (int i = 0; i < 4; i++) a[i] = bT[(tr + i) * PSTR + m] * sb[m];
            float bk[4], bv[4];
#pragma unroll
            for (int j = 0; j < 4; j++) {
                bk[j] = sK[m * PSTR + tc + j];
                bv[j] = sV[m * PSTR + tc + j];
            }
#pragma unroll
            for (int i = 0; i < 4; i++)
#pragma unroll
                for (int j = 0; j < 4; j++) {
                    accW[i][j] += a[i] * bk[j];
                    accU[i][j] += a[i] * bv[j];
                }
        }
        __syncthreads();
#pragma unroll
        for (int i = 0; i < 4; i++)
#pragma unroll
            for (int j = 0; j < 4; j++) {
                bA[(tr + i) * PSTR + tc + j] = accW[i][j];
                bU[(tr + i) * PSTR + tc + j] = accU[i][j];
            }
    }
    __syncthreads();

    {
        float acc[4][4] = {};
        for (int m = 0; m < 64; m++) {
            float a[4], b[4];
#pragma unroll
            for (int i = 0; i < 4; i++) a[i] = sQ[(tr + i) * PSTR + m];
#pragma unroll
            for (int j = 0; j < 4; j++) b[j] = sK[(tc + j) * PSTR + m];
#pragma unroll
            for (int i = 0; i < 4; i++)
#pragma unroll
                for (int j = 0; j < 4; j++) acc[i][j] += a[i] * b[j];
        }
        __syncthreads();
#pragma unroll
        for (int i = 0; i < 4; i++)
#pragma unroll
            for (int j = 0; j < 4; j++) {
                int t = tr + i, s = tc + j;
                bT[t * PSTR + s] = (s <= t) ? acc[i][j] : 0.f;
            }
    }
    __syncthreads();

    const size_t base = ((size_t)(h * NCH + c)) << 12;

    {
        float accQ[4][4] = {}, accO[4][4] = {};
        for (int m = 0; m < 64; m++) {
            float a[4];
#pragma unroll
            for (int i = 0; i < 4; i++) a[i] = bT[(tr + i) * PSTR + m];
            float bw[4], bu[4];
#pragma unroll
            for (int j = 0; j < 4; j++) {
                bw[j] = bA[m * PSTR + tc + j];
                bu[j] = bU[m * PSTR + tc + j];
            }
#pragma unroll
            for (int i = 0; i < 4; i++)
#pragma unroll
                for (int j = 0; j < 4; j++) {
                    accQ[i][j] += a[i] * bw[j];
                    accO[i][j] += a[i] * bu[j];
                }
        }
#pragma unroll
        for (int i = 0; i < 4; i++)
#pragma unroll
            for (int j = 0; j < 4; j++) {
                Qe[base + (tr + i) * 64 + tc + j] =
                    sQ[(tr + i) * PSTR + tc + j] - accQ[i][j];
                Of[base + (tr + i) * 64 + tc + j] = accO[i][j];
            }
    }

    {
        float accP[4][4] = {}, accR[4][4] = {};
        for (int m = 0; m < 64; m++) {
            float a[4];
#pragma unroll
            for (int i = 0; i < 4; i++) a[i] = sK[m * PSTR + tr + i];
            float bw[4], bu[4];
#pragma unroll
            for (int j = 0; j < 4; j++) {
                bw[j] = bA[m * PSTR + tc + j];
                bu[j] = bU[m * PSTR + tc + j];
            }
#pragma unroll
            for (int i = 0; i < 4; i++)
#pragma unroll
                for (int j = 0; j < 4; j++) {
                    accP[i][j] += a[i] * bw[j];
                    accR[i][j] += a[i] * bu[j];
                }
        }
#pragma unroll
        for (int i = 0; i < 4; i++)
#pragma unroll
            for (int j = 0; j < 4; j++) {
                Pm[base + (tr + i) * 64 + tc + j] = accP[i][j];
                Rm[base + (tr + i) * 64 + tc + j] = accR[i][j];
            }
    }
}

// Chunked delta rule, phase 2 (scan)
__global__ __launch_bounds__(256) void deltascan_k(
    const float* __restrict__ Qe, const float* __restrict__ Of,
    const float* __restrict__ Pm, const float* __restrict__ Rm,
    float* __restrict__ o) {
    const int h = blockIdx.x, cg = blockIdx.y;
    const int tid = threadIdx.x;
    __shared__ float sQe[64 * PSTR], sP[64 * PSTR];
    __shared__ float S[64 * 9], sOf[512], sR[512];

    for (int i = tid; i < 64 * 9; i += 256) S[i] = 0.f;
    __syncthreads();

#pragma unroll 1
    for (int c = 0; c < NCH; c++) {
        size_t base = ((size_t)(h * NCH + c)) << 12;
        for (int i = tid; i < 4096; i += 256) {
            int t = i >> 6, d = i & 63;
            sQe[t * PSTR + d] = Qe[base + i];
            sP[t * PSTR + d] = Pm[base + i];
        }
        for (int i = tid; i < 512; i += 256) {
            int t = i >> 3, j = i & 7;
            sOf[i] = Of[base + t * 64 + cg * 8 + j];
            sR[i] = Rm[base + t * 64 + cg * 8 + j];
        }
        __syncthreads();

        float outv[2], ns[2];
#pragma unroll
        for (int u = 0; u < 2; u++) {
            int idx = tid + u * 256;
            int t = idx >> 3, j = idx & 7;
            float a1 = sOf[idx];
            float a2 = S[t * 9 + j] + sR[idx];
#pragma unroll
            for (int m = 0; m < 64; m++) {
                float sv = S[m * 9 + j];
                a1 += sQe[t * PSTR + m] * sv;
                a2 -= sP[t * PSTR + m] * sv;
            }
            outv[u] = a1;
            ns[u] = a2;
        }
#pragma unroll
        for (int u = 0; u < 2; u++) {
            int idx = tid + u * 256;
            int t = idx >> 3, j = idx & 7;
            o[(size_t)(c * 64 + t) * DD + h * 64 + cg * 8 + j] = outv[u];
        }
        __syncthreads();
#pragma unroll
        for (int u = 0; u < 2; u++) {
            int idx = tid + u * 256;
            int t = idx >> 3, j = idx & 7;
            S[t * 9 + j] = ns[u];
        }
        __syncthreads();
    }
}

// per-64 rmsnorm * w of delta output -> packed words (feeds Wo GEMM)
__global__ void headnorm_pack_k(const float* __restrict__ o, const float* __restrict__ w,
                                uint32_t* __restrict__ pH, uint32_t* __restrict__ pL) {
    int gw = (blockIdx.x * blockDim.x + threadIdx.x) >> 5;
    int lane = threadIdx.x & 31;
    if (gw >= TT * HH) return;
    const float* r = o + (size_t)gw * 64;
    float a = r[2 * lane], b = r[2 * lane + 1];
    float s = a * a + b * b;
#pragma unroll
    for (int os = 16; os > 0; os >>= 1) s += __shfl_xor_sync(0xffffffffu, s, os);
    float rs = rsqrtf(s * (1.f / 64.f) + EPSF);
    int t = gw / HH, h = gw % HH;
    uint32_t hw, lw;
    split_pack(a * rs * w[2 * lane], b * rs * w[2 * lane + 1], hw, lw);
    size_t wi = (size_t)t * 384 + h * 32 + lane;
    pH[wi] = hw;
    pL[wi] = lw;
}

// silu(g)*u, writes packed words; i indexes element pairs
__global__ void silu_mul_pack_k(const float* __restrict__ g, const float* __restrict__ u,
                                uint32_t* __restrict__ pH, uint32_t* __restrict__ pL) {
    int i = blockIdx.x * blockDim.x + threadIdx.x;
    if (i >= TT * FFF / 2) return;
    float g0 = g[2 * i], g1 = g[2 * i + 1];
    float y0 = (g0 / (1.f + __expf(-g0))) * u[2 * i];
    float y1 = (g1 / (1.f + __expf(-g1))) * u[2 * i + 1];
    uint32_t h, l;
    split_pack(y0, y1, h, l);
    pH[i] = h;
    pL[i] = l;
}

// online-softmax cross-entropy row pass (single read of logits)
__global__ void loss_rows_k(const float* __restrict__ logits, const int* __restrict__ tgt,
                            float* __restrict__ nll, float* __restrict__ msk) {
    int t = blockIdx.x;
    const float* r = logits + (size_t)t * VV;
    int tid = threadIdx.x;
    __shared__ float sm_m[256], sm_s[256];
    float m = -INFINITY, s = 0.f;
    for (int i = tid; i < VV; i += 256) {
        float v = r[i];
        if (v > m) { s = s * __expf(m - v) + 1.f; m = v; }
        else s += __expf(v - m);
    }
    sm_m[tid] = m; sm_s[tid] = s;
    __syncthreads();
    for (int o = 128; o > 0; o >>= 1) {
        if (tid < o) {
            float m1 = sm_m[tid], m2 = sm_m[tid + o];
            float M = fmaxf(m1, m2);
            sm_s[tid] = sm_s[tid] * __expf(m1 - M) + sm_s[tid + o] * __expf(m2 - M);
            sm_m[tid] = M;
        }
        __syncthreads();
    }
    if (tid == 0) {
        float rowmax = sm_m[0], denom = sm_s[0];
        int tg = tgt[t];
        float mask = (tg >= 0) ? 1.f : 0.f;
        int tc = tg < 0 ? 0 : (tg > VV - 1 ? VV - 1 : tg);
        float lp = r[tc] - rowmax - logf(denom);
        nll[t] = -lp * mask;
        msk[t] = mask;
    }
}

__global__ void loss_reduce_k(const float* __restrict__ nll, const float* __restrict__ msk,
                              float* __restrict__ out) {
    int tid = threadIdx.x;
    __shared__ float r1[256], r2[256];
    float s = 0.f, c = 0.f;
    for (int i = tid; i < TT; i += 256) { s += nll[i]; c += msk[i]; }
    r1[tid] = s; r2[tid] = c; __syncthreads();
    for (int o = 128; o > 0; o >>= 1) {
        if (tid < o) { r1[tid] += r1[tid + o]; r2[tid] += r2[tid + o]; }
        __syncthreads();
    }
    if (tid == 0) out[0] = r1[0] / fmaxf(r2[0], 1.f);
}

// ---------------- host launcher ----------------
extern "C" void kernel_launch(void* const* d_in, const int* in_sizes, int n_in,
                              void* d_out, int out_size) {
    const int*   idx   = (const int*)d_in[0];
    const int*   tgt   = (const int*)d_in[1];
    const float* emb   = (const float*)d_in[2];
    const float* Wq    = (const float*)d_in[3];
    const float* Wk    = (const float*)d_in[4];
    const float* Wv    = (const float*)d_in[5];
    const float* convq = (const float*)d_in[6];
    const float* convk = (const float*)d_in[7];
    const float* convv = (const float*)d_in[8];
    const float* Wb    = (const float*)d_in[9];
    const float* onw   = (const float*)d_in[10];
    const float* Wo    = (const float*)d_in[11];
    const float* anw   = (const float*)d_in[12];
    const float* mnw   = (const float*)d_in[13];
    const float* Wg    = (const float*)d_in[14];
    const float* Wu    = (const float*)d_in[15];
    const float* Wd    = (const float*)d_in[16];
    const float* fnw   = (const float*)d_in[17];
    const float* lmh   = (const float*)d_in[18];
    float* out = (float*)d_out;

    float *hb, *xb, *t0, *t1, *t2, *qb, *kb, *vb, *ob, *bb, *gb, *ub, *nl, *mk, *lfb;
    cudaGetSymbolAddress((void**)&hb,  g_h);
    cudaGetSymbolAddress((void**)&xb,  g_x);
    cudaGetSymbolAddress((void**)&t0,  g_t0);
    cudaGetSymbolAddress((void**)&t1,  g_t1);
    cudaGetSymbolAddress((void**)&t2,  g_t2);
    cudaGetSymbolAddress((void**)&qb,  g_q);
    cudaGetSymbolAddress((void**)&kb,  g_k);
    cudaGetSymbolAddress((void**)&vb,  g_v);
    cudaGetSymbolAddress((void**)&ob,  g_o);
    cudaGetSymbolAddress((void**)&bb,  g_beta);
    cudaGetSymbolAddress((void**)&gb,  g_gate);
    cudaGetSymbolAddress((void**)&ub,  g_up);
    cudaGetSymbolAddress((void**)&nl,  g_nll);
    cudaGetSymbolAddress((void**)&mk,  g_msk);
    cudaGetSymbolAddress((void**)&lfb, g_logits_fb);

    float *dQe, *dOf, *dPm, *dRm;
    cudaGetSymbolAddress((void**)&dQe, g_Qe);
    cudaGetSymbolAddress((void**)&dOf, g_Of);
    cudaGetSymbolAddress((void**)&dPm, g_Pm);
    cudaGetSymbolAddress((void**)&dRm, g_Rm);

    uint32_t *pAh, *pAl;
    uint32_t *wqh, *wql, *wkh, *wkl, *wvh, *wvl, *woh, *wol;
    uint32_t *wgh, *wgl, *wuh, *wul, *wdh, *wdl, *lmH, *lmL;
    cudaGetSymbolAddress((void**)&pAh, g_pA_h);
    cudaGetSymbolAddress((void**)&pAl, g_pA_l);
    cudaGetSymbolAddress((void**)&wqh, g_Wq_h); cudaGetSymbolAddress((void**)&wql, g_Wq_l);
    cudaGetSymbolAddress((void**)&wkh, g_Wk_h); cudaGetSymbolAddress((void**)&wkl, g_Wk_l);
    cudaGetSymbolAddress((void**)&wvh, g_Wv_h); cudaGetSymbolAddress((void**)&wvl, g_Wv_l);
    cudaGetSymbolAddress((void**)&woh, g_Wo_h); cudaGetSymbolAddress((void**)&wol, g_Wo_l);
    cudaGetSymbolAddress((void**)&wgh, g_Wg_h); cudaGetSymbolAddress((void**)&wgl, g_Wg_l);
    cudaGetSymbolAddress((void**)&wuh, g_Wu_h); cudaGetSymbolAddress((void**)&wul, g_Wu_l);
    cudaGetSymbolAddress((void**)&wdh, g_Wd_h); cudaGetSymbolAddress((void**)&wdl, g_Wd_l);
    cudaGetSymbolAddress((void**)&lmH, g_Lm_h); cudaGetSymbolAddress((void**)&lmL, g_Lm_l);

    const int SMEM4 = (4 * 1024 + 4096) * 2 * 4;  // 65536 (MT=4)
    const int SMEM2 = (2 * 1024 + 4096) * 2 * 4;  // 49152 (MT=2)
    const int PREPSM = (6 * 64 * PSTR + 64) * 4 + 256;
    cudaFuncSetAttribute((const void*)tbgemm_k<false, 4, false>, cudaFuncAttributeMaxDynamicSharedMemorySize, SMEM4);
    cudaFuncSetAttribute((const void*)tbgemm_k<false, 4, true>,  cudaFuncAttributeMaxDynamicSharedMemorySize, SMEM4);
    cudaFuncSetAttribute((const void*)tbgemm_k<true, 2, false>,  cudaFuncAttributeMaxDynamicSharedMemorySize, SMEM2);
    cudaFuncSetAttribute((const void*)deltaprep_k, cudaFuncAttributeMaxDynamicSharedMemorySize, PREPSM);

    // ---- pack all weights ----
    pack_w_k<<<dim3(3, 384, LL), 256>>>(Wq, wqh, wql, 384, DD);
    pack_w_k<<<dim3(3, 384, LL), 256>>>(Wk, wkh, wkl, 384, DD);
    pack_w_k<<<dim3(3, 384, LL), 256>>>(Wv, wvh, wvl, 384, DD);
    pack_w_k<<<dim3(3, 384, LL), 256>>>(Wo, woh, wol, 384, DD);
    pack_w_k<<<dim3(8, 384, LL), 256>>>(Wg, wgh, wgl, 384, FFF);
    pack_w_k<<<dim3(8, 384, LL), 256>>>(Wu, wuh, wul, 384, FFF);
    pack_w_k<<<dim3(3, 1024, LL), 256>>>(Wd, wdh, wdl, 1024, DD);
    pack_w_k<<<dim3((VV + 255) / 256, 384, 1), 256>>>(lmh, lmH, lmL, 384, VV);

    const int ewarpBlocks = (TT * HH * 32 + 255) / 256;
    const int ffwBlocks = (TT * FFF / 2 + 255) / 256;

    embed_k<<<TT, 256>>>(idx, emb, hb);

    for (int l = 0; l < LL; l++) {
        const float* cq_l = convq + (size_t)l * DD * KC;
        const float* ck_l = convk + (size_t)l * DD * KC;
        const float* cv_l = convv + (size_t)l * DD * KC;
        const float* Wb_l = Wb + (size_t)l * DD * HH;
        const float* on_l = onw + (size_t)l * DKK;
        const float* an_l = anw + (size_t)l * DD;
        const float* mn_l = mnw + (size_t)l * DD;

        rmsnorm_pack_k<<<TT, 256>>>(hb, an_l, xb, pAh, pAl, DD);

        // QKV: MT=4, 2 CTAs/SM (288 blocks)
        dim3 gQKV(DD / 128, TT / 128, 3);
        tbgemm_k<false, 4, false><<<gQKV, 256, SMEM4>>>(
            pAh, pAl,
            wqh + (size_t)l * WSM, wql + (size_t)l * WSM,
            wkh + (size_t)l * WSM, wkl + (size_t)l * WSM,
            wvh + (size_t)l * WSM, wvl + (size_t)l * WSM,
            t0, t1, t2, TT, DD, DD);

        postqkv_k<<<TT, 768>>>(t0, t1, t2, cq_l, ck_l, cv_l, xb, Wb_l, qb, kb, vb, bb);

        deltaprep_k<<<dim3(NCH, HH), 256, PREPSM>>>(qb, kb, vb, bb, dQe, dOf, dPm, dRm);
        deltascan_k<<<dim3(HH, 8), 256>>>(dQe, dOf, dPm, dRm, ob);

        headnorm_pack_k<<<ewarpBlocks, 256>>>(ob, on_l, pAh, pAl);

        // Wo: MT=2 (192 blocks)
        dim3 gD(DD / 128, TT / 64, 1);
        tbgemm_k<true, 2, false><<<gD, 256, SMEM2>>>(
            pAh, pAl,
            woh + (size_t)l * WSM, wol + (size_t)l * WSM,
            woh + (size_t)l * WSM, wol + (size_t)l * WSM,
            woh + (size_t)l * WSM, wol + (size_t)l * WSM,
            hb, hb, hb, TT, DD, DD);

        rmsnorm_pack_k<<<TT, 256>>>(hb, mn_l, nullptr, pAh, pAl, DD);

        // gate+up: MT=4 (512 blocks)
        dim3 gGU(FFF / 128, TT / 128, 2);
        tbgemm_k<false, 4, false><<<gGU, 256, SMEM4>>>(
            pAh, pAl,
            wgh + (size_t)l * WGU, wgl + (size_t)l * WGU,
            wuh + (size_t)l * WGU, wul + (size_t)l * WGU,
            wuh + (size_t)l * WGU, wul + (size_t)l * WGU,
            gb, ub, ub, TT, FFF, DD);

        silu_mul_pack_k<<<ffwBlocks, 256>>>(gb, ub, pAh, pAl);

        // down: MT=2
        tbgemm_k<true, 2, false><<<gD, 256, SMEM2>>>(
            pAh, pAl,
            wdh + (size_t)l * WDN, wdl + (size_t)l * WDN,
            wdh + (size_t)l * WDN, wdl + (size_t)l * WDN,
            wdh + (size_t)l * WDN, wdl + (size_t)l * WDN,
            hb, hb, hb, TT, DD, FFF);
    }

    rmsnorm_pack_k<<<TT, 256>>>(hb, fnw, nullptr, pAh, pAl, DD);

    const size_t LOGN = (size_t)TT * VV;
    float* logits = ((size_t)out_size >= LOGN) ? out : lfb;
    // LM head: MT=4, m-fastest grid (B panel read once)
    dim3 gV(TT / 128, VV / 128, 1);
    tbgemm_k<false, 4, true><<<gV, 256, SMEM4>>>(pAh, pAl, lmH, lmL, lmH, lmL, lmH, lmL,
                                                 logits, logits, logits, TT, VV, DD);

    loss_rows_k<<<TT, 256>>>(logits, tgt, nl, mk);
    float* loss_dst = nullptr;
    if ((size_t)out_size >= LOGN + 1) loss_dst = out + LOGN;
    else if ((size_t)out_size < LOGN) loss_dst = out;
    if (loss_dst) loss_reduce_k<<<1, 256>>>(nl, mk, loss_dst);
}

// round 10
// speedup vs baseline: 1.5832x; 1.5832x over previous
#include <cuda_runtime.h>
#include <cuda_bf16.h>
#include <math.h>
#include <stdint.h>

// Problem constants
#define TT   2048
#define DD   768
#define HH   12
#define DKK  64
#define FFF  2048
#define VV   50304
#define LL   12
#define KC   4
#define EPSF 1e-6f
#define NCH  32     // chunks (T / 64)
#define PSTR 65     // padded smem stride

// packed word counts per matrix (word = uint32 = 2 bf16 packed along K)
#define WSM 294912     // 384*768   (Wq/Wk/Wv/Wo per layer)
#define WGU 786432     // 384*2048  (Wgate/Wup per layer)
#define WDN 786432     // 1024*768  (Wdown per layer)
#define WLM 19316736   // 384*50304 (lm_head)

// ---------------- scratch (__device__ globals; no allocation allowed) ----------------
__device__ float g_h[TT * DD];
__device__ float g_x[TT * DD];
__device__ float g_t0[TT * DD];
__device__ float g_t1[TT * DD];
__device__ float g_t2[TT * DD];
__device__ float g_q[TT * DD];
__device__ float g_k[TT * DD];
__device__ float g_v[TT * DD];
__device__ float g_o[TT * DD];
__device__ float g_beta[TT * HH];
__device__ float g_gate[TT * FFF];
__device__ float g_up[TT * FFF];
__device__ float g_nll[TT];
__device__ float g_msk[TT];
__device__ float g_logits_fb[(size_t)TT * VV];

// chunked-delta intermediates: [H][NCH][64][64]
__device__ float g_Qe[HH * NCH * 4096];
__device__ float g_Of[HH * NCH * 4096];
__device__ float g_Pm[HH * NCH * 4096];
__device__ float g_Rm[HH * NCH * 4096];

// packed activation A operand, max Kd=2048 -> 1024 words/row
__device__ uint32_t g_pA_h[TT * 1024];
__device__ uint32_t g_pA_l[TT * 1024];

// packed weights
__device__ uint32_t g_Wq_h[LL * WSM]; __device__ uint32_t g_Wq_l[LL * WSM];
__device__ uint32_t g_Wk_h[LL * WSM]; __device__ uint32_t g_Wk_l[LL * WSM];
__device__ uint32_t g_Wv_h[LL * WSM]; __device__ uint32_t g_Wv_l[LL * WSM];
__device__ uint32_t g_Wo_h[LL * WSM]; __device__ uint32_t g_Wo_l[LL * WSM];
__device__ uint32_t g_Wg_h[LL * WGU]; __device__ uint32_t g_Wg_l[LL * WGU];
__device__ uint32_t g_Wu_h[LL * WGU]; __device__ uint32_t g_Wu_l[LL * WGU];
__device__ uint32_t g_Wd_h[LL * WDN]; __device__ uint32_t g_Wd_l[LL * WDN];
__device__ uint32_t g_Lm_h[WLM];      __device__ uint32_t g_Lm_l[WLM];

// ---------------- helpers ----------------
__device__ __forceinline__ void mma_bf16(float* c, const uint32_t* a, const uint32_t* b) {
    asm volatile(
        "mma.sync.aligned.m16n8k16.row.col.f32.bf16.bf16.f32 "
        "{%0,%1,%2,%3}, {%4,%5,%6,%7}, {%8,%9}, {%0,%1,%2,%3};\n"
        : "+f"(c[0]), "+f"(c[1]), "+f"(c[2]), "+f"(c[3])
        : "r"(a[0]), "r"(a[1]), "r"(a[2]), "r"(a[3]), "r"(b[0]), "r"(b[1]));
}

__device__ __forceinline__ void split_pack(float x0, float x1, uint32_t& hp, uint32_t& lp) {
    __nv_bfloat16 h0 = __float2bfloat16(x0), h1 = __float2bfloat16(x1);
    float f0 = __bfloat162float(h0), f1 = __bfloat162float(h1);
    __nv_bfloat16 l0 = __float2bfloat16(x0 - f0), l1 = __float2bfloat16(x1 - f1);
    hp = (uint32_t)__bfloat16_as_ushort(h0) | ((uint32_t)__bfloat16_as_ushort(h1) << 16);
    lp = (uint32_t)__bfloat16_as_ushort(l0) | ((uint32_t)__bfloat16_as_ushort(l1) << 16);
}

// ---------------- kernels ----------------

__global__ void embed_k(const int* __restrict__ idx, const float* __restrict__ emb,
                        float* __restrict__ out) {
    int t = blockIdx.x;
    int row = idx[t];
    const float* src = emb + (size_t)row * DD;
    float* dst = out + (size_t)t * DD;
    for (int d = threadIdx.x; d < DD; d += blockDim.x) dst[d] = src[d];
}

// pack weights: src [count][2*Kw][N] fp32 -> dstH/dstL [count][Kw][N] words.
// grid: (ceil(N/256), Kw, count)
__global__ void pack_w_k(const float* __restrict__ src, uint32_t* __restrict__ dH,
                         uint32_t* __restrict__ dL, int Kw, int N) {
    int n = blockIdx.x * 256 + threadIdx.x;
    if (n >= N) return;
    int kw = blockIdx.y;
    size_t nw = (size_t)Kw * N;
    size_t bs = (size_t)blockIdx.z * 2u * nw;
    size_t bd = (size_t)blockIdx.z * nw;
    float a0 = src[bs + (size_t)(2 * kw) * N + n];
    float a1 = src[bs + (size_t)(2 * kw + 1) * N + n];
    uint32_t h, l;
    split_pack(a0, a1, h, l);
    dH[bd + (size_t)kw * N + n] = h;
    dL[bd + (size_t)kw * N + n] = l;
}

// rmsnorm; optional fp32 out; packed hi/lo words (row stride n/2)
__global__ void rmsnorm_pack_k(const float* __restrict__ in, const float* __restrict__ w,
                               float* __restrict__ outf,
                               uint32_t* __restrict__ pH, uint32_t* __restrict__ pL, int n) {
    int t = blockIdx.x;
    const float* r = in + (size_t)t * n;
    int tid = threadIdx.x;
    __shared__ float red[256];
    float s = 0.f;
    for (int i = tid; i < n; i += 256) { float vv = r[i]; s += vv * vv; }
    red[tid] = s; __syncthreads();
    for (int o = 128; o > 0; o >>= 1) { if (tid < o) red[tid] += red[tid + o]; __syncthreads(); }
    float rs = rsqrtf(red[0] / (float)n + EPSF);
    int nw = n >> 1;
    for (int i = tid; i < nw; i += 256) {
        float x0 = r[2 * i] * rs * w[2 * i];
        float x1 = r[2 * i + 1] * rs * w[2 * i + 1];
        if (outf) { outf[(size_t)t * n + 2 * i] = x0; outf[(size_t)t * n + 2 * i + 1] = x1; }
        uint32_t h, l;
        split_pack(x0, x1, h, l);
        pH[(size_t)t * nw + i] = h;
        pL[(size_t)t * nw + i] = l;
    }
}

// =======================================================================
// bf16x3 split-precision tensor-core GEMM, pre-packed operands.
// MT tiles: BM=MT*32, BN=128, BK=32. MINB = min blocks/SM for launch bounds:
//   MT=4 -> MINB=1 (needs ~150 regs; 2 CTAs/SM would spill — round 9 lesson)
//   MT=2 -> MINB=2 (fits 128 regs, 2 CTAs/SM hides sync bubbles)
// SW swaps grid axes (m-fastest) for B-panel L2 reuse on huge-N GEMMs.
// =======================================================================
template <bool ADD, int MT, bool SW, int MINB>
__global__ __launch_bounds__(256, MINB) void tbgemm_k(
    const uint32_t* __restrict__ AHg, const uint32_t* __restrict__ ALg,
    const uint32_t* __restrict__ B0H, const uint32_t* __restrict__ B0L,
    const uint32_t* __restrict__ B1H, const uint32_t* __restrict__ B1L,
    const uint32_t* __restrict__ B2H, const uint32_t* __restrict__ B2L,
    float* __restrict__ C0, float* __restrict__ C1, float* __restrict__ C2,
    int M, int N, int Kd) {
    extern __shared__ uint32_t smw[];
    const int AW = MT * 512;
    const int BUF = AW * 2 + 4096;
    const int Kw = Kd >> 1;

    const uint32_t* BHg = (blockIdx.z == 0) ? B0H : (blockIdx.z == 1 ? B1H : B2H);
    const uint32_t* BLg = (blockIdx.z == 0) ? B0L : (blockIdx.z == 1 ? B1L : B2L);
    float*          C   = (blockIdx.z == 0) ? C0  : (blockIdx.z == 1 ? C1  : C2);

    const int bm = (SW ? blockIdx.x : blockIdx.y) * (MT * 32);
    const int bn = (SW ? blockIdx.y : blockIdx.x) * 128;
    const int tid = threadIdx.x;
    const int warp = tid >> 5, lane = tid & 31;
    const int warpM = warp >> 2;
    const int warpN = warp & 3;
    const int g = lane >> 2, t4 = lane & 3;

    float acc[MT][4][4];
#pragma unroll
    for (int i = 0; i < MT; i++)
#pragma unroll
        for (int j = 0; j < 4; j++)
#pragma unroll
            for (int r = 0; r < 4; r++) acc[i][j][r] = 0.f;

    uint2 sa_h[MT], sa_l[MT];
    uint4 sb_h[2], sb_l[2];

    auto LOAD = [&](int kt) {
#pragma unroll
        for (int i = 0; i < MT; i++) {
            int id = i * 256 + tid;
            int r = id >> 3, c4 = id & 7;
            size_t off = (size_t)(bm + r) * Kw + kt * 16 + c4 * 2;
            sa_h[i] = *reinterpret_cast<const uint2*>(AHg + off);
            sa_l[i] = *reinterpret_cast<const uint2*>(ALg + off);
        }
#pragma unroll
        for (int i = 0; i < 2; i++) {
            int id = i * 256 + tid;
            int kw = id >> 5, n4 = id & 31;
            size_t off = (size_t)(kt * 16 + kw) * N + bn + n4 * 4;
            sb_h[i] = *reinterpret_cast<const uint4*>(BHg + off);
            sb_l[i] = *reinterpret_cast<const uint4*>(BLg + off);
        }
    };

    auto STORE = [&](int buf) {
        uint32_t* AH = smw + buf * BUF;
        uint32_t* AL = AH + AW;
        uint32_t* BH = AH + 2 * AW;
        uint32_t* BL = BH + 2048;
#pragma unroll
        for (int i = 0; i < MT; i++) {
            int id = i * 256 + tid;
            int r = id >> 3, c4 = id & 7;
            int off = r * 16 + ((c4 * 2) ^ ((r & 7) * 2));
            *reinterpret_cast<uint2*>(AH + off) = sa_h[i];
            *reinterpret_cast<uint2*>(AL + off) = sa_l[i];
        }
#pragma unroll
        for (int i = 0; i < 2; i++) {
            int id = i * 256 + tid;
            int kw = id >> 5, n4 = id & 31;
            int off = kw * 128 + ((n4 * 4) ^ ((kw * 8) & 127));
            *reinterpret_cast<uint4*>(BH + off) = sb_h[i];
            *reinterpret_cast<uint4*>(BL + off) = sb_l[i];
        }
    };

    auto COMPUTE = [&](int buf) {
        uint32_t* AH = smw + buf * BUF;
        uint32_t* AL = AH + AW;
        uint32_t* BH = AH + 2 * AW;
        uint32_t* BL = BH + 2048;
#pragma unroll
        for (int ks = 0; ks < 2; ks++) {
            uint32_t bh[4][2], bl[4][2];
#pragma unroll
            for (int nt = 0; nt < 4; nt++) {
                int n = warpN * 32 + nt * 8 + g;
                int k0w = ks * 8 + t4, k1w = k0w + 4;
                int o0 = k0w * 128 + (n ^ ((k0w * 8) & 127));
                int o1 = k1w * 128 + (n ^ ((k1w * 8) & 127));
                bh[nt][0] = BH[o0]; bh[nt][1] = BH[o1];
                bl[nt][0] = BL[o0]; bl[nt][1] = BL[o1];
            }
#pragma unroll
            for (int mt = 0; mt < MT; mt++) {
                uint32_t ah[4], al[4];
                int r0 = warpM * (MT * 16) + mt * 16 + g;
                int r1 = r0 + 8;
                int ka = ks * 8 + t4, kb = ka + 4;
                int o0 = r0 * 16 + (ka ^ ((r0 & 7) * 2));
                int o1 = r1 * 16 + (ka ^ ((r1 & 7) * 2));
                int o2 = r0 * 16 + (kb ^ ((r0 & 7) * 2));
                int o3 = r1 * 16 + (kb ^ ((r1 & 7) * 2));
                ah[0] = AH[o0]; ah[1] = AH[o1]; ah[2] = AH[o2]; ah[3] = AH[o3];
                al[0] = AL[o0]; al[1] = AL[o1]; al[2] = AL[o2]; al[3] = AL[o3];
#pragma unroll
                for (int nt = 0; nt < 4; nt++) {
                    mma_bf16(acc[mt][nt], al, bh[nt]);
                    mma_bf16(acc[mt][nt], ah, bl[nt]);
                    mma_bf16(acc[mt][nt], ah, bh[nt]);
                }
            }
        }
    };

    const int ntiles = Kd / 32;
    LOAD(0);
    STORE(0);
    __syncthreads();
    for (int kt = 0; kt < ntiles; kt++) {
        if (kt + 1 < ntiles) LOAD(kt + 1);
        COMPUTE(kt & 1);
        if (kt + 1 < ntiles) STORE((kt + 1) & 1);
        __syncthreads();
    }

#pragma unroll
    for (int mt = 0; mt < MT; mt++) {
        int r0 = bm + warpM * (MT * 16) + mt * 16 + g;
#pragma unroll
        for (int nt = 0; nt < 4; nt++) {
            int c0 = bn + warpN * 32 + nt * 8 + 2 * t4;
            float* p0 = C + (size_t)r0 * N + c0;
            float* p1 = C + (size_t)(r0 + 8) * N + c0;
            if (ADD) {
                p0[0] += acc[mt][nt][0]; p0[1] += acc[mt][nt][1];
                p1[0] += acc[mt][nt][2]; p1[1] += acc[mt][nt][3];
            } else {
                p0[0] = acc[mt][nt][0]; p0[1] = acc[mt][nt][1];
                p1[0] = acc[mt][nt][2]; p1[1] = acc[mt][nt][3];
            }
        }
    }
}

// =======================================================================
// Fused post-QKV, one 768-thread block per timestep.
// =======================================================================
__global__ __launch_bounds__(768) void postqkv_k(
    const float* __restrict__ t0, const float* __restrict__ t1, const float* __restrict__ t2,
    const float* __restrict__ cq, const float* __restrict__ ck, const float* __restrict__ cv,
    const float* __restrict__ x, const float* __restrict__ Wb,
    float* __restrict__ q, float* __restrict__ k, float* __restrict__ v,
    float* __restrict__ beta) {
    int t = blockIdx.x;
    int d = threadIdx.x;            // 0..767
    int h = d >> 6;
    int warp = d >> 5, lane = d & 31;
    __shared__ float sx[DD];
    __shared__ float redq[24], redk[24], redb[24];

    sx[d] = x[(size_t)t * DD + d];

    auto conv = [&](const float* src, const float* w) -> float {
        float acc = 0.f;
#pragma unroll
        for (int j = 0; j < KC; j++) {
            int tt = t - (KC - 1) + j;
            if (tt >= 0) acc += src[(size_t)tt * DD + d] * w[d * KC + j];
        }
        return acc / (1.f + __expf(-acc));
    };
    float qv = conv(t0, cq);
    float kv = conv(t1, ck);
    float vv = conv(t2, cv);

    float sq = qv * qv, sk = kv * kv;
#pragma unroll
    for (int o = 16; o > 0; o >>= 1) {
        sq += __shfl_xor_sync(0xffffffffu, sq, o);
        sk += __shfl_xor_sync(0xffffffffu, sk, o);
    }
    if (lane == 0) { redq[warp] = sq; redk[warp] = sk; }
    __syncthreads();

    {
        int h2 = warp >> 1, half = warp & 1;
        float sb = 0.f;
        for (int i = half * 384 + lane; i < half * 384 + 384; i += 32)
            sb += sx[i] * Wb[i * HH + h2];
#pragma unroll
        for (int o = 16; o > 0; o >>= 1) sb += __shfl_xor_sync(0xffffffffu, sb, o);
        if (lane == 0) redb[warp] = sb;
    }

    float rq = rsqrtf(redq[2 * h] + redq[2 * h + 1] + EPSF);
    float rk = rsqrtf(redk[2 * h] + redk[2 * h + 1] + EPSF);
    size_t gi = (size_t)t * DD + d;
    q[gi] = qv * rq;
    k[gi] = kv * rk;
    v[gi] = vv;
    __syncthreads();
    if (d < HH) beta[t * HH + d] = 1.f / (1.f + __expf(-(redb[2 * d] + redb[2 * d + 1])));
}

// =======================================================================
// Chunked delta rule, phase 1 (parallel; WY form).
// =======================================================================
__global__ __launch_bounds__(256) void deltaprep_k(
    const float* __restrict__ q, const float* __restrict__ k,
    const float* __restrict__ v, const float* __restrict__ beta,
    float* __restrict__ Qe, float* __restrict__ Of,
    float* __restrict__ Pm, float* __restrict__ Rm) {
    extern __shared__ float sm[];
    float* sK = sm;
    float* sV = sK + 64 * PSTR;
    float* sQ = sV + 64 * PSTR;
    float* bA = sQ + 64 * PSTR;
    float* bT = bA + 64 * PSTR;
    float* bU = bT + 64 * PSTR;
    float* sb = bU + 64 * PSTR;
    const int c = blockIdx.x, h = blockIdx.y;
    const int tid = threadIdx.x;
    const int tr = (tid >> 4) * 4, tc = (tid & 15) * 4;

    for (int i = tid; i < 4096; i += 256) {
        int t = i >> 6, d = i & 63;
        size_t g = (size_t)(c * 64 + t) * DD + h * 64 + d;
        sK[t * PSTR + d] = k[g];
        sV[t * PSTR + d] = v[g];
        sQ[t * PSTR + d] = q[g];
    }
    if (tid < 64) sb[tid] = beta[(c * 64 + tid) * HH + h];
    __syncthreads();

    {
        float acc[4][4] = {};
        for (int m = 0; m < 64; m++) {
            float a[4], b[4];
#pragma unroll
            for (int i = 0; i < 4; i++) a[i] = sK[(tr + i) * PSTR + m];
#pragma unroll
            for (int j = 0; j < 4; j++) b[j] = sK[(tc + j) * PSTR + m];
#pragma unroll
            for (int i = 0; i < 4; i++)
#pragma unroll
                for (int j = 0; j < 4; j++) acc[i][j] += a[i] * b[j];
        }
#pragma unroll
        for (int i = 0; i < 4; i++)
#pragma unroll
            for (int j = 0; j < 4; j++) {
                int t = tr + i, s = tc + j;
                bA[t * PSTR + s] = (s < t) ? acc[i][j] * sb[t] : 0.f;
            }
    }
    __syncthreads();

    for (int t = 0; t < 64; t++) {
        if (tid < 64) {
            float acc = (t == tid) ? 1.f : 0.f;
            for (int s = 0; s < t; s++) acc -= bA[t * PSTR + s] * bT[s * PSTR + tid];
            bT[t * PSTR + tid] = acc;
        }
        __syncthreads();
    }

    {
        float accW[4][4] = {}, accU[4][4] = {};
        for (int m = 0; m < 64; m++) {
            float a[4];
#pragma unroll
            for (int i = 0; i < 4; i++) a[i] = bT[(tr + i) * PSTR + m] * sb[m];
            float bk[4], bv[4];
#pragma unroll
            for (int j = 0; j < 4; j++) {
                bk[j] = sK[m * PSTR + tc + j];
                bv[j] = sV[m * PSTR + tc + j];
            }
#pragma unroll
            for (int i = 0; i < 4; i++)
#pragma unroll
                for (int j = 0; j < 4; j++) {
                    accW[i][j] += a[i] * bk[j];
                    accU[i][j] += a[i] * bv[j];
                }
        }
        __syncthreads();
#pragma unroll
        for (int i = 0; i < 4; i++)
#pragma unroll
            for (int j = 0; j < 4; j++) {
                bA[(tr + i) * PSTR + tc + j] = accW[i][j];
                bU[(tr + i) * PSTR + tc + j] = accU[i][j];
            }
    }
    __syncthreads();

    {
        float acc[4][4] = {};
        for (int m = 0; m < 64; m++) {
            float a[4], b[4];
#pragma unroll
            for (int i = 0; i < 4; i++) a[i] = sQ[(tr + i) * PSTR + m];
#pragma unroll
            for (int j = 0; j < 4; j++) b[j] = sK[(tc + j) * PSTR + m];
#pragma unroll
            for (int i = 0; i < 4; i++)
#pragma unroll
                for (int j = 0; j < 4; j++) acc[i][j] += a[i] * b[j];
        }
        __syncthreads();
#pragma unroll
        for (int i = 0; i < 4; i++)
#pragma unroll
            for (int j = 0; j < 4; j++) {
                int t = tr + i, s = tc + j;
                bT[t * PSTR + s] = (s <= t) ? acc[i][j] : 0.f;
            }
    }
    __syncthreads();

    const size_t base = ((size_t)(h * NCH + c)) << 12;

    {
        float accQ[4][4] = {}, accO[4][4] = {};
        for (int m = 0; m < 64; m++) {
            float a[4];
#pragma unroll
            for (int i = 0; i < 4; i++) a[i] = bT[(tr + i) * PSTR + m];
            float bw[4], bu[4];
#pragma unroll
            for (int j = 0; j < 4; j++) {
                bw[j] = bA[m * PSTR + tc + j];
                bu[j] = bU[m * PSTR + tc + j];
            }
#pragma unroll
            for (int i = 0; i < 4; i++)
#pragma unroll
                for (int j = 0; j < 4; j++) {
                    accQ[i][j] += a[i] * bw[j];
                    accO[i][j] += a[i] * bu[j];
                }
        }
#pragma unroll
        for (int i = 0; i < 4; i++)
#pragma unroll
            for (int j = 0; j < 4; j++) {
                Qe[base + (tr + i) * 64 + tc + j] =
                    sQ[(tr + i) * PSTR + tc + j] - accQ[i][j];
                Of[base + (tr + i) * 64 + tc + j] = accO[i][j];
            }
    }

    {
        float accP[4][4] = {}, accR[4][4] = {};
        for (int m = 0; m < 64; m++) {
            float a[4];
#pragma unroll
            for (int i = 0; i < 4; i++) a[i] = sK[m * PSTR + tr + i];
            float bw[4], bu[4];
#pragma unroll
            for (int j = 0; j < 4; j++) {
                bw[j] = bA[m * PSTR + tc + j];
                bu[j] = bU[m * PSTR + tc + j];
            }
#pragma unroll
            for (int i = 0; i < 4; i++)
#pragma unroll
                for (int j = 0; j < 4; j++) {
                    accP[i][j] += a[i] * bw[j];
                    accR[i][j] += a[i] * bu[j];
                }
        }
#pragma unroll
        for (int i = 0; i < 4; i++)
#pragma unroll
            for (int j = 0; j < 4; j++) {
                Pm[base + (tr + i) * 64 + tc + j] = accP[i][j];
                Rm[base + (tr + i) * 64 + tc + j] = accR[i][j];
            }
    }
}

// Chunked delta rule, phase 2 (scan)
__global__ __launch_bounds__(256) void deltascan_k(
    const float* __restrict__ Qe, const float* __restrict__ Of,
    const float* __restrict__ Pm, const float* __restrict__ Rm,
    float* __restrict__ o) {
    const int h = blockIdx.x, cg = blockIdx.y;
    const int tid = threadIdx.x;
    __shared__ float sQe[64 * PSTR], sP[64 * PSTR];
    __shared__ float S[64 * 9], sOf[512], sR[512];

    for (int i = tid; i < 64 * 9; i += 256) S[i] = 0.f;
    __syncthreads();

#pragma unroll 1
    for (int c = 0; c < NCH; c++) {
        size_t base = ((size_t)(h * NCH + c)) << 12;
        for (int i = tid; i < 4096; i += 256) {
            int t = i >> 6, d = i & 63;
            sQe[t * PSTR + d] = Qe[base + i];
            sP[t * PSTR + d] = Pm[base + i];
        }
        for (int i = tid; i < 512; i += 256) {
            int t = i >> 3, j = i & 7;
            sOf[i] = Of[base + t * 64 + cg * 8 + j];
            sR[i] = Rm[base + t * 64 + cg * 8 + j];
        }
        __syncthreads();

        float outv[2], ns[2];
#pragma unroll
        for (int u = 0; u < 2; u++) {
            int idx = tid + u * 256;
            int t = idx >> 3, j = idx & 7;
            float a1 = sOf[idx];
            float a2 = S[t * 9 + j] + sR[idx];
#pragma unroll
            for (int m = 0; m < 64; m++) {
                float sv = S[m * 9 + j];
                a1 += sQe[t * PSTR + m] * sv;
                a2 -= sP[t * PSTR + m] * sv;
            }
            outv[u] = a1;
            ns[u] = a2;
        }
#pragma unroll
        for (int u = 0; u < 2; u++) {
            int idx = tid + u * 256;
            int t = idx >> 3, j = idx & 7;
            o[(size_t)(c * 64 + t) * DD + h * 64 + cg * 8 + j] = outv[u];
        }
        __syncthreads();
#pragma unroll
        for (int u = 0; u < 2; u++) {
            int idx = tid + u * 256;
            int t = idx >> 3, j = idx & 7;
            S[t * 9 + j] = ns[u];
        }
        __syncthreads();
    }
}

// per-64 rmsnorm * w of delta output -> packed words (feeds Wo GEMM)
__global__ void headnorm_pack_k(const float* __restrict__ o, const float* __restrict__ w,
                                uint32_t* __restrict__ pH, uint32_t* __restrict__ pL) {
    int gw = (blockIdx.x * blockDim.x + threadIdx.x) >> 5;
    int lane = threadIdx.x & 31;
    if (gw >= TT * HH) return;
    const float* r = o + (size_t)gw * 64;
    float a = r[2 * lane], b = r[2 * lane + 1];
    float s = a * a + b * b;
#pragma unroll
    for (int os = 16; os > 0; os >>= 1) s += __shfl_xor_sync(0xffffffffu, s, os);
    float rs = rsqrtf(s * (1.f / 64.f) + EPSF);
    int t = gw / HH, h = gw % HH;
    uint32_t hw, lw;
    split_pack(a * rs * w[2 * lane], b * rs * w[2 * lane + 1], hw, lw);
    size_t wi = (size_t)t * 384 + h * 32 + lane;
    pH[wi] = hw;
    pL[wi] = lw;
}

// silu(g)*u, writes packed words; i indexes element pairs
__global__ void silu_mul_pack_k(const float* __restrict__ g, const float* __restrict__ u,
                                uint32_t* __restrict__ pH, uint32_t* __restrict__ pL) {
    int i = blockIdx.x * blockDim.x + threadIdx.x;
    if (i >= TT * FFF / 2) return;
    float g0 = g[2 * i], g1 = g[2 * i + 1];
    float y0 = (g0 / (1.f + __expf(-g0))) * u[2 * i];
    float y1 = (g1 / (1.f + __expf(-g1))) * u[2 * i + 1];
    uint32_t h, l;
    split_pack(y0, y1, h, l);
    pH[i] = h;
    pL[i] = l;
}

// online-softmax cross-entropy row pass (single read of logits)
__global__ void loss_rows_k(const float* __restrict__ logits, const int* __restrict__ tgt,
                            float* __restrict__ nll, float* __restrict__ msk) {
    int t = blockIdx.x;
    const float* r = logits + (size_t)t * VV;
    int tid = threadIdx.x;
    __shared__ float sm_m[256], sm_s[256];
    float m = -INFINITY, s = 0.f;
    for (int i = tid; i < VV; i += 256) {
        float v = r[i];
        if (v > m) { s = s * __expf(m - v) + 1.f; m = v; }
        else s += __expf(v - m);
    }
    sm_m[tid] = m; sm_s[tid] = s;
    __syncthreads();
    for (int o = 128; o > 0; o >>= 1) {
        if (tid < o) {
            float m1 = sm_m[tid], m2 = sm_m[tid + o];
            float M = fmaxf(m1, m2);
            sm_s[tid] = sm_s[tid] * __expf(m1 - M) + sm_s[tid + o] * __expf(m2 - M);
            sm_m[tid] = M;
        }
        __syncthreads();
    }
    if (tid == 0) {
        float rowmax = sm_m[0], denom = sm_s[0];
        int tg = tgt[t];
        float mask = (tg >= 0) ? 1.f : 0.f;
        int tc = tg < 0 ? 0 : (tg > VV - 1 ? VV - 1 : tg);
        float lp = r[tc] - rowmax - logf(denom);
        nll[t] = -lp * mask;
        msk[t] = mask;
    }
}

__global__ void loss_reduce_k(const float* __restrict__ nll, const float* __restrict__ msk,
                              float* __restrict__ out) {
    int tid = threadIdx.x;
    __shared__ float r1[256], r2[256];
    float s = 0.f, c = 0.f;
    for (int i = tid; i < TT; i += 256) { s += nll[i]; c += msk[i]; }
    r1[tid] = s; r2[tid] = c; __syncthreads();
    for (int o = 128; o > 0; o >>= 1) {
        if (tid < o) { r1[tid] += r1[tid + o]; r2[tid] += r2[tid + o]; }
        __syncthreads();
    }
    if (tid == 0) out[0] = r1[0] / fmaxf(r2[0], 1.f);
}

// ---------------- host launcher ----------------
extern "C" void kernel_launch(void* const* d_in, const int* in_sizes, int n_in,
                              void* d_out, int out_size) {
    const int*   idx   = (const int*)d_in[0];
    const int*   tgt   = (const int*)d_in[1];
    const float* emb   = (const float*)d_in[2];
    const float* Wq    = (const float*)d_in[3];
    const float* Wk    = (const float*)d_in[4];
    const float* Wv    = (const float*)d_in[5];
    const float* convq = (const float*)d_in[6];
    const float* convk = (const float*)d_in[7];
    const float* convv = (const float*)d_in[8];
    const float* Wb    = (const float*)d_in[9];
    const float* onw   = (const float*)d_in[10];
    const float* Wo    = (const float*)d_in[11];
    const float* anw   = (const float*)d_in[12];
    const float* mnw   = (const float*)d_in[13];
    const float* Wg    = (const float*)d_in[14];
    const float* Wu    = (const float*)d_in[15];
    const float* Wd    = (const float*)d_in[16];
    const float* fnw   = (const float*)d_in[17];
    const float* lmh   = (const float*)d_in[18];
    float* out = (float*)d_out;

    float *hb, *xb, *t0, *t1, *t2, *qb, *kb, *vb, *ob, *bb, *gb, *ub, *nl, *mk, *lfb;
    cudaGetSymbolAddress((void**)&hb,  g_h);
    cudaGetSymbolAddress((void**)&xb,  g_x);
    cudaGetSymbolAddress((void**)&t0,  g_t0);
    cudaGetSymbolAddress((void**)&t1,  g_t1);
    cudaGetSymbolAddress((void**)&t2,  g_t2);
    cudaGetSymbolAddress((void**)&qb,  g_q);
    cudaGetSymbolAddress((void**)&kb,  g_k);
    cudaGetSymbolAddress((void**)&vb,  g_v);
    cudaGetSymbolAddress((void**)&ob,  g_o);
    cudaGetSymbolAddress((void**)&bb,  g_beta);
    cudaGetSymbolAddress((void**)&gb,  g_gate);
    cudaGetSymbolAddress((void**)&ub,  g_up);
    cudaGetSymbolAddress((void**)&nl,  g_nll);
    cudaGetSymbolAddress((void**)&mk,  g_msk);
    cudaGetSymbolAddress((void**)&lfb, g_logits_fb);

    float *dQe, *dOf, *dPm, *dRm;
    cudaGetSymbolAddress((void**)&dQe, g_Qe);
    cudaGetSymbolAddress((void**)&dOf, g_Of);
    cudaGetSymbolAddress((void**)&dPm, g_Pm);
    cudaGetSymbolAddress((void**)&dRm, g_Rm);

    uint32_t *pAh, *pAl;
    uint32_t *wqh, *wql, *wkh, *wkl, *wvh, *wvl, *woh, *wol;
    uint32_t *wgh, *wgl, *wuh, *wul, *wdh, *wdl, *lmH, *lmL;
    cudaGetSymbolAddress((void**)&pAh, g_pA_h);
    cudaGetSymbolAddress((void**)&pAl, g_pA_l);
    cudaGetSymbolAddress((void**)&wqh, g_Wq_h); cudaGetSymbolAddress((void**)&wql, g_Wq_l);
    cudaGetSymbolAddress((void**)&wkh, g_Wk_h); cudaGetSymbolAddress((void**)&wkl, g_Wk_l);
    cudaGetSymbolAddress((void**)&wvh, g_Wv_h); cudaGetSymbolAddress((void**)&wvl, g_Wv_l);
    cudaGetSymbolAddress((void**)&woh, g_Wo_h); cudaGetSymbolAddress((void**)&wol, g_Wo_l);
    cudaGetSymbolAddress((void**)&wgh, g_Wg_h); cudaGetSymbolAddress((void**)&wgl, g_Wg_l);
    cudaGetSymbolAddress((void**)&wuh, g_Wu_h); cudaGetSymbolAddress((void**)&wul, g_Wu_l);
    cudaGetSymbolAddress((void**)&wdh, g_Wd_h); cudaGetSymbolAddress((void**)&wdl, g_Wd_l);
    cudaGetSymbolAddress((void**)&lmH, g_Lm_h); cudaGetSymbolAddress((void**)&lmL, g_Lm_l);

    const int SMEM4 = (4 * 1024 + 4096) * 2 * 4;  // 65536 (MT=4)
    const int SMEM2 = (2 * 1024 + 4096) * 2 * 4;  // 49152 (MT=2)
    const int PREPSM = (6 * 64 * PSTR + 64) * 4 + 256;
    cudaFuncSetAttribute((const void*)tbgemm_k<false, 4, false, 1>, cudaFuncAttributeMaxDynamicSharedMemorySize, SMEM4);
    cudaFuncSetAttribute((const void*)tbgemm_k<false, 4, true, 1>,  cudaFuncAttributeMaxDynamicSharedMemorySize, SMEM4);
    cudaFuncSetAttribute((const void*)tbgemm_k<true, 2, false, 2>,  cudaFuncAttributeMaxDynamicSharedMemorySize, SMEM2);
    cudaFuncSetAttribute((const void*)deltaprep_k, cudaFuncAttributeMaxDynamicSharedMemorySize, PREPSM);

    // ---- pack all weights ----
    pack_w_k<<<dim3(3, 384, LL), 256>>>(Wq, wqh, wql, 384, DD);
    pack_w_k<<<dim3(3, 384, LL), 256>>>(Wk, wkh, wkl, 384, DD);
    pack_w_k<<<dim3(3, 384, LL), 256>>>(Wv, wvh, wvl, 384, DD);
    pack_w_k<<<dim3(3, 384, LL), 256>>>(Wo, woh, wol, 384, DD);
    pack_w_k<<<dim3(8, 384, LL), 256>>>(Wg, wgh, wgl, 384, FFF);
    pack_w_k<<<dim3(8, 384, LL), 256>>>(Wu, wuh, wul, 384, FFF);
    pack_w_k<<<dim3(3, 1024, LL), 256>>>(Wd, wdh, wdl, 1024, DD);
    pack_w_k<<<dim3((VV + 255) / 256, 384, 1), 256>>>(lmh, lmH, lmL, 384, VV);

    const int ewarpBlocks = (TT * HH * 32 + 255) / 256;
    const int ffwBlocks = (TT * FFF / 2 + 255) / 256;

    embed_k<<<TT, 256>>>(idx, emb, hb);

    for (int l = 0; l < LL; l++) {
        const float* cq_l = convq + (size_t)l * DD * KC;
        const float* ck_l = convk + (size_t)l * DD * KC;
        const float* cv_l = convv + (size_t)l * DD * KC;
        const float* Wb_l = Wb + (size_t)l * DD * HH;
        const float* on_l = onw + (size_t)l * DKK;
        const float* an_l = anw + (size_t)l * DD;
        const float* mn_l = mnw + (size_t)l * DD;

        rmsnorm_pack_k<<<TT, 256>>>(hb, an_l, xb, pAh, pAl, DD);

        // QKV: MT=4 @ (256,1) — no spills (round-9 lesson), 288 blocks
        dim3 gQKV(DD / 128, TT / 128, 3);
        tbgemm_k<false, 4, false, 1><<<gQKV, 256, SMEM4>>>(
            pAh, pAl,
            wqh + (size_t)l * WSM, wql + (size_t)l * WSM,
            wkh + (size_t)l * WSM, wkl + (size_t)l * WSM,
            wvh + (size_t)l * WSM, wvl + (size_t)l * WSM,
            t0, t1, t2, TT, DD, DD);

        postqkv_k<<<TT, 768>>>(t0, t1, t2, cq_l, ck_l, cv_l, xb, Wb_l, qb, kb, vb, bb);

        deltaprep_k<<<dim3(NCH, HH), 256, PREPSM>>>(qb, kb, vb, bb, dQe, dOf, dPm, dRm);
        deltascan_k<<<dim3(HH, 8), 256>>>(dQe, dOf, dPm, dRm, ob);

        headnorm_pack_k<<<ewarpBlocks, 256>>>(ob, on_l, pAh, pAl);

        // Wo: MT=2 @ (256,2), 192 blocks
        dim3 gD(DD / 128, TT / 64, 1);
        tbgemm_k<true, 2, false, 2><<<gD, 256, SMEM2>>>(
            pAh, pAl,
            woh + (size_t)l * WSM, wol + (size_t)l * WSM,
            woh + (size_t)l * WSM, wol + (size_t)l * WSM,
            woh + (size_t)l * WSM, wol + (size_t)l * WSM,
            hb, hb, hb, TT, DD, DD);

        rmsnorm_pack_k<<<TT, 256>>>(hb, mn_l, nullptr, pAh, pAl, DD);

        // gate+up: MT=4 @ (256,1), 512 blocks
        dim3 gGU(FFF / 128, TT / 128, 2);
        tbgemm_k<false, 4, false, 1><<<gGU, 256, SMEM4>>>(
            pAh, pAl,
            wgh + (size_t)l * WGU, wgl + (size_t)l * WGU,
            wuh + (size_t)l * WGU, wul + (size_t)l * WGU,
            wuh + (size_t)l * WGU, wul + (size_t)l * WGU,
            gb, ub, ub, TT, FFF, DD);

        silu_mul_pack_k<<<ffwBlocks, 256>>>(gb, ub, pAh, pAl);

        // down: MT=2 @ (256,2)
        tbgemm_k<true, 2, false, 2><<<gD, 256, SMEM2>>>(
            pAh, pAl,
            wdh + (size_t)l * WDN, wdl + (size_t)l * WDN,
            wdh + (size_t)l * WDN, wdl + (size_t)l * WDN,
            wdh + (size_t)l * WDN, wdl + (size_t)l * WDN,
            hb, hb, hb, TT, DD, FFF);
    }

    rmsnorm_pack_k<<<TT, 256>>>(hb, fnw, nullptr, pAh, pAl, DD);

    const size_t LOGN = (size_t)TT * VV;
    float* logits = ((size_t)out_size >= LOGN) ? out : lfb;
    // LM head: MT=4 @ (256,1), m-fastest grid (B panel read once), 6288 blocks
    dim3 gV(TT / 128, VV / 128, 1);
    tbgemm_k<false, 4, true, 1><<<gV, 256, SMEM4>>>(pAh, pAl, lmH, lmL, lmH, lmL, lmH, lmL,
                                                    logits, logits, logits, TT, VV, DD);

    loss_rows_k<<<TT, 256>>>(logits, tgt, nl, mk);
    float* loss_dst = nullptr;
    if ((size_t)out_size >= LOGN + 1) loss_dst = out + LOGN;
    else if ((size_t)out_size < LOGN) loss_dst = out;
    if (loss_dst) loss_reduce_k<<<1, 256>>>(nl, mk, loss_dst);
}

// round 11
// speedup vs baseline: 1.7025x; 1.0753x over previous
#include <cuda_runtime.h>
#include <cuda_bf16.h>
#include <math.h>
#include <stdint.h>

// Problem constants
#define TT   2048
#define DD   768
#define HH   12
#define DKK  64
#define FFF  2048
#define VV   50304
#define LL   12
#define KC   4
#define EPSF 1e-6f
#define NCH  32     // chunks (T / 64)
#define PSTR 65     // padded smem stride

// packed word counts per matrix (word = uint32 = 2 bf16 packed along K)
#define WSM 294912     // 384*768   (Wq/Wk/Wv/Wo per layer)
#define WGU 786432     // 384*2048  (Wgate/Wup per layer)
#define WDN 786432     // 1024*768  (Wdown per layer)
#define WLM 19316736   // 384*50304 (lm_head)

// ---------------- scratch (__device__ globals; no allocation allowed) ----------------
__device__ float g_h[TT * DD];
__device__ float g_x[TT * DD];
__device__ float g_t0[TT * DD];
__device__ float g_t1[TT * DD];
__device__ float g_t2[TT * DD];
__device__ float g_q[TT * DD];
__device__ float g_k[TT * DD];
__device__ float g_v[TT * DD];
__device__ float g_o[TT * DD];
__device__ float g_beta[TT * HH];
__device__ float g_gate[TT * FFF];
__device__ float g_up[TT * FFF];
__device__ float g_nll[TT];
__device__ float g_msk[TT];
__device__ float g_logits_fb[(size_t)TT * VV];

// chunked-delta intermediates: [H][NCH][64][64]
__device__ float g_Qe[HH * NCH * 4096];
__device__ float g_Of[HH * NCH * 4096];
__device__ float g_Pm[HH * NCH * 4096];
__device__ float g_Rm[HH * NCH * 4096];

// packed activation A operand, max Kd=2048 -> 1024 words/row
__device__ __align__(256) uint32_t g_pA_h[TT * 1024];
__device__ __align__(256) uint32_t g_pA_l[TT * 1024];

// packed weights
__device__ __align__(256) uint32_t g_Wq_h[LL * WSM]; __device__ __align__(256) uint32_t g_Wq_l[LL * WSM];
__device__ __align__(256) uint32_t g_Wk_h[LL * WSM]; __device__ __align__(256) uint32_t g_Wk_l[LL * WSM];
__device__ __align__(256) uint32_t g_Wv_h[LL * WSM]; __device__ __align__(256) uint32_t g_Wv_l[LL * WSM];
__device__ __align__(256) uint32_t g_Wo_h[LL * WSM]; __device__ __align__(256) uint32_t g_Wo_l[LL * WSM];
__device__ __align__(256) uint32_t g_Wg_h[LL * WGU]; __device__ __align__(256) uint32_t g_Wg_l[LL * WGU];
__device__ __align__(256) uint32_t g_Wu_h[LL * WGU]; __device__ __align__(256) uint32_t g_Wu_l[LL * WGU];
__device__ __align__(256) uint32_t g_Wd_h[LL * WDN]; __device__ __align__(256) uint32_t g_Wd_l[LL * WDN];
__device__ __align__(256) uint32_t g_Lm_h[WLM];      __device__ __align__(256) uint32_t g_Lm_l[WLM];

// ---------------- helpers ----------------
__device__ __forceinline__ void mma_bf16(float* c, const uint32_t* a, const uint32_t* b) {
    asm volatile(
        "mma.sync.aligned.m16n8k16.row.col.f32.bf16.bf16.f32 "
        "{%0,%1,%2,%3}, {%4,%5,%6,%7}, {%8,%9}, {%0,%1,%2,%3};\n"
        : "+f"(c[0]), "+f"(c[1]), "+f"(c[2]), "+f"(c[3])
        : "r"(a[0]), "r"(a[1]), "r"(a[2]), "r"(a[3]), "r"(b[0]), "r"(b[1]));
}

__device__ __forceinline__ void split_pack(float x0, float x1, uint32_t& hp, uint32_t& lp) {
    __nv_bfloat16 h0 = __float2bfloat16(x0), h1 = __float2bfloat16(x1);
    float f0 = __bfloat162float(h0), f1 = __bfloat162float(h1);
    __nv_bfloat16 l0 = __float2bfloat16(x0 - f0), l1 = __float2bfloat16(x1 - f1);
    hp = (uint32_t)__bfloat16_as_ushort(h0) | ((uint32_t)__bfloat16_as_ushort(h1) << 16);
    lp = (uint32_t)__bfloat16_as_ushort(l0) | ((uint32_t)__bfloat16_as_ushort(l1) << 16);
}

__device__ __forceinline__ uint32_t smem_u32(const void* p) {
    uint32_t a;
    asm("{ .reg .u64 t; cvta.to.shared.u64 t, %1; cvt.u32.u64 %0, t; }" : "=r"(a) : "l"(p));
    return a;
}
__device__ __forceinline__ void cp_async8(uint32_t saddr, const void* gptr) {
    asm volatile("cp.async.ca.shared.global [%0], [%1], 8;" :: "r"(saddr), "l"(gptr));
}
__device__ __forceinline__ void cp_async16(uint32_t saddr, const void* gptr) {
    asm volatile("cp.async.cg.shared.global [%0], [%1], 16;" :: "r"(saddr), "l"(gptr));
}
#define CP_COMMIT() asm volatile("cp.async.commit_group;" ::: "memory")
#define CP_WAIT0()  asm volatile("cp.async.wait_group 0;" ::: "memory")
#define CP_WAIT1()  asm volatile("cp.async.wait_group 1;" ::: "memory")

// ---------------- kernels ----------------

__global__ void embed_k(const int* __restrict__ idx, const float* __restrict__ emb,
                        float* __restrict__ out) {
    int t = blockIdx.x;
    int row = idx[t];
    const float* src = emb + (size_t)row * DD;
    float* dst = out + (size_t)t * DD;
    for (int d = threadIdx.x; d < DD; d += blockDim.x) dst[d] = src[d];
}

// pack weights: src [count][2*Kw][N] fp32 -> dstH/dstL [count][Kw][N] words.
__global__ void pack_w_k(const float* __restrict__ src, uint32_t* __restrict__ dH,
                         uint32_t* __restrict__ dL, int Kw, int N) {
    int n = blockIdx.x * 256 + threadIdx.x;
    if (n >= N) return;
    int kw = blockIdx.y;
    size_t nw = (size_t)Kw * N;
    size_t bs = (size_t)blockIdx.z * 2u * nw;
    size_t bd = (size_t)blockIdx.z * nw;
    float a0 = src[bs + (size_t)(2 * kw) * N + n];
    float a1 = src[bs + (size_t)(2 * kw + 1) * N + n];
    uint32_t h, l;
    split_pack(a0, a1, h, l);
    dH[bd + (size_t)kw * N + n] = h;
    dL[bd + (size_t)kw * N + n] = l;
}

// rmsnorm; optional fp32 out; packed hi/lo words (row stride n/2)
__global__ void rmsnorm_pack_k(const float* __restrict__ in, const float* __restrict__ w,
                               float* __restrict__ outf,
                               uint32_t* __restrict__ pH, uint32_t* __restrict__ pL, int n) {
    int t = blockIdx.x;
    const float* r = in + (size_t)t * n;
    int tid = threadIdx.x;
    __shared__ float red[256];
    float s = 0.f;
    for (int i = tid; i < n; i += 256) { float vv = r[i]; s += vv * vv; }
    red[tid] = s; __syncthreads();
    for (int o = 128; o > 0; o >>= 1) { if (tid < o) red[tid] += red[tid + o]; __syncthreads(); }
    float rs = rsqrtf(red[0] / (float)n + EPSF);
    int nw = n >> 1;
    for (int i = tid; i < nw; i += 256) {
        float x0 = r[2 * i] * rs * w[2 * i];
        float x1 = r[2 * i + 1] * rs * w[2 * i + 1];
        if (outf) { outf[(size_t)t * n + 2 * i] = x0; outf[(size_t)t * n + 2 * i + 1] = x1; }
        uint32_t h, l;
        split_pack(x0, x1, h, l);
        pH[(size_t)t * nw + i] = h;
        pL[(size_t)t * nw + i] = l;
    }
}

// =======================================================================
// bf16x3 split-precision tensor-core GEMM, pre-packed operands, cp.async
// staging (no register staging -> MT=4 fits 128 regs at 2 CTAs/SM).
// MT tiles: BM=MT*32, BN=128, BK=32; __launch_bounds__(256, MINB).
// SW swaps grid axes (m-fastest) for B-panel L2 reuse on huge-N GEMMs.
// =======================================================================
template <bool ADD, int MT, bool SW, int MINB>
__global__ __launch_bounds__(256, MINB) void tbgemm_k(
    const uint32_t* __restrict__ AHg, const uint32_t* __restrict__ ALg,
    const uint32_t* __restrict__ B0H, const uint32_t* __restrict__ B0L,
    const uint32_t* __restrict__ B1H, const uint32_t* __restrict__ B1L,
    const uint32_t* __restrict__ B2H, const uint32_t* __restrict__ B2L,
    float* __restrict__ C0, float* __restrict__ C1, float* __restrict__ C2,
    int M, int N, int Kd) {
    extern __shared__ uint32_t smw[];
    const int AW = MT * 512;            // A words per hi or lo section
    const int BUF = AW * 2 + 4096;      // words per stage
    const int Kw = Kd >> 1;
    const uint32_t sbase = smem_u32(smw);

    const uint32_t* BHg = (blockIdx.z == 0) ? B0H : (blockIdx.z == 1 ? B1H : B2H);
    const uint32_t* BLg = (blockIdx.z == 0) ? B0L : (blockIdx.z == 1 ? B1L : B2L);
    float*          C   = (blockIdx.z == 0) ? C0  : (blockIdx.z == 1 ? C1  : C2);

    const int bm = (SW ? blockIdx.x : blockIdx.y) * (MT * 32);
    const int bn = (SW ? blockIdx.y : blockIdx.x) * 128;
    const int tid = threadIdx.x;
    const int warp = tid >> 5, lane = tid & 31;
    const int warpM = warp >> 2;
    const int warpN = warp & 3;
    const int g = lane >> 2, t4 = lane & 3;

    float acc[MT][4][4];
#pragma unroll
    for (int i = 0; i < MT; i++)
#pragma unroll
        for (int j = 0; j < 4; j++)
#pragma unroll
            for (int r = 0; r < 4; r++) acc[i][j][r] = 0.f;

    // async load of tile kt into stage buf
    auto ISSUE = [&](int kt, int buf) {
        uint32_t b0 = sbase + (uint32_t)buf * BUF * 4;
#pragma unroll
        for (int i = 0; i < MT; i++) {
            int id = i * 256 + tid;
            int r = id >> 3, c4 = id & 7;
            size_t off = (size_t)(bm + r) * Kw + kt * 16 + c4 * 2;
            uint32_t so = (uint32_t)(r * 16 + ((c4 * 2) ^ ((r & 7) * 2))) * 4;
            cp_async8(b0 + so, AHg + off);
            cp_async8(b0 + AW * 4 + so, ALg + off);
        }
#pragma unroll
        for (int i = 0; i < 2; i++) {
            int id = i * 256 + tid;
            int kw = id >> 5, n4 = id & 31;
            size_t off = (size_t)(kt * 16 + kw) * N + bn + n4 * 4;
            uint32_t so = (uint32_t)(kw * 128 + ((n4 * 4) ^ ((kw * 8) & 127))) * 4;
            cp_async16(b0 + 2 * AW * 4 + so, BHg + off);
            cp_async16(b0 + 2 * AW * 4 + 8192 + so, BLg + off);
        }
        CP_COMMIT();
    };

    auto COMPUTE = [&](int buf) {
        uint32_t* AH = smw + buf * BUF;
        uint32_t* AL = AH + AW;
        uint32_t* BH = AH + 2 * AW;
        uint32_t* BL = BH + 2048;
#pragma unroll
        for (int ks = 0; ks < 2; ks++) {
            uint32_t bh[4][2], bl[4][2];
#pragma unroll
            for (int nt = 0; nt < 4; nt++) {
                int n = warpN * 32 + nt * 8 + g;
                int k0w = ks * 8 + t4, k1w = k0w + 4;
                int o0 = k0w * 128 + (n ^ ((k0w * 8) & 127));
                int o1 = k1w * 128 + (n ^ ((k1w * 8) & 127));
                bh[nt][0] = BH[o0]; bh[nt][1] = BH[o1];
                bl[nt][0] = BL[o0]; bl[nt][1] = BL[o1];
            }
#pragma unroll
            for (int mt = 0; mt < MT; mt++) {
                uint32_t ah[4], al[4];
                int r0 = warpM * (MT * 16) + mt * 16 + g;
                int r1 = r0 + 8;
                int ka = ks * 8 + t4, kb = ka + 4;
                int o0 = r0 * 16 + (ka ^ ((r0 & 7) * 2));
                int o1 = r1 * 16 + (ka ^ ((r1 & 7) * 2));
                int o2 = r0 * 16 + (kb ^ ((r0 & 7) * 2));
                int o3 = r1 * 16 + (kb ^ ((r1 & 7) * 2));
                ah[0] = AH[o0]; ah[1] = AH[o1]; ah[2] = AH[o2]; ah[3] = AH[o3];
                al[0] = AL[o0]; al[1] = AL[o1]; al[2] = AL[o2]; al[3] = AL[o3];
#pragma unroll
                for (int nt = 0; nt < 4; nt++) {
                    mma_bf16(acc[mt][nt], al, bh[nt]);
                    mma_bf16(acc[mt][nt], ah, bl[nt]);
                    mma_bf16(acc[mt][nt], ah, bh[nt]);
                }
            }
        }
    };

    const int ntiles = Kd / 32;
    ISSUE(0, 0);
    for (int kt = 0; kt < ntiles; kt++) {
        if (kt + 1 < ntiles) {
            ISSUE(kt + 1, (kt + 1) & 1);
            CP_WAIT1();
        } else {
            CP_WAIT0();
        }
        __syncthreads();
        COMPUTE(kt & 1);
        __syncthreads();
    }

#pragma unroll
    for (int mt = 0; mt < MT; mt++) {
        int r0 = bm + warpM * (MT * 16) + mt * 16 + g;
#pragma unroll
        for (int nt = 0; nt < 4; nt++) {
            int c0 = bn + warpN * 32 + nt * 8 + 2 * t4;
            float* p0 = C + (size_t)r0 * N + c0;
            float* p1 = C + (size_t)(r0 + 8) * N + c0;
            if (ADD) {
                p0[0] += acc[mt][nt][0]; p0[1] += acc[mt][nt][1];
                p1[0] += acc[mt][nt][2]; p1[1] += acc[mt][nt][3];
            } else {
                p0[0] = acc[mt][nt][0]; p0[1] = acc[mt][nt][1];
                p1[0] = acc[mt][nt][2]; p1[1] = acc[mt][nt][3];
            }
        }
    }
}

// =======================================================================
// Fused post-QKV, one 768-thread block per timestep.
// =======================================================================
__global__ __launch_bounds__(768) void postqkv_k(
    const float* __restrict__ t0, const float* __restrict__ t1, const float* __restrict__ t2,
    const float* __restrict__ cq, const float* __restrict__ ck, const float* __restrict__ cv,
    const float* __restrict__ x, const float* __restrict__ Wb,
    float* __restrict__ q, float* __restrict__ k, float* __restrict__ v,
    float* __restrict__ beta) {
    int t = blockIdx.x;
    int d = threadIdx.x;            // 0..767
    int h = d >> 6;
    int warp = d >> 5, lane = d & 31;
    __shared__ float sx[DD];
    __shared__ float redq[24], redk[24], redb[24];

    sx[d] = x[(size_t)t * DD + d];

    auto conv = [&](const float* src, const float* w) -> float {
        float acc = 0.f;
#pragma unroll
        for (int j = 0; j < KC; j++) {
            int tt = t - (KC - 1) + j;
            if (tt >= 0) acc += src[(size_t)tt * DD + d] * w[d * KC + j];
        }
        return acc / (1.f + __expf(-acc));
    };
    float qv = conv(t0, cq);
    float kv = conv(t1, ck);
    float vv = conv(t2, cv);

    float sq = qv * qv, sk = kv * kv;
#pragma unroll
    for (int o = 16; o > 0; o >>= 1) {
        sq += __shfl_xor_sync(0xffffffffu, sq, o);
        sk += __shfl_xor_sync(0xffffffffu, sk, o);
    }
    if (lane == 0) { redq[warp] = sq; redk[warp] = sk; }
    __syncthreads();

    {
        int h2 = warp >> 1, half = warp & 1;
        float sb = 0.f;
        for (int i = half * 384 + lane; i < half * 384 + 384; i += 32)
            sb += sx[i] * Wb[i * HH + h2];
#pragma unroll
        for (int o = 16; o > 0; o >>= 1) sb += __shfl_xor_sync(0xffffffffu, sb, o);
        if (lane == 0) redb[warp] = sb;
    }

    float rq = rsqrtf(redq[2 * h] + redq[2 * h + 1] + EPSF);
    float rk = rsqrtf(redk[2 * h] + redk[2 * h + 1] + EPSF);
    size_t gi = (size_t)t * DD + d;
    q[gi] = qv * rq;
    k[gi] = kv * rk;
    v[gi] = vv;
    __syncthreads();
    if (d < HH) beta[t * HH + d] = 1.f / (1.f + __expf(-(redb[2 * d] + redb[2 * d + 1])));
}

// =======================================================================
// Chunked delta rule, phase 1 (parallel; WY form).
// =======================================================================
__global__ __launch_bounds__(256) void deltaprep_k(
    const float* __restrict__ q, const float* __restrict__ k,
    const float* __restrict__ v, const float* __restrict__ beta,
    float* __restrict__ Qe, float* __restrict__ Of,
    float* __restrict__ Pm, float* __restrict__ Rm) {
    extern __shared__ float sm[];
    float* sK = sm;
    float* sV = sK + 64 * PSTR;
    float* sQ = sV + 64 * PSTR;
    float* bA = sQ + 64 * PSTR;
    float* bT = bA + 64 * PSTR;
    float* bU = bT + 64 * PSTR;
    float* sb = bU + 64 * PSTR;
    const int c = blockIdx.x, h = blockIdx.y;
    const int tid = threadIdx.x;
    const int tr = (tid >> 4) * 4, tc = (tid & 15) * 4;

    for (int i = tid; i < 4096; i += 256) {
        int t = i >> 6, d = i & 63;
        size_t g = (size_t)(c * 64 + t) * DD + h * 64 + d;
        sK[t * PSTR + d] = k[g];
        sV[t * PSTR + d] = v[g];
        sQ[t * PSTR + d] = q[g];
    }
    if (tid < 64) sb[tid] = beta[(c * 64 + tid) * HH + h];
    __syncthreads();

    {
        float acc[4][4] = {};
        for (int m = 0; m < 64; m++) {
            float a[4], b[4];
#pragma unroll
            for (int i = 0; i < 4; i++) a[i] = sK[(tr + i) * PSTR + m];
#pragma unroll
            for (int j = 0; j < 4; j++) b[j] = sK[(tc + j) * PSTR + m];
#pragma unroll
            for (int i = 0; i < 4; i++)
#pragma unroll
                for (int j = 0; j < 4; j++) acc[i][j] += a[i] * b[j];
        }
#pragma unroll
        for (int i = 0; i < 4; i++)
#pragma unroll
            for (int j = 0; j < 4; j++) {
                int t = tr + i, s = tc + j;
                bA[t * PSTR + s] = (s < t) ? acc[i][j] * sb[t] : 0.f;
            }
    }
    __syncthreads();

    for (int t = 0; t < 64; t++) {
        if (tid < 64) {
            float acc = (t == tid) ? 1.f : 0.f;
            for (int s = 0; s < t; s++) acc -= bA[t * PSTR + s] * bT[s * PSTR + tid];
            bT[t * PSTR + tid] = acc;
        }
        __syncthreads();
    }

    {
        float accW[4][4] = {}, accU[4][4] = {};
        for (int m = 0; m < 64; m++) {
            float a[4];
#pragma unroll
            for (int i = 0; i < 4; i++) a[i] = bT[(tr + i) * PSTR + m] * sb[m];
            float bk[4], bv[4];
#pragma unroll
            for (int j = 0; j < 4; j++) {
                bk[j] = sK[m * PSTR + tc + j];
                bv[j] = sV[m * PSTR + tc + j];
            }
#pragma unroll
            for (int i = 0; i < 4; i++)
#pragma unroll
                for (int j = 0; j < 4; j++) {
                    accW[i][j] += a[i] * bk[j];
                    accU[i][j] += a[i] * bv[j];
                }
        }
        __syncthreads();
#pragma unroll
        for (int i = 0; i < 4; i++)
#pragma unroll
            for (int j = 0; j < 4; j++) {
                bA[(tr + i) * PSTR + tc + j] = accW[i][j];
                bU[(tr + i) * PSTR + tc + j] = accU[i][j];
            }
    }
    __syncthreads();

    {
        float acc[4][4] = {};
        for (int m = 0; m < 64; m++) {
            float a[4], b[4];
#pragma unroll
            for (int i = 0; i < 4; i++) a[i] = sQ[(tr + i) * PSTR + m];
#pragma unroll
            for (int j = 0; j < 4; j++) b[j] = sK[(tc + j) * PSTR + m];
#pragma unroll
            for (int i = 0; i < 4; i++)
#pragma unroll
                for (int j = 0; j < 4; j++) acc[i][j] += a[i] * b[j];
        }
        __syncthreads();
#pragma unroll
        for (int i = 0; i < 4; i++)
#pragma unroll
            for (int j = 0; j < 4; j++) {
                int t = tr + i, s = tc + j;
                bT[t * PSTR + s] = (s <= t) ? acc[i][j] : 0.f;
            }
    }
    __syncthreads();

    const size_t base = ((size_t)(h * NCH + c)) << 12;

    {
        float accQ[4][4] = {}, accO[4][4] = {};
        for (int m = 0; m < 64; m++) {
            float a[4];
#pragma unroll
            for (int i = 0; i < 4; i++) a[i] = bT[(tr + i) * PSTR + m];
            float bw[4], bu[4];
#pragma unroll
            for (int j = 0; j < 4; j++) {
                bw[j] = bA[m * PSTR + tc + j];
                bu[j] = bU[m * PSTR + tc + j];
            }
#pragma unroll
            for (int i = 0; i < 4; i++)
#pragma unroll
                for (int j = 0; j < 4; j++) {
                    accQ[i][j] += a[i] * bw[j];
                    accO[i][j] += a[i] * bu[j];
                }
        }
#pragma unroll
        for (int i = 0; i < 4; i++)
#pragma unroll
            for (int j = 0; j < 4; j++) {
                Qe[base + (tr + i) * 64 + tc + j] =
                    sQ[(tr + i) * PSTR + tc + j] - accQ[i][j];
                Of[base + (tr + i) * 64 + tc + j] = accO[i][j];
            }
    }

    {
        float accP[4][4] = {}, accR[4][4] = {};
        for (int m = 0; m < 64; m++) {
            float a[4];
#pragma unroll
            for (int i = 0; i < 4; i++) a[i] = sK[m * PSTR + tr + i];
            float bw[4], bu[4];
#pragma unroll
            for (int j = 0; j < 4; j++) {
                bw[j] = bA[m * PSTR + tc + j];
                bu[j] = bU[m * PSTR + tc + j];
            }
#pragma unroll
            for (int i = 0; i < 4; i++)
#pragma unroll
                for (int j = 0; j < 4; j++) {
                    accP[i][j] += a[i] * bw[j];
                    accR[i][j] += a[i] * bu[j];
                }
        }
#pragma unroll
        for (int i = 0; i < 4; i++)
#pragma unroll
            for (int j = 0; j < 4; j++) {
                Pm[base + (tr + i) * 64 + tc + j] = accP[i][j];
                Rm[base + (tr + i) * 64 + tc + j] = accR[i][j];
            }
    }
}

// Chunked delta rule, phase 2 (scan)
__global__ __launch_bounds__(256) void deltascan_k(
    const float* __restrict__ Qe, const float* __restrict__ Of,
    const float* __restrict__ Pm, const float* __restrict__ Rm,
    float* __restrict__ o) {
    const int h = blockIdx.x, cg = blockIdx.y;
    const int tid = threadIdx.x;
    __shared__ float sQe[64 * PSTR], sP[64 * PSTR];
    __shared__ float S[64 * 9], sOf[512], sR[512];

    for (int i = tid; i < 64 * 9; i += 256) S[i] = 0.f;
    __syncthreads();

#pragma unroll 1
    for (int c = 0; c < NCH; c++) {
        size_t base = ((size_t)(h * NCH + c)) << 12;
        for (int i = tid; i < 4096; i += 256) {
            int t = i >> 6, d = i & 63;
            sQe[t * PSTR + d] = Qe[base + i];
            sP[t * PSTR + d] = Pm[base + i];
        }
        for (int i = tid; i < 512; i += 256) {
            int t = i >> 3, j = i & 7;
            sOf[i] = Of[base + t * 64 + cg * 8 + j];
            sR[i] = Rm[base + t * 64 + cg * 8 + j];
        }
        __syncthreads();

        float outv[2], ns[2];
#pragma unroll
        for (int u = 0; u < 2; u++) {
            int idx = tid + u * 256;
            int t = idx >> 3, j = idx & 7;
            float a1 = sOf[idx];
            float a2 = S[t * 9 + j] + sR[idx];
#pragma unroll
            for (int m = 0; m < 64; m++) {
                float sv = S[m * 9 + j];
                a1 += sQe[t * PSTR + m] * sv;
                a2 -= sP[t * PSTR + m] * sv;
            }
            outv[u] = a1;
            ns[u] = a2;
        }
#pragma unroll
        for (int u = 0; u < 2; u++) {
            int idx = tid + u * 256;
            int t = idx >> 3, j = idx & 7;
            o[(size_t)(c * 64 + t) * DD + h * 64 + cg * 8 + j] = outv[u];
        }
        __syncthreads();
#pragma unroll
        for (int u = 0; u < 2; u++) {
            int idx = tid + u * 256;
            int t = idx >> 3, j = idx & 7;
            S[t * 9 + j] = ns[u];
        }
        __syncthreads();
    }
}

// per-64 rmsnorm * w of delta output -> packed words (feeds Wo GEMM)
__global__ void headnorm_pack_k(const float* __restrict__ o, const float* __restrict__ w,
                                uint32_t* __restrict__ pH, uint32_t* __restrict__ pL) {
    int gw = (blockIdx.x * blockDim.x + threadIdx.x) >> 5;
    int lane = threadIdx.x & 31;
    if (gw >= TT * HH) return;
    const float* r = o + (size_t)gw * 64;
    float a = r[2 * lane], b = r[2 * lane + 1];
    float s = a * a + b * b;
#pragma unroll
    for (int os = 16; os > 0; os >>= 1) s += __shfl_xor_sync(0xffffffffu, s, os);
    float rs = rsqrtf(s * (1.f / 64.f) + EPSF);
    int t = gw / HH, h = gw % HH;
    uint32_t hw, lw;
    split_pack(a * rs * w[2 * lane], b * rs * w[2 * lane + 1], hw, lw);
    size_t wi = (size_t)t * 384 + h * 32 + lane;
    pH[wi] = hw;
    pL[wi] = lw;
}

// silu(g)*u, writes packed words; i indexes element pairs
__global__ void silu_mul_pack_k(const float* __restrict__ g, const float* __restrict__ u,
                                uint32_t* __restrict__ pH, uint32_t* __restrict__ pL) {
    int i = blockIdx.x * blockDim.x + threadIdx.x;
    if (i >= TT * FFF / 2) return;
    float g0 = g[2 * i], g1 = g[2 * i + 1];
    float y0 = (g0 / (1.f + __expf(-g0))) * u[2 * i];
    float y1 = (g1 / (1.f + __expf(-g1))) * u[2 * i + 1];
    uint32_t h, l;
    split_pack(y0, y1, h, l);
    pH[i] = h;
    pL[i] = l;
}

// online-softmax cross-entropy row pass (single read of logits)
__global__ void loss_rows_k(const float* __restrict__ logits, const int* __restrict__ tgt,
                            float* __restrict__ nll, float* __restrict__ msk) {
    int t = blockIdx.x;
    const float* r = logits + (size_t)t * VV;
    int tid = threadIdx.x;
    __shared__ float sm_m[256], sm_s[256];
    float m = -INFINITY, s = 0.f;
    for (int i = tid; i < VV; i += 256) {
        float v = r[i];
        if (v > m) { s = s * __expf(m - v) + 1.f; m = v; }
        else s += __expf(v - m);
    }
    sm_m[tid] = m; sm_s[tid] = s;
    __syncthreads();
    for (int o = 128; o > 0; o >>= 1) {
        if (tid < o) {
            float m1 = sm_m[tid], m2 = sm_m[tid + o];
            float M = fmaxf(m1, m2);
            sm_s[tid] = sm_s[tid] * __expf(m1 - M) + sm_s[tid + o] * __expf(m2 - M);
            sm_m[tid] = M;
        }
        __syncthreads();
    }
    if (tid == 0) {
        float rowmax = sm_m[0], denom = sm_s[0];
        int tg = tgt[t];
        float mask = (tg >= 0) ? 1.f : 0.f;
        int tc = tg < 0 ? 0 : (tg > VV - 1 ? VV - 1 : tg);
        float lp = r[tc] - rowmax - logf(denom);
        nll[t] = -lp * mask;
        msk[t] = mask;
    }
}

__global__ void loss_reduce_k(const float* __restrict__ nll, const float* __restrict__ msk,
                              float* __restrict__ out) {
    int tid = threadIdx.x;
    __shared__ float r1[256], r2[256];
    float s = 0.f, c = 0.f;
    for (int i = tid; i < TT; i += 256) { s += nll[i]; c += msk[i]; }
    r1[tid] = s; r2[tid] = c; __syncthreads();
    for (int o = 128; o > 0; o >>= 1) {
        if (tid < o) { r1[tid] += r1[tid + o]; r2[tid] += r2[tid + o]; }
        __syncthreads();
    }
    if (tid == 0) out[0] = r1[0] / fmaxf(r2[0], 1.f);
}

// ---------------- host launcher ----------------
extern "C" void kernel_launch(void* const* d_in, const int* in_sizes, int n_in,
                              void* d_out, int out_size) {
    const int*   idx   = (const int*)d_in[0];
    const int*   tgt   = (const int*)d_in[1];
    const float* emb   = (const float*)d_in[2];
    const float* Wq    = (const float*)d_in[3];
    const float* Wk    = (const float*)d_in[4];
    const float* Wv    = (const float*)d_in[5];
    const float* convq = (const float*)d_in[6];
    const float* convk = (const float*)d_in[7];
    const float* convv = (const float*)d_in[8];
    const float* Wb    = (const float*)d_in[9];
    const float* onw   = (const float*)d_in[10];
    const float* Wo    = (const float*)d_in[11];
    const float* anw   = (const float*)d_in[12];
    const float* mnw   = (const float*)d_in[13];
    const float* Wg    = (const float*)d_in[14];
    const float* Wu    = (const float*)d_in[15];
    const float* Wd    = (const float*)d_in[16];
    const float* fnw   = (const float*)d_in[17];
    const float* lmh   = (const float*)d_in[18];
    float* out = (float*)d_out;

    float *hb, *xb, *t0, *t1, *t2, *qb, *kb, *vb, *ob, *bb, *gb, *ub, *nl, *mk, *lfb;
    cudaGetSymbolAddress((void**)&hb,  g_h);
    cudaGetSymbolAddress((void**)&xb,  g_x);
    cudaGetSymbolAddress((void**)&t0,  g_t0);
    cudaGetSymbolAddress((void**)&t1,  g_t1);
    cudaGetSymbolAddress((void**)&t2,  g_t2);
    cudaGetSymbolAddress((void**)&qb,  g_q);
    cudaGetSymbolAddress((void**)&kb,  g_k);
    cudaGetSymbolAddress((void**)&vb,  g_v);
    cudaGetSymbolAddress((void**)&ob,  g_o);
    cudaGetSymbolAddress((void**)&bb,  g_beta);
    cudaGetSymbolAddress((void**)&gb,  g_gate);
    cudaGetSymbolAddress((void**)&ub,  g_up);
    cudaGetSymbolAddress((void**)&nl,  g_nll);
    cudaGetSymbolAddress((void**)&mk,  g_msk);
    cudaGetSymbolAddress((void**)&lfb, g_logits_fb);

    float *dQe, *dOf, *dPm, *dRm;
    cudaGetSymbolAddress((void**)&dQe, g_Qe);
    cudaGetSymbolAddress((void**)&dOf, g_Of);
    cudaGetSymbolAddress((void**)&dPm, g_Pm);
    cudaGetSymbolAddress((void**)&dRm, g_Rm);

    uint32_t *pAh, *pAl;
    uint32_t *wqh, *wql, *wkh, *wkl, *wvh, *wvl, *woh, *wol;
    uint32_t *wgh, *wgl, *wuh, *wul, *wdh, *wdl, *lmH, *lmL;
    cudaGetSymbolAddress((void**)&pAh, g_pA_h);
    cudaGetSymbolAddress((void**)&pAl, g_pA_l);
    cudaGetSymbolAddress((void**)&wqh, g_Wq_h); cudaGetSymbolAddress((void**)&wql, g_Wq_l);
    cudaGetSymbolAddress((void**)&wkh, g_Wk_h); cudaGetSymbolAddress((void**)&wkl, g_Wk_l);
    cudaGetSymbolAddress((void**)&wvh, g_Wv_h); cudaGetSymbolAddress((void**)&wvl, g_Wv_l);
    cudaGetSymbolAddress((void**)&woh, g_Wo_h); cudaGetSymbolAddress((void**)&wol, g_Wo_l);
    cudaGetSymbolAddress((void**)&wgh, g_Wg_h); cudaGetSymbolAddress((void**)&wgl, g_Wg_l);
    cudaGetSymbolAddress((void**)&wuh, g_Wu_h); cudaGetSymbolAddress((void**)&wul, g_Wu_l);
    cudaGetSymbolAddress((void**)&wdh, g_Wd_h); cudaGetSymbolAddress((void**)&wdl, g_Wd_l);
    cudaGetSymbolAddress((void**)&lmH, g_Lm_h); cudaGetSymbolAddress((void**)&lmL, g_Lm_l);

    const int SMEM4 = (4 * 1024 + 4096) * 2 * 4;  // 65536 (MT=4)
    const int SMEM2 = (2 * 1024 + 4096) * 2 * 4;  // 49152 (MT=2)
    const int PREPSM = (6 * 64 * PSTR + 64) * 4 + 256;
    cudaFuncSetAttribute((const void*)tbgemm_k<false, 4, false, 2>, cudaFuncAttributeMaxDynamicSharedMemorySize, SMEM4);
    cudaFuncSetAttribute((const void*)tbgemm_k<false, 4, true, 2>,  cudaFuncAttributeMaxDynamicSharedMemorySize, SMEM4);
    cudaFuncSetAttribute((const void*)tbgemm_k<true, 2, false, 2>,  cudaFuncAttributeMaxDynamicSharedMemorySize, SMEM2);
    cudaFuncSetAttribute((const void*)deltaprep_k, cudaFuncAttributeMaxDynamicSharedMemorySize, PREPSM);

    // ---- pack all weights ----
    pack_w_k<<<dim3(3, 384, LL), 256>>>(Wq, wqh, wql, 384, DD);
    pack_w_k<<<dim3(3, 384, LL), 256>>>(Wk, wkh, wkl, 384, DD);
    pack_w_k<<<dim3(3, 384, LL), 256>>>(Wv, wvh, wvl, 384, DD);
    pack_w_k<<<dim3(3, 384, LL), 256>>>(Wo, woh, wol, 384, DD);
    pack_w_k<<<dim3(8, 384, LL), 256>>>(Wg, wgh, wgl, 384, FFF);
    pack_w_k<<<dim3(8, 384, LL), 256>>>(Wu, wuh, wul, 384, FFF);
    pack_w_k<<<dim3(3, 1024, LL), 256>>>(Wd, wdh, wdl, 1024, DD);
    pack_w_k<<<dim3((VV + 255) / 256, 384, 1), 256>>>(lmh, lmH, lmL, 384, VV);

    const int ewarpBlocks = (TT * HH * 32 + 255) / 256;
    const int ffwBlocks = (TT * FFF / 2 + 255) / 256;

    embed_k<<<TT, 256>>>(idx, emb, hb);

    for (int l = 0; l < LL; l++) {
        const float* cq_l = convq + (size_t)l * DD * KC;
        const float* ck_l = convk + (size_t)l * DD * KC;
        const float* cv_l = convv + (size_t)l * DD * KC;
        const float* Wb_l = Wb + (size_t)l * DD * HH;
        const float* on_l = onw + (size_t)l * DKK;
        const float* an_l = anw + (size_t)l * DD;
        const float* mn_l = mnw + (size_t)l * DD;

        rmsnorm_pack_k<<<TT, 256>>>(hb, an_l, xb, pAh, pAl, DD);

        // QKV: MT=4 @ (256,2) with cp.async (no reg staging -> no spill)
        dim3 gQKV(DD / 128, TT / 128, 3);
        tbgemm_k<false, 4, false, 2><<<gQKV, 256, SMEM4>>>(
            pAh, pAl,
            wqh + (size_t)l * WSM, wql + (size_t)l * WSM,
            wkh + (size_t)l * WSM, wkl + (size_t)l * WSM,
            wvh + (size_t)l * WSM, wvl + (size_t)l * WSM,
            t0, t1, t2, TT, DD, DD);

        postqkv_k<<<TT, 768>>>(t0, t1, t2, cq_l, ck_l, cv_l, xb, Wb_l, qb, kb, vb, bb);

        deltaprep_k<<<dim3(NCH, HH), 256, PREPSM>>>(qb, kb, vb, bb, dQe, dOf, dPm, dRm);
        deltascan_k<<<dim3(HH, 8), 256>>>(dQe, dOf, dPm, dRm, ob);

        headnorm_pack_k<<<ewarpBlocks, 256>>>(ob, on_l, pAh, pAl);

        // Wo: MT=2 @ (256,2), 192 blocks
        dim3 gD(DD / 128, TT / 64, 1);
        tbgemm_k<true, 2, false, 2><<<gD, 256, SMEM2>>>(
            pAh, pAl,
            woh + (size_t)l * WSM, wol + (size_t)l * WSM,
            woh + (size_t)l * WSM, wol + (size_t)l * WSM,
            woh + (size_t)l * WSM, wol + (size_t)l * WSM,
            hb, hb, hb, TT, DD, DD);

        rmsnorm_pack_k<<<TT, 256>>>(hb, mn_l, nullptr, pAh, pAl, DD);

        // gate+up: MT=4 @ (256,2), 512 blocks
        dim3 gGU(FFF / 128, TT / 128, 2);
        tbgemm_k<false, 4, false, 2><<<gGU, 256, SMEM4>>>(
            pAh, pAl,
            wgh + (size_t)l * WGU, wgl + (size_t)l * WGU,
            wuh + (size_t)l * WGU, wul + (size_t)l * WGU,
            wuh + (size_t)l * WGU, wul + (size_t)l * WGU,
            gb, ub, ub, TT, FFF, DD);

        silu_mul_pack_k<<<ffwBlocks, 256>>>(gb, ub, pAh, pAl);

        // down: MT=2 @ (256,2)
        tbgemm_k<true, 2, false, 2><<<gD, 256, SMEM2>>>(
            pAh, pAl,
            wdh + (size_t)l * WDN, wdl + (size_t)l * WDN,
            wdh + (size_t)l * WDN, wdl + (size_t)l * WDN,
            wdh + (size_t)l * WDN, wdl + (size_t)l * WDN,
            hb, hb, hb, TT, DD, FFF);
    }

    rmsnorm_pack_k<<<TT, 256>>>(hb, fnw, nullptr, pAh, pAl, DD);

    const size_t LOGN = (size_t)TT * VV;
    float* logits = ((size_t)out_size >= LOGN) ? out : lfb;
    // LM head: MT=4 @ (256,2), m-fastest grid (B panel read once), 6288 blocks
    dim3 gV(TT / 128, VV / 128, 1);
    tbgemm_k<false, 4, true, 2><<<gV, 256, SMEM4>>>(pAh, pAl, lmH, lmL, lmH, lmL, lmH, lmL,
                                                    logits, logits, logits, TT, VV, DD);

    loss_rows_k<<<TT, 256>>>(logits, tgt, nl, mk);
    float* loss_dst = nullptr;
    if ((size_t)out_size >= LOGN + 1) loss_dst = out + LOGN;
    else if ((size_t)out_size < LOGN) loss_dst = out;
    if (loss_dst) loss_reduce_k<<<1, 256>>>(nl, mk, loss_dst);
}

// round 12
// speedup vs baseline: 1.7041x; 1.0010x over previous
#include <cuda_runtime.h>
#include <cuda_bf16.h>
#include <math.h>
#include <stdint.h>

// Problem constants
#define TT   2048
#define DD   768
#define HH   12
#define DKK  64
#define FFF  2048
#define VV   50304
#define LL   12
#define KC   4
#define EPSF 1e-6f
#define NCH  32     // chunks (T / 64)
#define PSTR 65     // padded smem stride

// packed word counts per matrix (word = uint32 = 2 bf16 packed along K)
#define WSM 294912     // 384*768   (Wq/Wk/Wv/Wo per layer)
#define WGU 786432     // 384*2048  (Wgate/Wup per layer)
#define WDN 786432     // 1024*768  (Wdown per layer)
#define WLM 19316736   // 384*50304 (lm_head)

// ---------------- scratch (__device__ globals; no allocation allowed) ----------------
__device__ float g_h[TT * DD];
__device__ float g_x[TT * DD];
__device__ float g_t0[TT * DD];
__device__ float g_t1[TT * DD];
__device__ float g_t2[TT * DD];
__device__ float g_q[TT * DD];
__device__ float g_k[TT * DD];
__device__ float g_v[TT * DD];
__device__ float g_o[TT * DD];
__device__ float g_beta[TT * HH];
__device__ float g_gate[TT * FFF];
__device__ float g_up[TT * FFF];
__device__ float g_nll[TT];
__device__ float g_msk[TT];
__device__ float g_logits_fb[(size_t)TT * VV];

// chunked-delta intermediates: [H][NCH][64][64]
__device__ float g_Qe[HH * NCH * 4096];
__device__ float g_Of[HH * NCH * 4096];
__device__ float g_Pm[HH * NCH * 4096];
__device__ float g_Rm[HH * NCH * 4096];

// packed activation A operand, max Kd=2048 -> 1024 words/row
__device__ __align__(256) uint32_t g_pA_h[TT * 1024];
__device__ __align__(256) uint32_t g_pA_l[TT * 1024];

// packed weights
__device__ __align__(256) uint32_t g_Wq_h[LL * WSM]; __device__ __align__(256) uint32_t g_Wq_l[LL * WSM];
__device__ __align__(256) uint32_t g_Wk_h[LL * WSM]; __device__ __align__(256) uint32_t g_Wk_l[LL * WSM];
__device__ __align__(256) uint32_t g_Wv_h[LL * WSM]; __device__ __align__(256) uint32_t g_Wv_l[LL * WSM];
__device__ __align__(256) uint32_t g_Wo_h[LL * WSM]; __device__ __align__(256) uint32_t g_Wo_l[LL * WSM];
__device__ __align__(256) uint32_t g_Wg_h[LL * WGU]; __device__ __align__(256) uint32_t g_Wg_l[LL * WGU];
__device__ __align__(256) uint32_t g_Wu_h[LL * WGU]; __device__ __align__(256) uint32_t g_Wu_l[LL * WGU];
__device__ __align__(256) uint32_t g_Wd_h[LL * WDN]; __device__ __align__(256) uint32_t g_Wd_l[LL * WDN];
__device__ __align__(256) uint32_t g_Lm_h[WLM];      __device__ __align__(256) uint32_t g_Lm_l[WLM];

// ---------------- helpers ----------------
__device__ __forceinline__ void mma_bf16(float* c, const uint32_t* a, const uint32_t* b) {
    asm volatile(
        "mma.sync.aligned.m16n8k16.row.col.f32.bf16.bf16.f32 "
        "{%0,%1,%2,%3}, {%4,%5,%6,%7}, {%8,%9}, {%0,%1,%2,%3};\n"
        : "+f"(c[0]), "+f"(c[1]), "+f"(c[2]), "+f"(c[3])
        : "r"(a[0]), "r"(a[1]), "r"(a[2]), "r"(a[3]), "r"(b[0]), "r"(b[1]));
}

__device__ __forceinline__ void split_pack(float x0, float x1, uint32_t& hp, uint32_t& lp) {
    __nv_bfloat16 h0 = __float2bfloat16(x0), h1 = __float2bfloat16(x1);
    float f0 = __bfloat162float(h0), f1 = __bfloat162float(h1);
    __nv_bfloat16 l0 = __float2bfloat16(x0 - f0), l1 = __float2bfloat16(x1 - f1);
    hp = (uint32_t)__bfloat16_as_ushort(h0) | ((uint32_t)__bfloat16_as_ushort(h1) << 16);
    lp = (uint32_t)__bfloat16_as_ushort(l0) | ((uint32_t)__bfloat16_as_ushort(l1) << 16);
}

__device__ __forceinline__ uint32_t smem_u32(const void* p) {
    uint32_t a;
    asm("{ .reg .u64 t; cvta.to.shared.u64 t, %1; cvt.u32.u64 %0, t; }" : "=r"(a) : "l"(p));
    return a;
}
__device__ __forceinline__ void cp_async8(uint32_t saddr, const void* gptr) {
    asm volatile("cp.async.ca.shared.global [%0], [%1], 8;" :: "r"(saddr), "l"(gptr));
}
__device__ __forceinline__ void cp_async16(uint32_t saddr, const void* gptr) {
    asm volatile("cp.async.cg.shared.global [%0], [%1], 16;" :: "r"(saddr), "l"(gptr));
}
#define CP_COMMIT() asm volatile("cp.async.commit_group;" ::: "memory")
#define CP_WAIT0()  asm volatile("cp.async.wait_group 0;" ::: "memory")

// ---------------- kernels ----------------

__global__ void embed_k(const int* __restrict__ idx, const float* __restrict__ emb,
                        float* __restrict__ out) {
    int t = blockIdx.x;
    int row = idx[t];
    const float* src = emb + (size_t)row * DD;
    float* dst = out + (size_t)t * DD;
    for (int d = threadIdx.x; d < DD; d += blockDim.x) dst[d] = src[d];
}

// pack weights: src [count][2*Kw][N] fp32 -> dstH/dstL [count][Kw][N] words.
__global__ void pack_w_k(const float* __restrict__ src, uint32_t* __restrict__ dH,
                         uint32_t* __restrict__ dL, int Kw, int N) {
    int n = blockIdx.x * 256 + threadIdx.x;
    if (n >= N) return;
    int kw = blockIdx.y;
    size_t nw = (size_t)Kw * N;
    size_t bs = (size_t)blockIdx.z * 2u * nw;
    size_t bd = (size_t)blockIdx.z * nw;
    float a0 = src[bs + (size_t)(2 * kw) * N + n];
    float a1 = src[bs + (size_t)(2 * kw + 1) * N + n];
    uint32_t h, l;
    split_pack(a0, a1, h, l);
    dH[bd + (size_t)kw * N + n] = h;
    dL[bd + (size_t)kw * N + n] = l;
}

// rmsnorm; optional fp32 out; packed hi/lo words (row stride n/2)
__global__ void rmsnorm_pack_k(const float* __restrict__ in, const float* __restrict__ w,
                               float* __restrict__ outf,
                               uint32_t* __restrict__ pH, uint32_t* __restrict__ pL, int n) {
    int t = blockIdx.x;
    const float* r = in + (size_t)t * n;
    int tid = threadIdx.x;
    __shared__ float red[256];
    float s = 0.f;
    for (int i = tid; i < n; i += 256) { float vv = r[i]; s += vv * vv; }
    red[tid] = s; __syncthreads();
    for (int o = 128; o > 0; o >>= 1) { if (tid < o) red[tid] += red[tid + o]; __syncthreads(); }
    float rs = rsqrtf(red[0] / (float)n + EPSF);
    int nw = n >> 1;
    for (int i = tid; i < nw; i += 256) {
        float x0 = r[2 * i] * rs * w[2 * i];
        float x1 = r[2 * i + 1] * rs * w[2 * i + 1];
        if (outf) { outf[(size_t)t * n + 2 * i] = x0; outf[(size_t)t * n + 2 * i + 1] = x1; }
        uint32_t h, l;
        split_pack(x0, x1, h, l);
        pH[(size_t)t * nw + i] = h;
        pL[(size_t)t * nw + i] = l;
    }
}

// =======================================================================
// bf16x3 split-precision tensor-core GEMM, pre-packed operands, cp.async
// staging, ONE __syncthreads per K-tile:
//   loop: WAIT(kt) -> sync -> ISSUE(kt+1) -> COMPUTE(kt)
// ISSUE(kt+1) writes buf (kt-1)&1; the sync guarantees all warps finished
// COMPUTE(kt-1) which read that buffer. The async load of kt+1 overlaps
// COMPUTE(kt).
// =======================================================================
template <bool ADD, int MT, bool SW, int MINB>
__global__ __launch_bounds__(256, MINB) void tbgemm_k(
    const uint32_t* __restrict__ AHg, const uint32_t* __restrict__ ALg,
    const uint32_t* __restrict__ B0H, const uint32_t* __restrict__ B0L,
    const uint32_t* __restrict__ B1H, const uint32_t* __restrict__ B1L,
    const uint32_t* __restrict__ B2H, const uint32_t* __restrict__ B2L,
    float* __restrict__ C0, float* __restrict__ C1, float* __restrict__ C2,
    int M, int N, int Kd) {
    extern __shared__ uint32_t smw[];
    const int AW = MT * 512;            // A words per hi or lo section
    const int BUF = AW * 2 + 4096;      // words per stage
    const int Kw = Kd >> 1;
    const uint32_t sbase = smem_u32(smw);

    const uint32_t* BHg = (blockIdx.z == 0) ? B0H : (blockIdx.z == 1 ? B1H : B2H);
    const uint32_t* BLg = (blockIdx.z == 0) ? B0L : (blockIdx.z == 1 ? B1L : B2L);
    float*          C   = (blockIdx.z == 0) ? C0  : (blockIdx.z == 1 ? C1  : C2);

    const int bm = (SW ? blockIdx.x : blockIdx.y) * (MT * 32);
    const int bn = (SW ? blockIdx.y : blockIdx.x) * 128;
    const int tid = threadIdx.x;
    const int warp = tid >> 5, lane = tid & 31;
    const int warpM = warp >> 2;
    const int warpN = warp & 3;
    const int g = lane >> 2, t4 = lane & 3;

    float acc[MT][4][4];
#pragma unroll
    for (int i = 0; i < MT; i++)
#pragma unroll
        for (int j = 0; j < 4; j++)
#pragma unroll
            for (int r = 0; r < 4; r++) acc[i][j][r] = 0.f;

    auto ISSUE = [&](int kt, int buf) {
        uint32_t b0 = sbase + (uint32_t)buf * BUF * 4;
#pragma unroll
        for (int i = 0; i < MT; i++) {
            int id = i * 256 + tid;
            int r = id >> 3, c4 = id & 7;
            size_t off = (size_t)(bm + r) * Kw + kt * 16 + c4 * 2;
            uint32_t so = (uint32_t)(r * 16 + ((c4 * 2) ^ ((r & 7) * 2))) * 4;
            cp_async8(b0 + so, AHg + off);
            cp_async8(b0 + AW * 4 + so, ALg + off);
        }
#pragma unroll
        for (int i = 0; i < 2; i++) {
            int id = i * 256 + tid;
            int kw = id >> 5, n4 = id & 31;
            size_t off = (size_t)(kt * 16 + kw) * N + bn + n4 * 4;
            uint32_t so = (uint32_t)(kw * 128 + ((n4 * 4) ^ ((kw * 8) & 127))) * 4;
            cp_async16(b0 + 2 * AW * 4 + so, BHg + off);
            cp_async16(b0 + 2 * AW * 4 + 8192 + so, BLg + off);
        }
        CP_COMMIT();
    };

    auto COMPUTE = [&](int buf) {
        uint32_t* AH = smw + buf * BUF;
        uint32_t* AL = AH + AW;
        uint32_t* BH = AH + 2 * AW;
        uint32_t* BL = BH + 2048;
#pragma unroll
        for (int ks = 0; ks < 2; ks++) {
            uint32_t bh[4][2], bl[4][2];
#pragma unroll
            for (int nt = 0; nt < 4; nt++) {
                int n = warpN * 32 + nt * 8 + g;
                int k0w = ks * 8 + t4, k1w = k0w + 4;
                int o0 = k0w * 128 + (n ^ ((k0w * 8) & 127));
                int o1 = k1w * 128 + (n ^ ((k1w * 8) & 127));
                bh[nt][0] = BH[o0]; bh[nt][1] = BH[o1];
                bl[nt][0] = BL[o0]; bl[nt][1] = BL[o1];
            }
#pragma unroll
            for (int mt = 0; mt < MT; mt++) {
                uint32_t ah[4], al[4];
                int r0 = warpM * (MT * 16) + mt * 16 + g;
                int r1 = r0 + 8;
                int ka = ks * 8 + t4, kb = ka + 4;
                int o0 = r0 * 16 + (ka ^ ((r0 & 7) * 2));
                int o1 = r1 * 16 + (ka ^ ((r1 & 7) * 2));
                int o2 = r0 * 16 + (kb ^ ((r0 & 7) * 2));
                int o3 = r1 * 16 + (kb ^ ((r1 & 7) * 2));
                ah[0] = AH[o0]; ah[1] = AH[o1]; ah[2] = AH[o2]; ah[3] = AH[o3];
                al[0] = AL[o0]; al[1] = AL[o1]; al[2] = AL[o2]; al[3] = AL[o3];
#pragma unroll
                for (int nt = 0; nt < 4; nt++) {
                    mma_bf16(acc[mt][nt], al, bh[nt]);
                    mma_bf16(acc[mt][nt], ah, bl[nt]);
                    mma_bf16(acc[mt][nt], ah, bh[nt]);
                }
            }
        }
    };

    const int ntiles = Kd / 32;
    ISSUE(0, 0);
    for (int kt = 0; kt < ntiles; kt++) {
        CP_WAIT0();
        __syncthreads();
        if (kt + 1 < ntiles) ISSUE(kt + 1, (kt + 1) & 1);
        COMPUTE(kt & 1);
    }

#pragma unroll
    for (int mt = 0; mt < MT; mt++) {
        int r0 = bm + warpM * (MT * 16) + mt * 16 + g;
#pragma unroll
        for (int nt = 0; nt < 4; nt++) {
            int c0 = bn + warpN * 32 + nt * 8 + 2 * t4;
            float* p0 = C + (size_t)r0 * N + c0;
            float* p1 = C + (size_t)(r0 + 8) * N + c0;
            if (ADD) {
                p0[0] += acc[mt][nt][0]; p0[1] += acc[mt][nt][1];
                p1[0] += acc[mt][nt][2]; p1[1] += acc[mt][nt][3];
            } else {
                p0[0] = acc[mt][nt][0]; p0[1] = acc[mt][nt][1];
                p1[0] = acc[mt][nt][2]; p1[1] = acc[mt][nt][3];
            }
        }
    }
}

// =======================================================================
// Strip-mined post-QKV: one block per 8 timesteps, 768 threads.
// Rolling conv window in registers (reads each t0/t1/t2 element once),
// x strip in smem read once for the 96 beta dots (24 warps x 4 dots).
// =======================================================================
#define TS 8
__global__ __launch_bounds__(768) void postqkv_k(
    const float* __restrict__ t0, const float* __restrict__ t1, const float* __restrict__ t2,
    const float* __restrict__ cq, const float* __restrict__ ck, const float* __restrict__ cv,
    const float* __restrict__ x, const float* __restrict__ Wb,
    float* __restrict__ q, float* __restrict__ k, float* __restrict__ v,
    float* __restrict__ beta) {
    int ts = blockIdx.x * TS;
    int d = threadIdx.x;            // 0..767 channel
    int h = d >> 6;
    int warp = d >> 5, lane = d & 31;
    __shared__ float sx[TS * DD];   // 24 KB
    __shared__ float redq[TS][26], redk[TS][26];
    __shared__ float redb[96];

#pragma unroll
    for (int i = 0; i < TS; i++) sx[i * DD + d] = x[(size_t)(ts + i) * DD + d];
    __syncthreads();

    // beta dots: warp w computes 4 of the 96 (t,h) dots
    {
#pragma unroll
        for (int r = 0; r < 4; r++) {
            int idx = warp * 4 + r;
            int tt = idx / HH, hh = idx - tt * HH;
            float sb = 0.f;
            for (int i = lane; i < DD; i += 32) sb += sx[tt * DD + i] * Wb[i * HH + hh];
#pragma unroll
            for (int o = 16; o > 0; o >>= 1) sb += __shfl_xor_sync(0xffffffffu, sb, o);
            if (lane == 0) redb[idx] = sb;
        }
    }

    // conv weights + rolling windows
    float cqw[KC], ckw[KC], cvw[KC];
#pragma unroll
    for (int j = 0; j < KC; j++) {
        cqw[j] = cq[d * KC + j];
        ckw[j] = ck[d * KC + j];
        cvw[j] = cv[d * KC + j];
    }
    float wq[KC], wk[KC], wv[KC];
#pragma unroll
    for (int j = 0; j < 3; j++) {
        int tt = ts - 3 + j;
        bool ok = (tt >= 0);
        size_t gg = ok ? (size_t)tt * DD + d : 0;
        wq[j] = ok ? t0[gg] : 0.f;
        wk[j] = ok ? t1[gg] : 0.f;
        wv[j] = ok ? t2[gg] : 0.f;
    }

    float qv[TS], kv[TS], vv[TS];
#pragma unroll
    for (int i = 0; i < TS; i++) {
        size_t gg = (size_t)(ts + i) * DD + d;
        wq[3] = t0[gg]; wk[3] = t1[gg]; wv[3] = t2[gg];
        float aq = wq[0] * cqw[0] + wq[1] * cqw[1] + wq[2] * cqw[2] + wq[3] * cqw[3];
        float ak = wk[0] * ckw[0] + wk[1] * ckw[1] + wk[2] * ckw[2] + wk[3] * ckw[3];
        float av = wv[0] * cvw[0] + wv[1] * cvw[1] + wv[2] * cvw[2] + wv[3] * cvw[3];
        qv[i] = aq / (1.f + __expf(-aq));
        kv[i] = ak / (1.f + __expf(-ak));
        vv[i] = av / (1.f + __expf(-av));
#pragma unroll
        for (int j = 0; j < 3; j++) { wq[j] = wq[j + 1]; wk[j] = wk[j + 1]; wv[j] = wv[j + 1]; }

        float sq = qv[i] * qv[i], sk = kv[i] * kv[i];
#pragma unroll
        for (int o = 16; o > 0; o >>= 1) {
            sq += __shfl_xor_sync(0xffffffffu, sq, o);
            sk += __shfl_xor_sync(0xffffffffu, sk, o);
        }
        if (lane == 0) { redq[i][warp] = sq; redk[i][warp] = sk; }
    }
    __syncthreads();

#pragma unroll
    for (int i = 0; i < TS; i++) {
        float rq = rsqrtf(redq[i][2 * h] + redq[i][2 * h + 1] + EPSF);
        float rk = rsqrtf(redk[i][2 * h] + redk[i][2 * h + 1] + EPSF);
        size_t gi = (size_t)(ts + i) * DD + d;
        q[gi] = qv[i] * rq;
        k[gi] = kv[i] * rk;
        v[gi] = vv[i];
    }
    if (d < 96) {
        int tt = d / HH, hh = d - tt * HH;
        beta[(ts + tt) * HH + hh] = 1.f / (1.f + __expf(-redb[d]));
    }
}

// =======================================================================
// Chunked delta rule, phase 1 (parallel; WY form).
// =======================================================================
__global__ __launch_bounds__(256) void deltaprep_k(
    const float* __restrict__ q, const float* __restrict__ k,
    const float* __restrict__ v, const float* __restrict__ beta,
    float* __restrict__ Qe, float* __restrict__ Of,
    float* __restrict__ Pm, float* __restrict__ Rm) {
    extern __shared__ float sm[];
    float* sK = sm;
    float* sV = sK + 64 * PSTR;
    float* sQ = sV + 64 * PSTR;
    float* bA = sQ + 64 * PSTR;
    float* bT = bA + 64 * PSTR;
    float* bU = bT + 64 * PSTR;
    float* sb = bU + 64 * PSTR;
    const int c = blockIdx.x, h = blockIdx.y;
    const int tid = threadIdx.x;
    const int tr = (tid >> 4) * 4, tc = (tid & 15) * 4;

    for (int i = tid; i < 4096; i += 256) {
        int t = i >> 6, d = i & 63;
        size_t g = (size_t)(c * 64 + t) * DD + h * 64 + d;
        sK[t * PSTR + d] = k[g];
        sV[t * PSTR + d] = v[g];
        sQ[t * PSTR + d] = q[g];
    }
    if (tid < 64) sb[tid] = beta[(c * 64 + tid) * HH + h];
    __syncthreads();

    {
        float acc[4][4] = {};
        for (int m = 0; m < 64; m++) {
            float a[4], b[4];
#pragma unroll
            for (int i = 0; i < 4; i++) a[i] = sK[(tr + i) * PSTR + m];
#pragma unroll
            for (int j = 0; j < 4; j++) b[j] = sK[(tc + j) * PSTR + m];
#pragma unroll
            for (int i = 0; i < 4; i++)
#pragma unroll
                for (int j = 0; j < 4; j++) acc[i][j] += a[i] * b[j];
        }
#pragma unroll
        for (int i = 0; i < 4; i++)
#pragma unroll
            for (int j = 0; j < 4; j++) {
                int t = tr + i, s = tc + j;
                bA[t * PSTR + s] = (s < t) ? acc[i][j] * sb[t] : 0.f;
            }
    }
    __syncthreads();

    for (int t = 0; t < 64; t++) {
        if (tid < 64) {
            float acc = (t == tid) ? 1.f : 0.f;
            for (int s = 0; s < t; s++) acc -= bA[t * PSTR + s] * bT[s * PSTR + tid];
            bT[t * PSTR + tid] = acc;
        }
        __syncthreads();
    }

    {
        float accW[4][4] = {}, accU[4][4] = {};
        for (int m = 0; m < 64; m++) {
            float a[4];
#pragma unroll
            for (int i = 0; i < 4; i++) a[i] = bT[(tr + i) * PSTR + m] * sb[m];
            float bk[4], bv[4];
#pragma unroll
            for (int j = 0; j < 4; j++) {
                bk[j] = sK[m * PSTR + tc + j];
                bv[j] = sV[m * PSTR + tc + j];
            }
#pragma unroll
            for (int i = 0; i < 4; i++)
#pragma unroll
                for (int j = 0; j < 4; j++) {
                    accW[i][j] += a[i] * bk[j];
                    accU[i][j] += a[i] * bv[j];
                }
        }
        __syncthreads();
#pragma unroll
        for (int i = 0; i < 4; i++)
#pragma unroll
            for (int j = 0; j < 4; j++) {
                bA[(tr + i) * PSTR + tc + j] = accW[i][j];
                bU[(tr + i) * PSTR + tc + j] = accU[i][j];
            }
    }
    __syncthreads();

    {
        float acc[4][4] = {};
        for (int m = 0; m < 64; m++) {
            float a[4], b[4];
#pragma unroll
            for (int i = 0; i < 4; i++) a[i] = sQ[(tr + i) * PSTR + m];
#pragma unroll
            for (int j = 0; j < 4; j++) b[j] = sK[(tc + j) * PSTR + m];
#pragma unroll
            for (int i = 0; i < 4; i++)
#pragma unroll
                for (int j = 0; j < 4; j++) acc[i][j] += a[i] * b[j];
        }
        __syncthreads();
#pragma unroll
        for (int i = 0; i < 4; i++)
#pragma unroll
            for (int j = 0; j < 4; j++) {
                int t = tr + i, s = tc + j;
                bT[t * PSTR + s] = (s <= t) ? acc[i][j] : 0.f;
            }
    }
    __syncthreads();

    const size_t base = ((size_t)(h * NCH + c)) << 12;

    {
        float accQ[4][4] = {}, accO[4][4] = {};
        for (int m = 0; m < 64; m++) {
            float a[4];
#pragma unroll
            for (int i = 0; i < 4; i++) a[i] = bT[(tr + i) * PSTR + m];
            float bw[4], bu[4];
#pragma unroll
            for (int j = 0; j < 4; j++) {
                bw[j] = bA[m * PSTR + tc + j];
                bu[j] = bU[m * PSTR + tc + j];
            }
#pragma unroll
            for (int i = 0; i < 4; i++)
#pragma unroll
                for (int j = 0; j < 4; j++) {
                    accQ[i][j] += a[i] * bw[j];
                    accO[i][j] += a[i] * bu[j];
                }
        }
#pragma unroll
        for (int i = 0; i < 4; i++)
#pragma unroll
            for (int j = 0; j < 4; j++) {
                Qe[base + (tr + i) * 64 + tc + j] =
                    sQ[(tr + i) * PSTR + tc + j] - accQ[i][j];
                Of[base + (tr + i) * 64 + tc + j] = accO[i][j];
            }
    }

    {
        float accP[4][4] = {}, accR[4][4] = {};
        for (int m = 0; m < 64; m++) {
            float a[4];
#pragma unroll
            for (int i = 0; i < 4; i++) a[i] = sK[m * PSTR + tr + i];
            float bw[4], bu[4];
#pragma unroll
            for (int j = 0; j < 4; j++) {
                bw[j] = bA[m * PSTR + tc + j];
                bu[j] = bU[m * PSTR + tc + j];
            }
#pragma unroll
            for (int i = 0; i < 4; i++)
#pragma unroll
                for (int j = 0; j < 4; j++) {
                    accP[i][j] += a[i] * bw[j];
                    accR[i][j] += a[i] * bu[j];
                }
        }
#pragma unroll
        for (int i = 0; i < 4; i++)
#pragma unroll
            for (int j = 0; j < 4; j++) {
                Pm[base + (tr + i) * 64 + tc + j] = accP[i][j];
                Rm[base + (tr + i) * 64 + tc + j] = accR[i][j];
            }
    }
}

// Chunked delta rule, phase 2 (scan)
__global__ __launch_bounds__(256) void deltascan_k(
    const float* __restrict__ Qe, const float* __restrict__ Of,
    const float* __restrict__ Pm, const float* __restrict__ Rm,
    float* __restrict__ o) {
    const int h = blockIdx.x, cg = blockIdx.y;
    const int tid = threadIdx.x;
    __shared__ float sQe[64 * PSTR], sP[64 * PSTR];
    __shared__ float S[64 * 9], sOf[512], sR[512];

    for (int i = tid; i < 64 * 9; i += 256) S[i] = 0.f;
    __syncthreads();

#pragma unroll 1
    for (int c = 0; c < NCH; c++) {
        size_t base = ((size_t)(h * NCH + c)) << 12;
        for (int i = tid; i < 4096; i += 256) {
            int t = i >> 6, d = i & 63;
            sQe[t * PSTR + d] = Qe[base + i];
            sP[t * PSTR + d] = Pm[base + i];
        }
        for (int i = tid; i < 512; i += 256) {
            int t = i >> 3, j = i & 7;
            sOf[i] = Of[base + t * 64 + cg * 8 + j];
            sR[i] = Rm[base + t * 64 + cg * 8 + j];
        }
        __syncthreads();

        float outv[2], ns[2];
#pragma unroll
        for (int u = 0; u < 2; u++) {
            int idx = tid + u * 256;
            int t = idx >> 3, j = idx & 7;
            float a1 = sOf[idx];
            float a2 = S[t * 9 + j] + sR[idx];
#pragma unroll
            for (int m = 0; m < 64; m++) {
                float sv = S[m * 9 + j];
                a1 += sQe[t * PSTR + m] * sv;
                a2 -= sP[t * PSTR + m] * sv;
            }
            outv[u] = a1;
            ns[u] = a2;
        }
#pragma unroll
        for (int u = 0; u < 2; u++) {
            int idx = tid + u * 256;
            int t = idx >> 3, j = idx & 7;
            o[(size_t)(c * 64 + t) * DD + h * 64 + cg * 8 + j] = outv[u];
        }
        __syncthreads();
#pragma unroll
        for (int u = 0; u < 2; u++) {
            int idx = tid + u * 256;
            int t = idx >> 3, j = idx & 7;
            S[t * 9 + j] = ns[u];
        }
        __syncthreads();
    }
}

// per-64 rmsnorm * w of delta output -> packed words (feeds Wo GEMM)
__global__ void headnorm_pack_k(const float* __restrict__ o, const float* __restrict__ w,
                                uint32_t* __restrict__ pH, uint32_t* __restrict__ pL) {
    int gw = (blockIdx.x * blockDim.x + threadIdx.x) >> 5;
    int lane = threadIdx.x & 31;
    if (gw >= TT * HH) return;
    const float* r = o + (size_t)gw * 64;
    float a = r[2 * lane], b = r[2 * lane + 1];
    float s = a * a + b * b;
#pragma unroll
    for (int os = 16; os > 0; os >>= 1) s += __shfl_xor_sync(0xffffffffu, s, os);
    float rs = rsqrtf(s * (1.f / 64.f) + EPSF);
    int t = gw / HH, h = gw % HH;
    uint32_t hw, lw;
    split_pack(a * rs * w[2 * lane], b * rs * w[2 * lane + 1], hw, lw);
    size_t wi = (size_t)t * 384 + h * 32 + lane;
    pH[wi] = hw;
    pL[wi] = lw;
}

// silu(g)*u, writes packed words; i indexes element pairs
__global__ void silu_mul_pack_k(const float* __restrict__ g, const float* __restrict__ u,
                                uint32_t* __restrict__ pH, uint32_t* __restrict__ pL) {
    int i = blockIdx.x * blockDim.x + threadIdx.x;
    if (i >= TT * FFF / 2) return;
    float g0 = g[2 * i], g1 = g[2 * i + 1];
    float y0 = (g0 / (1.f + __expf(-g0))) * u[2 * i];
    float y1 = (g1 / (1.f + __expf(-g1))) * u[2 * i + 1];
    uint32_t h, l;
    split_pack(y0, y1, h, l);
    pH[i] = h;
    pL[i] = l;
}

// online-softmax cross-entropy row pass (single read of logits)
__global__ void loss_rows_k(const float* __restrict__ logits, const int* __restrict__ tgt,
                            float* __restrict__ nll, float* __restrict__ msk) {
    int t = blockIdx.x;
    const float* r = logits + (size_t)t * VV;
    int tid = threadIdx.x;
    __shared__ float sm_m[256], sm_s[256];
    float m = -INFINITY, s = 0.f;
    for (int i = tid; i < VV; i += 256) {
        float v = r[i];
        if (v > m) { s = s * __expf(m - v) + 1.f; m = v; }
        else s += __expf(v - m);
    }
    sm_m[tid] = m; sm_s[tid] = s;
    __syncthreads();
    for (int o = 128; o > 0; o >>= 1) {
        if (tid < o) {
            float m1 = sm_m[tid], m2 = sm_m[tid + o];
            float M = fmaxf(m1, m2);
            sm_s[tid] = sm_s[tid] * __expf(m1 - M) + sm_s[tid + o] * __expf(m2 - M);
            sm_m[tid] = M;
        }
        __syncthreads();
    }
    if (tid == 0) {
        float rowmax = sm_m[0], denom = sm_s[0];
        int tg = tgt[t];
        float mask = (tg >= 0) ? 1.f : 0.f;
        int tc = tg < 0 ? 0 : (tg > VV - 1 ? VV - 1 : tg);
        float lp = r[tc] - rowmax - logf(denom);
        nll[t] = -lp * mask;
        msk[t] = mask;
    }
}

__global__ void loss_reduce_k(const float* __restrict__ nll, const float* __restrict__ msk,
                              float* __restrict__ out) {
    int tid = threadIdx.x;
    __shared__ float r1[256], r2[256];
    float s = 0.f, c = 0.f;
    for (int i = tid; i < TT; i += 256) { s += nll[i]; c += msk[i]; }
    r1[tid] = s; r2[tid] = c; __syncthreads();
    for (int o = 128; o > 0; o >>= 1) {
        if (tid < o) { r1[tid] += r1[tid + o]; r2[tid] += r2[tid + o]; }
        __syncthreads();
    }
    if (tid == 0) out[0] = r1[0] / fmaxf(r2[0], 1.f);
}

// ---------------- host launcher ----------------
extern "C" void kernel_launch(void* const* d_in, const int* in_sizes, int n_in,
                              void* d_out, int out_size) {
    const int*   idx   = (const int*)d_in[0];
    const int*   tgt   = (const int*)d_in[1];
    const float* emb   = (const float*)d_in[2];
    const float* Wq    = (const float*)d_in[3];
    const float* Wk    = (const float*)d_in[4];
    const float* Wv    = (const float*)d_in[5];
    const float* convq = (const float*)d_in[6];
    const float* convk = (const float*)d_in[7];
    const float* convv = (const float*)d_in[8];
    const float* Wb    = (const float*)d_in[9];
    const float* onw   = (const float*)d_in[10];
    const float* Wo    = (const float*)d_in[11];
    const float* anw   = (const float*)d_in[12];
    const float* mnw   = (const float*)d_in[13];
    const float* Wg    = (const float*)d_in[14];
    const float* Wu    = (const float*)d_in[15];
    const float* Wd    = (const float*)d_in[16];
    const float* fnw   = (const float*)d_in[17];
    const float* lmh   = (const float*)d_in[18];
    float* out = (float*)d_out;

    float *hb, *xb, *t0, *t1, *t2, *qb, *kb, *vb, *ob, *bb, *gb, *ub, *nl, *mk, *lfb;
    cudaGetSymbolAddress((void**)&hb,  g_h);
    cudaGetSymbolAddress((void**)&xb,  g_x);
    cudaGetSymbolAddress((void**)&t0,  g_t0);
    cudaGetSymbolAddress((void**)&t1,  g_t1);
    cudaGetSymbolAddress((void**)&t2,  g_t2);
    cudaGetSymbolAddress((void**)&qb,  g_q);
    cudaGetSymbolAddress((void**)&kb,  g_k);
    cudaGetSymbolAddress((void**)&vb,  g_v);
    cudaGetSymbolAddress((void**)&ob,  g_o);
    cudaGetSymbolAddress((void**)&bb,  g_beta);
    cudaGetSymbolAddress((void**)&gb,  g_gate);
    cudaGetSymbolAddress((void**)&ub,  g_up);
    cudaGetSymbolAddress((void**)&nl,  g_nll);
    cudaGetSymbolAddress((void**)&mk,  g_msk);
    cudaGetSymbolAddress((void**)&lfb, g_logits_fb);

    float *dQe, *dOf, *dPm, *dRm;
    cudaGetSymbolAddress((void**)&dQe, g_Qe);
    cudaGetSymbolAddress((void**)&dOf, g_Of);
    cudaGetSymbolAddress((void**)&dPm, g_Pm);
    cudaGetSymbolAddress((void**)&dRm, g_Rm);

    uint32_t *pAh, *pAl;
    uint32_t *wqh, *wql, *wkh, *wkl, *wvh, *wvl, *woh, *wol;
    uint32_t *wgh, *wgl, *wuh, *wul, *wdh, *wdl, *lmH, *lmL;
    cudaGetSymbolAddress((void**)&pAh, g_pA_h);
    cudaGetSymbolAddress((void**)&pAl, g_pA_l);
    cudaGetSymbolAddress((void**)&wqh, g_Wq_h); cudaGetSymbolAddress((void**)&wql, g_Wq_l);
    cudaGetSymbolAddress((void**)&wkh, g_Wk_h); cudaGetSymbolAddress((void**)&wkl, g_Wk_l);
    cudaGetSymbolAddress((void**)&wvh, g_Wv_h); cudaGetSymbolAddress((void**)&wvl, g_Wv_l);
    cudaGetSymbolAddress((void**)&woh, g_Wo_h); cudaGetSymbolAddress((void**)&wol, g_Wo_l);
    cudaGetSymbolAddress((void**)&wgh, g_Wg_h); cudaGetSymbolAddress((void**)&wgl, g_Wg_l);
    cudaGetSymbolAddress((void**)&wuh, g_Wu_h); cudaGetSymbolAddress((void**)&wul, g_Wu_l);
    cudaGetSymbolAddress((void**)&wdh, g_Wd_h); cudaGetSymbolAddress((void**)&wdl, g_Wd_l);
    cudaGetSymbolAddress((void**)&lmH, g_Lm_h); cudaGetSymbolAddress((void**)&lmL, g_Lm_l);

    const int SMEM4 = (4 * 1024 + 4096) * 2 * 4;  // 65536 (MT=4)
    const int SMEM2 = (2 * 1024 + 4096) * 2 * 4;  // 49152 (MT=2)
    const int PREPSM = (6 * 64 * PSTR + 64) * 4 + 256;
    cudaFuncSetAttribute((const void*)tbgemm_k<false, 4, false, 2>, cudaFuncAttributeMaxDynamicSharedMemorySize, SMEM4);
    cudaFuncSetAttribute((const void*)tbgemm_k<false, 4, true, 2>,  cudaFuncAttributeMaxDynamicSharedMemorySize, SMEM4);
    cudaFuncSetAttribute((const void*)tbgemm_k<true, 2, false, 2>,  cudaFuncAttributeMaxDynamicSharedMemorySize, SMEM2);
    cudaFuncSetAttribute((const void*)deltaprep_k, cudaFuncAttributeMaxDynamicSharedMemorySize, PREPSM);

    // ---- pack all weights ----
    pack_w_k<<<dim3(3, 384, LL), 256>>>(Wq, wqh, wql, 384, DD);
    pack_w_k<<<dim3(3, 384, LL), 256>>>(Wk, wkh, wkl, 384, DD);
    pack_w_k<<<dim3(3, 384, LL), 256>>>(Wv, wvh, wvl, 384, DD);
    pack_w_k<<<dim3(3, 384, LL), 256>>>(Wo, woh, wol, 384, DD);
    pack_w_k<<<dim3(8, 384, LL), 256>>>(Wg, wgh, wgl, 384, FFF);
    pack_w_k<<<dim3(8, 384, LL), 256>>>(Wu, wuh, wul, 384, FFF);
    pack_w_k<<<dim3(3, 1024, LL), 256>>>(Wd, wdh, wdl, 1024, DD);
    pack_w_k<<<dim3((VV + 255) / 256, 384, 1), 256>>>(lmh, lmH, lmL, 384, VV);

    const int ewarpBlocks = (TT * HH * 32 + 255) / 256;
    const int ffwBlocks = (TT * FFF / 2 + 255) / 256;

    embed_k<<<TT, 256>>>(idx, emb, hb);

    for (int l = 0; l < LL; l++) {
        const float* cq_l = convq + (size_t)l * DD * KC;
        const float* ck_l = convk + (size_t)l * DD * KC;
        const float* cv_l = convv + (size_t)l * DD * KC;
        const float* Wb_l = Wb + (size_t)l * DD * HH;
        const float* on_l = onw + (size_t)l * DKK;
        const float* an_l = anw + (size_t)l * DD;
        const float* mn_l = mnw + (size_t)l * DD;

        rmsnorm_pack_k<<<TT, 256>>>(hb, an_l, xb, pAh, pAl, DD);

        // QKV: MT=4 @ (256,2) cp.async, one-sync pipeline
        dim3 gQKV(DD / 128, TT / 128, 3);
        tbgemm_k<false, 4, false, 2><<<gQKV, 256, SMEM4>>>(
            pAh, pAl,
            wqh + (size_t)l * WSM, wql + (size_t)l * WSM,
            wkh + (size_t)l * WSM, wkl + (size_t)l * WSM,
            wvh + (size_t)l * WSM, wvl + (size_t)l * WSM,
            t0, t1, t2, TT, DD, DD);

        postqkv_k<<<TT / TS, 768>>>(t0, t1, t2, cq_l, ck_l, cv_l, xb, Wb_l, qb, kb, vb, bb);

        deltaprep_k<<<dim3(NCH, HH), 256, PREPSM>>>(qb, kb, vb, bb, dQe, dOf, dPm, dRm);
        deltascan_k<<<dim3(HH, 8), 256>>>(dQe, dOf, dPm, dRm, ob);

        headnorm_pack_k<<<ewarpBlocks, 256>>>(ob, on_l, pAh, pAl);

        // Wo: MT=2 @ (256,2), 192 blocks
        dim3 gD(DD / 128, TT / 64, 1);
        tbgemm_k<true, 2, false, 2><<<gD, 256, SMEM2>>>(
            pAh, pAl,
            woh + (size_t)l * WSM, wol + (size_t)l * WSM,
            woh + (size_t)l * WSM, wol + (size_t)l * WSM,
            woh + (size_t)l * WSM, wol + (size_t)l * WSM,
            hb, hb, hb, TT, DD, DD);

        rmsnorm_pack_k<<<TT, 256>>>(hb, mn_l, nullptr, pAh, pAl, DD);

        // gate+up: MT=4 @ (256,2), 512 blocks
        dim3 gGU(FFF / 128, TT / 128, 2);
        tbgemm_k<false, 4, false, 2><<<gGU, 256, SMEM4>>>(
            pAh, pAl,
            wgh + (size_t)l * WGU, wgl + (size_t)l * WGU,
            wuh + (size_t)l * WGU, wul + (size_t)l * WGU,
            wuh + (size_t)l * WGU, wul + (size_t)l * WGU,
            gb, ub, ub, TT, FFF, DD);

        silu_mul_pack_k<<<ffwBlocks, 256>>>(gb, ub, pAh, pAl);

        // down: MT=2 @ (256,2)
        tbgemm_k<true, 2, false, 2><<<gD, 256, SMEM2>>>(
            pAh, pAl,
            wdh + (size_t)l * WDN, wdl + (size_t)l * WDN,
            wdh + (size_t)l * WDN, wdl + (size_t)l * WDN,
            wdh + (size_t)l * WDN, wdl + (size_t)l * WDN,
            hb, hb, hb, TT, DD, FFF);
    }

    rmsnorm_pack_k<<<TT, 256>>>(hb, fnw, nullptr, pAh, pAl, DD);

    const size_t LOGN = (size_t)TT * VV;
    float* logits = ((size_t)out_size >= LOGN) ? out : lfb;
    // LM head: MT=4 @ (256,2), m-fastest grid (B panel read once)
    dim3 gV(TT / 128, VV / 128, 1);
    tbgemm_k<false, 4, true, 2><<<gV, 256, SMEM4>>>(pAh, pAl, lmH, lmL, lmH, lmL, lmH, lmL,
                                                    logits, logits, logits, TT, VV, DD);

    loss_rows_k<<<TT, 256>>>(logits, tgt, nl, mk);
    float* loss_dst = nullptr;
    if ((size_t)out_size >= LOGN + 1) loss_dst = out + LOGN;
    else if ((size_t)out_size < LOGN) loss_dst = out;
    if (loss_dst) loss_reduce_k<<<1, 256>>>(nl, mk, loss_dst);
}

// round 13
// speedup vs baseline: 1.7351x; 1.0182x over previous
#include <cuda_runtime.h>
#include <cuda_bf16.h>
#include <math.h>
#include <stdint.h>

// Problem constants
#define TT   2048
#define DD   768
#define HH   12
#define DKK  64
#define FFF  2048
#define VV   50304
#define LL   12
#define KC   4
#define EPSF 1e-6f
#define NCH  32
#define PSTR 65

#define WSM 294912
#define WGU 786432
#define WDN 786432
#define WLM 19316736

// ---------------- scratch ----------------
__device__ float g_h[TT * DD];
__device__ float g_x[TT * DD];
__device__ float g_t0[TT * DD];
__device__ float g_t1[TT * DD];
__device__ float g_t2[TT * DD];
__device__ float g_q[TT * DD];
__device__ float g_k[TT * DD];
__device__ float g_v[TT * DD];
__device__ float g_o[TT * DD];
__device__ float g_beta[TT * HH];
__device__ float g_gate[TT * FFF];
__device__ float g_up[TT * FFF];
__device__ float g_nll[TT];
__device__ float g_msk[TT];
__device__ float g_logits_fb[(size_t)TT * VV];

__device__ float g_Qe[HH * NCH * 4096];
__device__ float g_Of[HH * NCH * 4096];
__device__ float g_Pm[HH * NCH * 4096];
__device__ float g_Rm[HH * NCH * 4096];

__device__ __align__(256) uint32_t g_pA_h[TT * 1024];
__device__ __align__(256) uint32_t g_pA_l[TT * 1024];

__device__ __align__(256) uint32_t g_Wq_h[LL * WSM]; __device__ __align__(256) uint32_t g_Wq_l[LL * WSM];
__device__ __align__(256) uint32_t g_Wk_h[LL * WSM]; __device__ __align__(256) uint32_t g_Wk_l[LL * WSM];
__device__ __align__(256) uint32_t g_Wv_h[LL * WSM]; __device__ __align__(256) uint32_t g_Wv_l[LL * WSM];
__device__ __align__(256) uint32_t g_Wo_h[LL * WSM]; __device__ __align__(256) uint32_t g_Wo_l[LL * WSM];
__device__ __align__(256) uint32_t g_Wg_h[LL * WGU]; __device__ __align__(256) uint32_t g_Wg_l[LL * WGU];
__device__ __align__(256) uint32_t g_Wu_h[LL * WGU]; __device__ __align__(256) uint32_t g_Wu_l[LL * WGU];
__device__ __align__(256) uint32_t g_Wd_h[LL * WDN]; __device__ __align__(256) uint32_t g_Wd_l[LL * WDN];
__device__ __align__(256) uint32_t g_Lm_h[WLM];      __device__ __align__(256) uint32_t g_Lm_l[WLM];

// ---------------- helpers ----------------
__device__ __forceinline__ void mma_bf16(float* c, const uint32_t* a, const uint32_t* b) {
    asm volatile(
        "mma.sync.aligned.m16n8k16.row.col.f32.bf16.bf16.f32 "
        "{%0,%1,%2,%3}, {%4,%5,%6,%7}, {%8,%9}, {%0,%1,%2,%3};\n"
        : "+f"(c[0]), "+f"(c[1]), "+f"(c[2]), "+f"(c[3])
        : "r"(a[0]), "r"(a[1]), "r"(a[2]), "r"(a[3]), "r"(b[0]), "r"(b[1]));
}

__device__ __forceinline__ void split_pack(float x0, float x1, uint32_t& hp, uint32_t& lp) {
    __nv_bfloat16 h0 = __float2bfloat16(x0), h1 = __float2bfloat16(x1);
    float f0 = __bfloat162float(h0), f1 = __bfloat162float(h1);
    __nv_bfloat16 l0 = __float2bfloat16(x0 - f0), l1 = __float2bfloat16(x1 - f1);
    hp = (uint32_t)__bfloat16_as_ushort(h0) | ((uint32_t)__bfloat16_as_ushort(h1) << 16);
    lp = (uint32_t)__bfloat16_as_ushort(l0) | ((uint32_t)__bfloat16_as_ushort(l1) << 16);
}

__device__ __forceinline__ uint32_t smem_u32(const void* p) {
    uint32_t a;
    asm("{ .reg .u64 t; cvta.to.shared.u64 t, %1; cvt.u32.u64 %0, t; }" : "=r"(a) : "l"(p));
    return a;
}
__device__ __forceinline__ void cp_async8(uint32_t saddr, const void* gptr) {
    asm volatile("cp.async.ca.shared.global [%0], [%1], 8;" :: "r"(saddr), "l"(gptr));
}
__device__ __forceinline__ void cp_async16(uint32_t saddr, const void* gptr) {
    asm volatile("cp.async.cg.shared.global [%0], [%1], 16;" :: "r"(saddr), "l"(gptr));
}
#define CP_COMMIT() asm volatile("cp.async.commit_group;" ::: "memory")
#define CP_WAIT0()  asm volatile("cp.async.wait_group 0;" ::: "memory")

// ---------------- kernels ----------------

__global__ void embed_k(const int* __restrict__ idx, const float* __restrict__ emb,
                        float* __restrict__ out) {
    int t = blockIdx.x;
    int row = idx[t];
    const float* src = emb + (size_t)row * DD;
    float* dst = out + (size_t)t * DD;
    for (int d = threadIdx.x; d < DD; d += blockDim.x) dst[d] = src[d];
}

__global__ void pack_w_k(const float* __restrict__ src, uint32_t* __restrict__ dH,
                         uint32_t* __restrict__ dL, int Kw, int N) {
    int n = blockIdx.x * 256 + threadIdx.x;
    if (n >= N) return;
    int kw = blockIdx.y;
    size_t nw = (size_t)Kw * N;
    size_t bs = (size_t)blockIdx.z * 2u * nw;
    size_t bd = (size_t)blockIdx.z * nw;
    float a0 = src[bs + (size_t)(2 * kw) * N + n];
    float a1 = src[bs + (size_t)(2 * kw + 1) * N + n];
    uint32_t h, l;
    split_pack(a0, a1, h, l);
    dH[bd + (size_t)kw * N + n] = h;
    dL[bd + (size_t)kw * N + n] = l;
}

__global__ void rmsnorm_pack_k(const float* __restrict__ in, const float* __restrict__ w,
                               float* __restrict__ outf,
                               uint32_t* __restrict__ pH, uint32_t* __restrict__ pL, int n) {
    int t = blockIdx.x;
    const float* r = in + (size_t)t * n;
    int tid = threadIdx.x;
    __shared__ float red[256];
    float s = 0.f;
    for (int i = tid; i < n; i += 256) { float vv = r[i]; s += vv * vv; }
    red[tid] = s; __syncthreads();
    for (int o = 128; o > 0; o >>= 1) { if (tid < o) red[tid] += red[tid + o]; __syncthreads(); }
    float rs = rsqrtf(red[0] / (float)n + EPSF);
    int nw = n >> 1;
    for (int i = tid; i < nw; i += 256) {
        float x0 = r[2 * i] * rs * w[2 * i];
        float x1 = r[2 * i + 1] * rs * w[2 * i + 1];
        if (outf) { outf[(size_t)t * n + 2 * i] = x0; outf[(size_t)t * n + 2 * i + 1] = x1; }
        uint32_t h, l;
        split_pack(x0, x1, h, l);
        pH[(size_t)t * nw + i] = h;
        pL[(size_t)t * nw + i] = l;
    }
}

// =======================================================================
// NEW: 64x64-warp-tile bf16x3 GEMM for big non-ADD GEMMs.
// Block 128x128, 128 threads = 4 warps (2x2), warp tile 64x64.
// 1.5x lower smem-crossbar traffic per FLOP than the 64x32-warp version.
// __launch_bounds__(128,2): reg cap 256 -> acc(128)+frags fits, no spill.
// cp.async one-sync pipeline. SW: m-fastest grid for B L2 reuse.
// =======================================================================
template <bool SW>
__global__ __launch_bounds__(128, 2) void tbgemm4w_k(
    const uint32_t* __restrict__ AHg, const uint32_t* __restrict__ ALg,
    const uint32_t* __restrict__ B0H, const uint32_t* __restrict__ B0L,
    const uint32_t* __restrict__ B1H, const uint32_t* __restrict__ B1L,
    const uint32_t* __restrict__ B2H, const uint32_t* __restrict__ B2L,
    float* __restrict__ C0, float* __restrict__ C1, float* __restrict__ C2,
    int M, int N, int Kd) {
    extern __shared__ uint32_t smw[];
    const int BUF = 8192;               // words/stage: AH 2048 AL 2048 BH 2048 BL 2048
    const int Kw = Kd >> 1;
    const uint32_t sbase = smem_u32(smw);

    const uint32_t* BHg = (blockIdx.z == 0) ? B0H : (blockIdx.z == 1 ? B1H : B2H);
    const uint32_t* BLg = (blockIdx.z == 0) ? B0L : (blockIdx.z == 1 ? B1L : B2L);
    float*          C   = (blockIdx.z == 0) ? C0  : (blockIdx.z == 1 ? C1  : C2);

    const int bm = (SW ? blockIdx.x : blockIdx.y) * 128;
    const int bn = (SW ? blockIdx.y : blockIdx.x) * 128;
    const int tid = threadIdx.x;
    const int warp = tid >> 5, lane = tid & 31;
    const int warpM = warp >> 1, warpN = warp & 1;
    const int g = lane >> 2, t4 = lane & 3;

    float acc[4][8][4];
#pragma unroll
    for (int i = 0; i < 4; i++)
#pragma unroll
        for (int j = 0; j < 8; j++)
#pragma unroll
            for (int r = 0; r < 4; r++) acc[i][j][r] = 0.f;

    auto ISSUE = [&](int kt, int buf) {
        uint32_t b0 = sbase + (uint32_t)buf * BUF * 4;
#pragma unroll
        for (int i = 0; i < 8; i++) {
            int id = i * 128 + tid;
            int r = id >> 3, c4 = id & 7;
            size_t off = (size_t)(bm + r) * Kw + kt * 16 + c4 * 2;
            uint32_t so = (uint32_t)(r * 16 + ((c4 * 2) ^ ((r & 7) * 2))) * 4;
            cp_async8(b0 + so, AHg + off);
            cp_async8(b0 + 8192 + so, ALg + off);
        }
#pragma unroll
        for (int i = 0; i < 4; i++) {
            int id = i * 128 + tid;
            int kw = id >> 5, n4 = id & 31;
            size_t off = (size_t)(kt * 16 + kw) * N + bn + n4 * 4;
            uint32_t so = (uint32_t)(kw * 128 + ((n4 * 4) ^ ((kw * 8) & 127))) * 4;
            cp_async16(b0 + 16384 + so, BHg + off);
            cp_async16(b0 + 24576 + so, BLg + off);
        }
        CP_COMMIT();
    };

    auto COMPUTE = [&](int buf) {
        uint32_t* AH = smw + buf * BUF;
        uint32_t* AL = AH + 2048;
        uint32_t* BH = AH + 4096;
        uint32_t* BL = AH + 6144;
#pragma unroll
        for (int ks = 0; ks < 2; ks++) {
            uint32_t bh[8][2], bl[8][2];
#pragma unroll
            for (int nt = 0; nt < 8; nt++) {
                int n = warpN * 64 + nt * 8 + g;
                int k0w = ks * 8 + t4, k1w = k0w + 4;
                int o0 = k0w * 128 + (n ^ ((k0w * 8) & 127));
                int o1 = k1w * 128 + (n ^ ((k1w * 8) & 127));
                bh[nt][0] = BH[o0]; bh[nt][1] = BH[o1];
                bl[nt][0] = BL[o0]; bl[nt][1] = BL[o1];
            }
#pragma unroll
            for (int mt = 0; mt < 4; mt++) {
                uint32_t ah[4], al[4];
                int r0 = warpM * 64 + mt * 16 + g;
                int r1 = r0 + 8;
                int ka = ks * 8 + t4, kb = ka + 4;
                int o0 = r0 * 16 + (ka ^ ((r0 & 7) * 2));
                int o1 = r1 * 16 + (ka ^ ((r1 & 7) * 2));
                int o2 = r0 * 16 + (kb ^ ((r0 & 7) * 2));
                int o3 = r1 * 16 + (kb ^ ((r1 & 7) * 2));
                ah[0] = AH[o0]; ah[1] = AH[o1]; ah[2] = AH[o2]; ah[3] = AH[o3];
                al[0] = AL[o0]; al[1] = AL[o1]; al[2] = AL[o2]; al[3] = AL[o3];
#pragma unroll
                for (int nt = 0; nt < 8; nt++) {
                    mma_bf16(acc[mt][nt], al, bh[nt]);
                    mma_bf16(acc[mt][nt], ah, bl[nt]);
                    mma_bf16(acc[mt][nt], ah, bh[nt]);
                }
            }
        }
    };

    const int ntiles = Kd / 32;
    ISSUE(0, 0);
    for (int kt = 0; kt < ntiles; kt++) {
        CP_WAIT0();
        __syncthreads();
        if (kt + 1 < ntiles) ISSUE(kt + 1, (kt + 1) & 1);
        COMPUTE(kt & 1);
    }

#pragma unroll
    for (int mt = 0; mt < 4; mt++) {
        int r0 = bm + warpM * 64 + mt * 16 + g;
#pragma unroll
        for (int nt = 0; nt < 8; nt++) {
            int c0 = bn + warpN * 64 + nt * 8 + 2 * t4;
            float* p0 = C + (size_t)r0 * N + c0;
            float* p1 = C + (size_t)(r0 + 8) * N + c0;
            p0[0] = acc[mt][nt][0]; p0[1] = acc[mt][nt][1];
            p1[0] = acc[mt][nt][2]; p1[1] = acc[mt][nt][3];
        }
    }
}

// =======================================================================
// Old 64x32-warp GEMM (MT=2, 256 thr), used for the small Wo/down GEMMs.
// =======================================================================
template <bool ADD, int MT, bool SW, int MINB>
__global__ __launch_bounds__(256, MINB) void tbgemm_k(
    const uint32_t* __restrict__ AHg, const uint32_t* __restrict__ ALg,
    const uint32_t* __restrict__ B0H, const uint32_t* __restrict__ B0L,
    const uint32_t* __restrict__ B1H, const uint32_t* __restrict__ B1L,
    const uint32_t* __restrict__ B2H, const uint32_t* __restrict__ B2L,
    float* __restrict__ C0, float* __restrict__ C1, float* __restrict__ C2,
    int M, int N, int Kd) {
    extern __shared__ uint32_t smw[];
    const int AW = MT * 512;
    const int BUF = AW * 2 + 4096;
    const int Kw = Kd >> 1;
    const uint32_t sbase = smem_u32(smw);

    const uint32_t* BHg = (blockIdx.z == 0) ? B0H : (blockIdx.z == 1 ? B1H : B2H);
    const uint32_t* BLg = (blockIdx.z == 0) ? B0L : (blockIdx.z == 1 ? B1L : B2L);
    float*          C   = (blockIdx.z == 0) ? C0  : (blockIdx.z == 1 ? C1  : C2);

    const int bm = (SW ? blockIdx.x : blockIdx.y) * (MT * 32);
    const int bn = (SW ? blockIdx.y : blockIdx.x) * 128;
    const int tid = threadIdx.x;
    const int warp = tid >> 5, lane = tid & 31;
    const int warpM = warp >> 2;
    const int warpN = warp & 3;
    const int g = lane >> 2, t4 = lane & 3;

    float acc[MT][4][4];
#pragma unroll
    for (int i = 0; i < MT; i++)
#pragma unroll
        for (int j = 0; j < 4; j++)
#pragma unroll
            for (int r = 0; r < 4; r++) acc[i][j][r] = 0.f;

    auto ISSUE = [&](int kt, int buf) {
        uint32_t b0 = sbase + (uint32_t)buf * BUF * 4;
#pragma unroll
        for (int i = 0; i < MT; i++) {
            int id = i * 256 + tid;
            int r = id >> 3, c4 = id & 7;
            size_t off = (size_t)(bm + r) * Kw + kt * 16 + c4 * 2;
            uint32_t so = (uint32_t)(r * 16 + ((c4 * 2) ^ ((r & 7) * 2))) * 4;
            cp_async8(b0 + so, AHg + off);
            cp_async8(b0 + AW * 4 + so, ALg + off);
        }
#pragma unroll
        for (int i = 0; i < 2; i++) {
            int id = i * 256 + tid;
            int kw = id >> 5, n4 = id & 31;
            size_t off = (size_t)(kt * 16 + kw) * N + bn + n4 * 4;
            uint32_t so = (uint32_t)(kw * 128 + ((n4 * 4) ^ ((kw * 8) & 127))) * 4;
            cp_async16(b0 + 2 * AW * 4 + so, BHg + off);
            cp_async16(b0 + 2 * AW * 4 + 8192 + so, BLg + off);
        }
        CP_COMMIT();
    };

    auto COMPUTE = [&](int buf) {
        uint32_t* AH = smw + buf * BUF;
        uint32_t* AL = AH + AW;
        uint32_t* BH = AH + 2 * AW;
        uint32_t* BL = BH + 2048;
#pragma unroll
        for (int ks = 0; ks < 2; ks++) {
            uint32_t bh[4][2], bl[4][2];
#pragma unroll
            for (int nt = 0; nt < 4; nt++) {
                int n = warpN * 32 + nt * 8 + g;
                int k0w = ks * 8 + t4, k1w = k0w + 4;
                int o0 = k0w * 128 + (n ^ ((k0w * 8) & 127));
                int o1 = k1w * 128 + (n ^ ((k1w * 8) & 127));
                bh[nt][0] = BH[o0]; bh[nt][1] = BH[o1];
                bl[nt][0] = BL[o0]; bl[nt][1] = BL[o1];
            }
#pragma unroll
            for (int mt = 0; mt < MT; mt++) {
                uint32_t ah[4], al[4];
                int r0 = warpM * (MT * 16) + mt * 16 + g;
                int r1 = r0 + 8;
                int ka = ks * 8 + t4, kb = ka + 4;
                int o0 = r0 * 16 + (ka ^ ((r0 & 7) * 2));
                int o1 = r1 * 16 + (ka ^ ((r1 & 7) * 2));
                int o2 = r0 * 16 + (kb ^ ((r0 & 7) * 2));
                int o3 = r1 * 16 + (kb ^ ((r1 & 7) * 2));
                ah[0] = AH[o0]; ah[1] = AH[o1]; ah[2] = AH[o2]; ah[3] = AH[o3];
                al[0] = AL[o0]; al[1] = AL[o1]; al[2] = AL[o2]; al[3] = AL[o3];
#pragma unroll
                for (int nt = 0; nt < 4; nt++) {
                    mma_bf16(acc[mt][nt], al, bh[nt]);
                    mma_bf16(acc[mt][nt], ah, bl[nt]);
                    mma_bf16(acc[mt][nt], ah, bh[nt]);
                }
            }
        }
    };

    const int ntiles = Kd / 32;
    ISSUE(0, 0);
    for (int kt = 0; kt < ntiles; kt++) {
        CP_WAIT0();
        __syncthreads();
        if (kt + 1 < ntiles) ISSUE(kt + 1, (kt + 1) & 1);
        COMPUTE(kt & 1);
    }

#pragma unroll
    for (int mt = 0; mt < MT; mt++) {
        int r0 = bm + warpM * (MT * 16) + mt * 16 + g;
#pragma unroll
        for (int nt = 0; nt < 4; nt++) {
            int c0 = bn + warpN * 32 + nt * 8 + 2 * t4;
            float* p0 = C + (size_t)r0 * N + c0;
            float* p1 = C + (size_t)(r0 + 8) * N + c0;
            if (ADD) {
                p0[0] += acc[mt][nt][0]; p0[1] += acc[mt][nt][1];
                p1[0] += acc[mt][nt][2]; p1[1] += acc[mt][nt][3];
            } else {
                p0[0] = acc[mt][nt][0]; p0[1] = acc[mt][nt][1];
                p1[0] = acc[mt][nt][2]; p1[1] = acc[mt][nt][3];
            }
        }
    }
}

// =======================================================================
// Strip-mined post-QKV (8 timesteps/block, 768 threads).
// =======================================================================
#define TS 8
__global__ __launch_bounds__(768) void postqkv_k(
    const float* __restrict__ t0, const float* __restrict__ t1, const float* __restrict__ t2,
    const float* __restrict__ cq, const float* __restrict__ ck, const float* __restrict__ cv,
    const float* __restrict__ x, const float* __restrict__ Wb,
    float* __restrict__ q, float* __restrict__ k, float* __restrict__ v,
    float* __restrict__ beta) {
    int ts = blockIdx.x * TS;
    int d = threadIdx.x;
    int h = d >> 6;
    int warp = d >> 5, lane = d & 31;
    __shared__ float sx[TS * DD];
    __shared__ float redq[TS][26], redk[TS][26];
    __shared__ float redb[96];

#pragma unroll
    for (int i = 0; i < TS; i++) sx[i * DD + d] = x[(size_t)(ts + i) * DD + d];
    __syncthreads();

    {
#pragma unroll
        for (int r = 0; r < 4; r++) {
            int idx = warp * 4 + r;
            int tt = idx / HH, hh = idx - tt * HH;
            float sb = 0.f;
            for (int i = lane; i < DD; i += 32) sb += sx[tt * DD + i] * Wb[i * HH + hh];
#pragma unroll
            for (int o = 16; o > 0; o >>= 1) sb += __shfl_xor_sync(0xffffffffu, sb, o);
            if (lane == 0) redb[idx] = sb;
        }
    }

    float cqw[KC], ckw[KC], cvw[KC];
#pragma unroll
    for (int j = 0; j < KC; j++) {
        cqw[j] = cq[d * KC + j];
        ckw[j] = ck[d * KC + j];
        cvw[j] = cv[d * KC + j];
    }
    float wq[KC], wk[KC], wv[KC];
#pragma unroll
    for (int j = 0; j < 3; j++) {
        int tt = ts - 3 + j;
        bool ok = (tt >= 0);
        size_t gg = ok ? (size_t)tt * DD + d : 0;
        wq[j] = ok ? t0[gg] : 0.f;
        wk[j] = ok ? t1[gg] : 0.f;
        wv[j] = ok ? t2[gg] : 0.f;
    }

    float qv[TS], kv[TS], vv[TS];
#pragma unroll
    for (int i = 0; i < TS; i++) {
        size_t gg = (size_t)(ts + i) * DD + d;
        wq[3] = t0[gg]; wk[3] = t1[gg]; wv[3] = t2[gg];
        float aq = wq[0] * cqw[0] + wq[1] * cqw[1] + wq[2] * cqw[2] + wq[3] * cqw[3];
        float ak = wk[0] * ckw[0] + wk[1] * ckw[1] + wk[2] * ckw[2] + wk[3] * ckw[3];
        float av = wv[0] * cvw[0] + wv[1] * cvw[1] + wv[2] * cvw[2] + wv[3] * cvw[3];
        qv[i] = aq / (1.f + __expf(-aq));
        kv[i] = ak / (1.f + __expf(-ak));
        vv[i] = av / (1.f + __expf(-av));
#pragma unroll
        for (int j = 0; j < 3; j++) { wq[j] = wq[j + 1]; wk[j] = wk[j + 1]; wv[j] = wv[j + 1]; }

        float sq = qv[i] * qv[i], sk = kv[i] * kv[i];
#pragma unroll
        for (int o = 16; o > 0; o >>= 1) {
            sq += __shfl_xor_sync(0xffffffffu, sq, o);
            sk += __shfl_xor_sync(0xffffffffu, sk, o);
        }
        if (lane == 0) { redq[i][warp] = sq; redk[i][warp] = sk; }
    }
    __syncthreads();

#pragma unroll
    for (int i = 0; i < TS; i++) {
        float rq = rsqrtf(redq[i][2 * h] + redq[i][2 * h + 1] + EPSF);
        float rk = rsqrtf(redk[i][2 * h] + redk[i][2 * h + 1] + EPSF);
        size_t gi = (size_t)(ts + i) * DD + d;
        q[gi] = qv[i] * rq;
        k[gi] = kv[i] * rk;
        v[gi] = vv[i];
    }
    if (d < 96) {
        int tt = d / HH, hh = d - tt * HH;
        beta[(ts + tt) * HH + hh] = 1.f / (1.f + __expf(-redb[d]));
    }
}

// =======================================================================
// Chunked delta rule, phase 1 (parallel; WY form).
// =======================================================================
__global__ __launch_bounds__(256) void deltaprep_k(
    const float* __restrict__ q, const float* __restrict__ k,
    const float* __restrict__ v, const float* __restrict__ beta,
    float* __restrict__ Qe, float* __restrict__ Of,
    float* __restrict__ Pm, float* __restrict__ Rm) {
    extern __shared__ float sm[];
    float* sK = sm;
    float* sV = sK + 64 * PSTR;
    float* sQ = sV + 64 * PSTR;
    float* bA = sQ + 64 * PSTR;
    float* bT = bA + 64 * PSTR;
    float* bU = bT + 64 * PSTR;
    float* sb = bU + 64 * PSTR;
    const int c = blockIdx.x, h = blockIdx.y;
    const int tid = threadIdx.x;
    const int tr = (tid >> 4) * 4, tc = (tid & 15) * 4;

    for (int i = tid; i < 4096; i += 256) {
        int t = i >> 6, d = i & 63;
        size_t g = (size_t)(c * 64 + t) * DD + h * 64 + d;
        sK[t * PSTR + d] = k[g];
        sV[t * PSTR + d] = v[g];
        sQ[t * PSTR + d] = q[g];
    }
    if (tid < 64) sb[tid] = beta[(c * 64 + tid) * HH + h];
    __syncthreads();

    {
        float acc[4][4] = {};
        for (int m = 0; m < 64; m++) {
            float a[4], b[4];
#pragma unroll
            for (int i = 0; i < 4; i++) a[i] = sK[(tr + i) * PSTR + m];
#pragma unroll
            for (int j = 0; j < 4; j++) b[j] = sK[(tc + j) * PSTR + m];
#pragma unroll
            for (int i = 0; i < 4; i++)
#pragma unroll
                for (int j = 0; j < 4; j++) acc[i][j] += a[i] * b[j];
        }
#pragma unroll
        for (int i = 0; i < 4; i++)
#pragma unroll
            for (int j = 0; j < 4; j++) {
                int t = tr + i, s = tc + j;
                bA[t * PSTR + s] = (s < t) ? acc[i][j] * sb[t] : 0.f;
            }
    }
    __syncthreads();

    for (int t = 0; t < 64; t++) {
        if (tid < 64) {
            float acc = (t == tid) ? 1.f : 0.f;
            for (int s = 0; s < t; s++) acc -= bA[t * PSTR + s] * bT[s * PSTR + tid];
            bT[t * PSTR + tid] = acc;
        }
        __syncthreads();
    }

    {
        float accW[4][4] = {}, accU[4][4] = {};
        for (int m = 0; m < 64; m++) {
            float a[4];
#pragma unroll
            for (int i = 0; i < 4; i++) a[i] = bT[(tr + i) * PSTR + m] * sb[m];
            float bk[4], bv[4];
#pragma unroll
            for (int j = 0; j < 4; j++) {
                bk[j] = sK[m * PSTR + tc + j];
                bv[j] = sV[m * PSTR + tc + j];
            }
#pragma unroll
            for (int i = 0; i < 4; i++)
#pragma unroll
                for (int j = 0; j < 4; j++) {
                    accW[i][j] += a[i] * bk[j];
                    accU[i][j] += a[i] * bv[j];
                }
        }
        __syncthreads();
#pragma unroll
        for (int i = 0; i < 4; i++)
#pragma unroll
            for (int j = 0; j < 4; j++) {
                bA[(tr + i) * PSTR + tc + j] = accW[i][j];
                bU[(tr + i) * PSTR + tc + j] = accU[i][j];
            }
    }
    __syncthreads();

    {
        float acc[4][4] = {};
        for (int m = 0; m < 64; m++) {
            float a[4], b[4];
#pragma unroll
            for (int i = 0; i < 4; i++) a[i] = sQ[(tr + i) * PSTR + m];
#pragma unroll
            for (int j = 0; j < 4; j++) b[j] = sK[(tc + j) * PSTR + m];
#pragma unroll
            for (int i = 0; i < 4; i++)
#pragma unroll
                for (int j = 0; j < 4; j++) acc[i][j] += a[i] * b[j];
        }
        __syncthreads();
#pragma unroll
        for (int i = 0; i < 4; i++)
#pragma unroll
            for (int j = 0; j < 4; j++) {
                int t = tr + i, s = tc + j;
                bT[t * PSTR + s] = (s <= t) ? acc[i][j] : 0.f;
            }
    }
    __syncthreads();

    const size_t base = ((size_t)(h * NCH + c)) << 12;

    {
        float accQ[4][4] = {}, accO[4][4] = {};
        for (int m = 0; m < 64; m++) {
            float a[4];
#pragma unroll
            for (int i = 0; i < 4; i++) a[i] = bT[(tr + i) * PSTR + m];
            float bw[4], bu[4];
#pragma unroll
            for (int j = 0; j < 4; j++) {
                bw[j] = bA[m * PSTR + tc + j];
                bu[j] = bU[m * PSTR + tc + j];
            }
#pragma unroll
            for (int i = 0; i < 4; i++)
#pragma unroll
                for (int j = 0; j < 4; j++) {
                    accQ[i][j] += a[i] * bw[j];
                    accO[i][j] += a[i] * bu[j];
                }
        }
#pragma unroll
        for (int i = 0; i < 4; i++)
#pragma unroll
            for (int j = 0; j < 4; j++) {
                Qe[base + (tr + i) * 64 + tc + j] =
                    sQ[(tr + i) * PSTR + tc + j] - accQ[i][j];
                Of[base + (tr + i) * 64 + tc + j] = accO[i][j];
            }
    }

    {
        float accP[4][4] = {}, accR[4][4] = {};
        for (int m = 0; m < 64; m++) {
            float a[4];
#pragma unroll
            for (int i = 0; i < 4; i++) a[i] = sK[m * PSTR + tr + i];
            float bw[4], bu[4];
#pragma unroll
            for (int j = 0; j < 4; j++) {
                bw[j] = bA[m * PSTR + tc + j];
                bu[j] = bU[m * PSTR + tc + j];
            }
#pragma unroll
            for (int i = 0; i < 4; i++)
#pragma unroll
                for (int j = 0; j < 4; j++) {
                    accP[i][j] += a[i] * bw[j];
                    accR[i][j] += a[i] * bu[j];
                }
        }
#pragma unroll
        for (int i = 0; i < 4; i++)
#pragma unroll
            for (int j = 0; j < 4; j++) {
                Pm[base + (tr + i) * 64 + tc + j] = accP[i][j];
                Rm[base + (tr + i) * 64 + tc + j] = accR[i][j];
            }
    }
}

// Chunked delta rule, phase 2 (scan)
__global__ __launch_bounds__(256) void deltascan_k(
    const float* __restrict__ Qe, const float* __restrict__ Of,
    const float* __restrict__ Pm, const float* __restrict__ Rm,
    float* __restrict__ o) {
    const int h = blockIdx.x, cg = blockIdx.y;
    const int tid = threadIdx.x;
    __shared__ float sQe[64 * PSTR], sP[64 * PSTR];
    __shared__ float S[64 * 9], sOf[512], sR[512];

    for (int i = tid; i < 64 * 9; i += 256) S[i] = 0.f;
    __syncthreads();

#pragma unroll 1
    for (int c = 0; c < NCH; c++) {
        size_t base = ((size_t)(h * NCH + c)) << 12;
        for (int i = tid; i < 4096; i += 256) {
            int t = i >> 6, d = i & 63;
            sQe[t * PSTR + d] = Qe[base + i];
            sP[t * PSTR + d] = Pm[base + i];
        }
        for (int i = tid; i < 512; i += 256) {
            int t = i >> 3, j = i & 7;
            sOf[i] = Of[base + t * 64 + cg * 8 + j];
            sR[i] = Rm[base + t * 64 + cg * 8 + j];
        }
        __syncthreads();

        float outv[2], ns[2];
#pragma unroll
        for (int u = 0; u < 2; u++) {
            int idx = tid + u * 256;
            int t = idx >> 3, j = idx & 7;
            float a1 = sOf[idx];
            float a2 = S[t * 9 + j] + sR[idx];
#pragma unroll
            for (int m = 0; m < 64; m++) {
                float sv = S[m * 9 + j];
                a1 += sQe[t * PSTR + m] * sv;
                a2 -= sP[t * PSTR + m] * sv;
            }
            outv[u] = a1;
            ns[u] = a2;
        }
#pragma unroll
        for (int u = 0; u < 2; u++) {
            int idx = tid + u * 256;
            int t = idx >> 3, j = idx & 7;
            o[(size_t)(c * 64 + t) * DD + h * 64 + cg * 8 + j] = outv[u];
        }
        __syncthreads();
#pragma unroll
        for (int u = 0; u < 2; u++) {
            int idx = tid + u * 256;
            int t = idx >> 3, j = idx & 7;
            S[t * 9 + j] = ns[u];
        }
        __syncthreads();
    }
}

// per-64 rmsnorm * w of delta output -> packed words
__global__ void headnorm_pack_k(const float* __restrict__ o, const float* __restrict__ w,
                                uint32_t* __restrict__ pH, uint32_t* __restrict__ pL) {
    int gw = (blockIdx.x * blockDim.x + threadIdx.x) >> 5;
    int lane = threadIdx.x & 31;
    if (gw >= TT * HH) return;
    const float* r = o + (size_t)gw * 64;
    float a = r[2 * lane], b = r[2 * lane + 1];
    float s = a * a + b * b;
#pragma unroll
    for (int os = 16; os > 0; os >>= 1) s += __shfl_xor_sync(0xffffffffu, s, os);
    float rs = rsqrtf(s * (1.f / 64.f) + EPSF);
    int t = gw / HH, h = gw % HH;
    uint32_t hw, lw;
    split_pack(a * rs * w[2 * lane], b * rs * w[2 * lane + 1], hw, lw);
    size_t wi = (size_t)t * 384 + h * 32 + lane;
    pH[wi] = hw;
    pL[wi] = lw;
}

// silu(g)*u -> packed words
__global__ void silu_mul_pack_k(const float* __restrict__ g, const float* __restrict__ u,
                                uint32_t* __restrict__ pH, uint32_t* __restrict__ pL) {
    int i = blockIdx.x * blockDim.x + threadIdx.x;
    if (i >= TT * FFF / 2) return;
    float g0 = g[2 * i], g1 = g[2 * i + 1];
    float y0 = (g0 / (1.f + __expf(-g0))) * u[2 * i];
    float y1 = (g1 / (1.f + __expf(-g1))) * u[2 * i + 1];
    uint32_t h, l;
    split_pack(y0, y1, h, l);
    pH[i] = h;
    pL[i] = l;
}

// online-softmax cross-entropy row pass
__global__ void loss_rows_k(const float* __restrict__ logits, const int* __restrict__ tgt,
                            float* __restrict__ nll, float* __restrict__ msk) {
    int t = blockIdx.x;
    const float* r = logits + (size_t)t * VV;
    int tid = threadIdx.x;
    __shared__ float sm_m[256], sm_s[256];
    float m = -INFINITY, s = 0.f;
    for (int i = tid; i < VV; i += 256) {
        float v = r[i];
        if (v > m) { s = s * __expf(m - v) + 1.f; m = v; }
        else s += __expf(v - m);
    }
    sm_m[tid] = m; sm_s[tid] = s;
    __syncthreads();
    for (int o = 128; o > 0; o >>= 1) {
        if (tid < o) {
            float m1 = sm_m[tid], m2 = sm_m[tid + o];
            float M = fmaxf(m1, m2);
            sm_s[tid] = sm_s[tid] * __expf(m1 - M) + sm_s[tid + o] * __expf(m2 - M);
            sm_m[tid] = M;
        }
        __syncthreads();
    }
    if (tid == 0) {
        float rowmax = sm_m[0], denom = sm_s[0];
        int tg = tgt[t];
        float mask = (tg >= 0) ? 1.f : 0.f;
        int tc = tg < 0 ? 0 : (tg > VV - 1 ? VV - 1 : tg);
        float lp = r[tc] - rowmax - logf(denom);
        nll[t] = -lp * mask;
        msk[t] = mask;
    }
}

__global__ void loss_reduce_k(const float* __restrict__ nll, const float* __restrict__ msk,
                              float* __restrict__ out) {
    int tid = threadIdx.x;
    __shared__ float r1[256], r2[256];
    float s = 0.f, c = 0.f;
    for (int i = tid; i < TT; i += 256) { s += nll[i]; c += msk[i]; }
    r1[tid] = s; r2[tid] = c; __syncthreads();
    for (int o = 128; o > 0; o >>= 1) {
        if (tid < o) { r1[tid] += r1[tid + o]; r2[tid] += r2[tid + o]; }
        __syncthreads();
    }
    if (tid == 0) out[0] = r1[0] / fmaxf(r2[0], 1.f);
}

// ---------------- host launcher ----------------
extern "C" void kernel_launch(void* const* d_in, const int* in_sizes, int n_in,
                              void* d_out, int out_size) {
    const int*   idx   = (const int*)d_in[0];
    const int*   tgt   = (const int*)d_in[1];
    const float* emb   = (const float*)d_in[2];
    const float* Wq    = (const float*)d_in[3];
    const float* Wk    = (const float*)d_in[4];
    const float* Wv    = (const float*)d_in[5];
    const float* convq = (const float*)d_in[6];
    const float* convk = (const float*)d_in[7];
    const float* convv = (const float*)d_in[8];
    const float* Wb    = (const float*)d_in[9];
    const float* onw   = (const float*)d_in[10];
    const float* Wo    = (const float*)d_in[11];
    const float* anw   = (const float*)d_in[12];
    const float* mnw   = (const float*)d_in[13];
    const float* Wg    = (const float*)d_in[14];
    const float* Wu    = (const float*)d_in[15];
    const float* Wd    = (const float*)d_in[16];
    const float* fnw   = (const float*)d_in[17];
    const float* lmh   = (const float*)d_in[18];
    float* out = (float*)d_out;

    float *hb, *xb, *t0, *t1, *t2, *qb, *kb, *vb, *ob, *bb, *gb, *ub, *nl, *mk, *lfb;
    cudaGetSymbolAddress((void**)&hb,  g_h);
    cudaGetSymbolAddress((void**)&xb,  g_x);
    cudaGetSymbolAddress((void**)&t0,  g_t0);
    cudaGetSymbolAddress((void**)&t1,  g_t1);
    cudaGetSymbolAddress((void**)&t2,  g_t2);
    cudaGetSymbolAddress((void**)&qb,  g_q);
    cudaGetSymbolAddress((void**)&kb,  g_k);
    cudaGetSymbolAddress((void**)&vb,  g_v);
    cudaGetSymbolAddress((void**)&ob,  g_o);
    cudaGetSymbolAddress((void**)&bb,  g_beta);
    cudaGetSymbolAddress((void**)&gb,  g_gate);
    cudaGetSymbolAddress((void**)&ub,  g_up);
    cudaGetSymbolAddress((void**)&nl,  g_nll);
    cudaGetSymbolAddress((void**)&mk,  g_msk);
    cudaGetSymbolAddress((void**)&lfb, g_logits_fb);

    float *dQe, *dOf, *dPm, *dRm;
    cudaGetSymbolAddress((void**)&dQe, g_Qe);
    cudaGetSymbolAddress((void**)&dOf, g_Of);
    cudaGetSymbolAddress((void**)&dPm, g_Pm);
    cudaGetSymbolAddress((void**)&dRm, g_Rm);

    uint32_t *pAh, *pAl;
    uint32_t *wqh, *wql, *wkh, *wkl, *wvh, *wvl, *woh, *wol;
    uint32_t *wgh, *wgl, *wuh, *wul, *wdh, *wdl, *lmH, *lmL;
    cudaGetSymbolAddress((void**)&pAh, g_pA_h);
    cudaGetSymbolAddress((void**)&pAl, g_pA_l);
    cudaGetSymbolAddress((void**)&wqh, g_Wq_h); cudaGetSymbolAddress((void**)&wql, g_Wq_l);
    cudaGetSymbolAddress((void**)&wkh, g_Wk_h); cudaGetSymbolAddress((void**)&wkl, g_Wk_l);
    cudaGetSymbolAddress((void**)&wvh, g_Wv_h); cudaGetSymbolAddress((void**)&wvl, g_Wv_l);
    cudaGetSymbolAddress((void**)&woh, g_Wo_h); cudaGetSymbolAddress((void**)&wol, g_Wo_l);
    cudaGetSymbolAddress((void**)&wgh, g_Wg_h); cudaGetSymbolAddress((void**)&wgl, g_Wg_l);
    cudaGetSymbolAddress((void**)&wuh, g_Wu_h); cudaGetSymbolAddress((void**)&wul, g_Wu_l);
    cudaGetSymbolAddress((void**)&wdh, g_Wd_h); cudaGetSymbolAddress((void**)&wdl, g_Wd_l);
    cudaGetSymbolAddress((void**)&lmH, g_Lm_h); cudaGetSymbolAddress((void**)&lmL, g_Lm_l);

    const int SMEM4 = 65536;   // both 4-warp and MT=4 use 64 KB
    const int SMEM2 = 49152;
    const int PREPSM = (6 * 64 * PSTR + 64) * 4 + 256;
    cudaFuncSetAttribute((const void*)tbgemm4w_k<false>, cudaFuncAttributeMaxDynamicSharedMemorySize, SMEM4);
    cudaFuncSetAttribute((const void*)tbgemm4w_k<true>,  cudaFuncAttributeMaxDynamicSharedMemorySize, SMEM4);
    cudaFuncSetAttribute((const void*)tbgemm_k<true, 2, false, 2>, cudaFuncAttributeMaxDynamicSharedMemorySize, SMEM2);
    cudaFuncSetAttribute((const void*)deltaprep_k, cudaFuncAttributeMaxDynamicSharedMemorySize, PREPSM);

    // ---- pack all weights ----
    pack_w_k<<<dim3(3, 384, LL), 256>>>(Wq, wqh, wql, 384, DD);
    pack_w_k<<<dim3(3, 384, LL), 256>>>(Wk, wkh, wkl, 384, DD);
    pack_w_k<<<dim3(3, 384, LL), 256>>>(Wv, wvh, wvl, 384, DD);
    pack_w_k<<<dim3(3, 384, LL), 256>>>(Wo, woh, wol, 384, DD);
    pack_w_k<<<dim3(8, 384, LL), 256>>>(Wg, wgh, wgl, 384, FFF);
    pack_w_k<<<dim3(8, 384, LL), 256>>>(Wu, wuh, wul, 384, FFF);
    pack_w_k<<<dim3(3, 1024, LL), 256>>>(Wd, wdh, wdl, 1024, DD);
    pack_w_k<<<dim3((VV + 255) / 256, 384, 1), 256>>>(lmh, lmH, lmL, 384, VV);

    const int ewarpBlocks = (TT * HH * 32 + 255) / 256;
    const int ffwBlocks = (TT * FFF / 2 + 255) / 256;

    embed_k<<<TT, 256>>>(idx, emb, hb);

    for (int l = 0; l < LL; l++) {
        const float* cq_l = convq + (size_t)l * DD * KC;
        const float* ck_l = convk + (size_t)l * DD * KC;
        const float* cv_l = convv + (size_t)l * DD * KC;
        const float* Wb_l = Wb + (size_t)l * DD * HH;
        const float* on_l = onw + (size_t)l * DKK;
        const float* an_l = anw + (size_t)l * DD;
        const float* mn_l = mnw + (size_t)l * DD;

        rmsnorm_pack_k<<<TT, 256>>>(hb, an_l, xb, pAh, pAl, DD);

        // QKV: 64x64-warp-tile kernel, 288 blocks of 128 threads
        dim3 gQKV(DD / 128, TT / 128, 3);
        tbgemm4w_k<false><<<gQKV, 128, SMEM4>>>(
            pAh, pAl,
            wqh + (size_t)l * WSM, wql + (size_t)l * WSM,
            wkh + (size_t)l * WSM, wkl + (size_t)l * WSM,
            wvh + (size_t)l * WSM, wvl + (size_t)l * WSM,
            t0, t1, t2, TT, DD, DD);

        postqkv_k<<<TT / TS, 768>>>(t0, t1, t2, cq_l, ck_l, cv_l, xb, Wb_l, qb, kb, vb, bb);

        deltaprep_k<<<dim3(NCH, HH), 256, PREPSM>>>(qb, kb, vb, bb, dQe, dOf, dPm, dRm);
        deltascan_k<<<dim3(HH, 8), 256>>>(dQe, dOf, dPm, dRm, ob);

        headnorm_pack_k<<<ewarpBlocks, 256>>>(ob, on_l, pAh, pAl);

        // Wo: MT=2 @ (256,2)
        dim3 gD(DD / 128, TT / 64, 1);
        tbgemm_k<true, 2, false, 2><<<gD, 256, SMEM2>>>(
            pAh, pAl,
            woh + (size_t)l * WSM, wol + (size_t)l * WSM,
            woh + (size_t)l * WSM, wol + (size_t)l * WSM,
            woh + (size_t)l * WSM, wol + (size_t)l * WSM,
            hb, hb, hb, TT, DD, DD);

        rmsnorm_pack_k<<<TT, 256>>>(hb, mn_l, nullptr, pAh, pAl, DD);

        // gate+up: 64x64-warp-tile kernel, 512 blocks
        dim3 gGU(FFF / 128, TT / 128, 2);
        tbgemm4w_k<false><<<gGU, 128, SMEM4>>>(
            pAh, pAl,
            wgh + (size_t)l * WGU, wgl + (size_t)l * WGU,
            wuh + (size_t)l * WGU, wul + (size_t)l * WGU,
            wuh + (size_t)l * WGU, wul + (size_t)l * WGU,
            gb, ub, ub, TT, FFF, DD);

        silu_mul_pack_k<<<ffwBlocks, 256>>>(gb, ub, pAh, pAl);

        // down: MT=2 @ (256,2)
        tbgemm_k<true, 2, false, 2><<<gD, 256, SMEM2>>>(
            pAh, pAl,
            wdh + (size_t)l * WDN, wdl + (size_t)l * WDN,
            wdh + (size_t)l * WDN, wdl + (size_t)l * WDN,
            wdh + (size_t)l * WDN, wdl + (size_t)l * WDN,
            hb, hb, hb, TT, DD, FFF);
    }

    rmsnorm_pack_k<<<TT, 256>>>(hb, fnw, nullptr, pAh, pAl, DD);

    const size_t LOGN = (size_t)TT * VV;
    float* logits = ((size_t)out_size >= LOGN) ? out : lfb;
    // LM head: 64x64-warp-tile, m-fastest grid (B panel read once)
    dim3 gV(TT / 128, VV / 128, 1);
    tbgemm4w_k<true><<<gV, 128, SMEM4>>>(pAh, pAl, lmH, lmL, lmH, lmL, lmH, lmL,
                                         logits, logits, logits, TT, VV, DD);

    loss_rows_k<<<TT, 256>>>(logits, tgt, nl, mk);
    float* loss_dst = nullptr;
    if ((size_t)out_size >= LOGN + 1) loss_dst = out + LOGN;
    else if ((size_t)out_size < LOGN) loss_dst = out;
    if (loss_dst) loss_reduce_k<<<1, 256>>>(nl, mk, loss_dst);
}